// round 8
// baseline (speedup 1.0000x reference)
#include <cuda_runtime.h>
#include <cuda_bf16.h>
#include <cstdint>
#include <math.h>

#define B_      4
#define N_      32768
#define C_      256
#define H_      8
#define D_      64
#define G_      64
#define INNER_  512
#define BNTOK   (B_*N_)          // 131072

// single dynamic smem symbol shared by all kernels
extern __shared__ char smem_dyn[];

// ---------------- scratch (device globals; allocation-free) ----------------
__device__ __nv_bfloat16 g_fxhi[(size_t)BNTOK * 512]; // fx split hi  [m][512]
__device__ __nv_bfloat16 g_fxlo[(size_t)BNTOK * 512]; // fx split lo
__device__ __nv_bfloat16 g_xhi[(size_t)BNTOK * 256];
__device__ __nv_bfloat16 g_xlo[(size_t)BNTOK * 256];
__device__ __nv_bfloat16 g_Whi[512 * 256];           // [n][k] transposed W_fx
__device__ __nv_bfloat16 g_Wlo[512 * 256];
__device__ float g_bias0[512];
__device__ __nv_bfloat16 g_Wc[H_ * 64 * 256];        // combined W_x@Ws, [h][g][c]
__device__ float g_bcomb[H_ * 64];
__device__ __nv_bfloat16 g_whi[(size_t)BNTOK * 512]; // slice weights hi
__device__ __nv_bfloat16 g_wlo[(size_t)BNTOK * 512];
__device__ __nv_bfloat16 g_Pthi[B_ * C_ * INNER_];
__device__ __nv_bfloat16 g_Ptlo[B_ * C_ * INNER_];
__device__ float g_st [B_*H_*G_*D_];
__device__ float g_nrm[B_*H_*G_];
__device__ float g_os [B_*H_*G_*D_];

// ---------------- helpers ----------------
__device__ __forceinline__ uint32_t smem_to_u32(const void* p) {
    uint32_t a;
    asm("{ .reg .u64 t; cvta.to.shared.u64 t, %1; cvt.u32.u64 %0, t; }" : "=r"(a) : "l"(p));
    return a;
}
__device__ __forceinline__ void ldsm4(uint32_t &r0, uint32_t &r1, uint32_t &r2, uint32_t &r3,
                                      uint32_t addr) {
    asm volatile("ldmatrix.sync.aligned.m8n8.x4.shared.b16 {%0,%1,%2,%3}, [%4];"
        : "=r"(r0), "=r"(r1), "=r"(r2), "=r"(r3) : "r"(addr));
}
__device__ __forceinline__ void ldsm4t(uint32_t &r0, uint32_t &r1, uint32_t &r2, uint32_t &r3,
                                       uint32_t addr) {
    asm volatile("ldmatrix.sync.aligned.m8n8.x4.trans.shared.b16 {%0,%1,%2,%3}, [%4];"
        : "=r"(r0), "=r"(r1), "=r"(r2), "=r"(r3) : "r"(addr));
}
__device__ __forceinline__ void mma16816(float* c,
                                         uint32_t a0, uint32_t a1, uint32_t a2, uint32_t a3,
                                         uint32_t b0, uint32_t b1) {
    asm volatile(
        "mma.sync.aligned.m16n8k16.row.col.f32.bf16.bf16.f32 "
        "{%0,%1,%2,%3}, {%4,%5,%6,%7}, {%8,%9}, {%0,%1,%2,%3};"
        : "+f"(c[0]), "+f"(c[1]), "+f"(c[2]), "+f"(c[3])
        : "r"(a0), "r"(a1), "r"(a2), "r"(a3), "r"(b0), "r"(b1));
}
__device__ __forceinline__ void split_one(float a, __nv_bfloat16 &hi, __nv_bfloat16 &lo) {
    hi = __float2bfloat16(a);
    lo = __float2bfloat16(a - __bfloat162float(hi));
}
__device__ __forceinline__ void split_pair(float a, float b, unsigned &hi, unsigned &lo) {
    __nv_bfloat16 ah, al, bh, bl;
    split_one(a, ah, al);
    split_one(b, bh, bl);
    hi = ((unsigned)__bfloat16_as_ushort(bh) << 16) | (unsigned)__bfloat16_as_ushort(ah);
    lo = ((unsigned)__bfloat16_as_ushort(bl) << 16) | (unsigned)__bfloat16_as_ushort(al);
}
#define CP_ASYNC16(dst, src) \
    asm volatile("cp.async.cg.shared.global [%0], [%1], 16;" :: "r"(dst), "l"(src))
#define CP_COMMIT()  asm volatile("cp.async.commit_group;")
#define CP_WAIT0()   asm volatile("cp.async.wait_group 0;")

// ---------------- K0: zero accumulators ----------------
__global__ void k_zero() {
    int i = blockIdx.x * blockDim.x + threadIdx.x;
    if (i < B_*H_*G_*D_) g_st[i] = 0.f;
    if (i < B_*H_*G_)    g_nrm[i] = 0.f;
}

// ---------------- K_sx: split x into bf16 hi/lo ----------------
__global__ void __launch_bounds__(256) k_split_x(const float* __restrict__ x) {
    size_t i = (size_t)blockIdx.x * 256 + threadIdx.x;
    float4 v = *(const float4*)(x + i * 4);
    unsigned h0, l0, h1, l1;
    split_pair(v.x, v.y, h0, l0);
    split_pair(v.z, v.w, h1, l1);
    *(uint2*)&g_xhi[i * 4] = make_uint2(h0, h1);
    *(uint2*)&g_xlo[i * 4] = make_uint2(l0, l1);
}

// ---------------- K_sw: split + transpose W_fx, build bias ----------------
__global__ void __launch_bounds__(256) k_split_W(
    const float* __restrict__ Wfx, const float* __restrict__ bfx)
{
    int idx = blockIdx.x * 256 + threadIdx.x;     // 131072 total
    int n = idx & 511;
    int k = idx >> 9;
    float v = Wfx[k * 512 + n];
    __nv_bfloat16 hi, lo;
    split_one(v, hi, lo);
    g_Whi[n * 256 + k] = hi;
    g_Wlo[n * 256 + k] = lo;
    if (blockIdx.x == 0) {
        for (int j = threadIdx.x; j < 512; j += 256)
            g_bias0[j] = bfx[j];
    }
}

// ---------------- K_comb: Wc[h][g][c] = sum_d Wx[c][h64+d]*Ws[d][g] ----------------
__global__ void __launch_bounds__(256) k_comb(
    const float* __restrict__ Wx, const float* __restrict__ Wsl,
    const float* __restrict__ bx, const float* __restrict__ bsl)
{
    __shared__ float sws[64*64];
    const int h = blockIdx.x, tid = threadIdx.x;
    for (int i = tid; i < 4096; i += 256) sws[i] = Wsl[i];
    __syncthreads();
    const int g = tid & 63, cq = tid >> 6;
    for (int cc = 0; cc < 64; cc++) {
        int c = cq * 64 + cc;
        float s = 0.f;
        const float* wxr = &Wx[(size_t)c * 512 + h * 64];
#pragma unroll 16
        for (int d = 0; d < 64; d++) s += wxr[d] * sws[d*64 + g];
        g_Wc[(h*64 + g)*256 + c] = __float2bfloat16(s);
    }
    if (tid < 64) {
        float s = bsl[tid];
        for (int d = 0; d < 64; d++) s += bx[h*64 + d] * sws[d*64 + tid];
        g_bcomb[h*64 + tid] = s;
    }
}

// ================= split-bf16 tensor-core GEMM, cp.async pipelined =================
// 3-pass (hh, hl, lh). CTA tile 128x128, K-chunk 32, distance-1 prefetch, 1 sync/chunk.
// mode 0: write g_fxhi/g_fxlo (bf16 split). mode 1: write fp32 OutF.

#define GK_ROWB 80                      // 32 halves + 8 pad (16B-aligned rows)
#define GK_ARR  (128 * GK_ROWB)         // 10240
#define GK_STG  (4 * GK_ARR)            // 40960 per stage
#define GK_SMEM (2 * GK_STG)            // 81920

__global__ void __launch_bounds__(256, 2) k_gemm_ts(
    const __nv_bfloat16* __restrict__ Ahi, const __nv_bfloat16* __restrict__ Alo,
    const __nv_bfloat16* __restrict__ Bhi, const __nv_bfloat16* __restrict__ Blo,
    int K, int mode,
    const float* __restrict__ bias,
    float* __restrict__ OutF, int ldc)
{
    char* sm = smem_dyn;
    const uint32_t sbase = smem_to_u32(sm);

    const int tid  = threadIdx.x;
    const int wid  = tid >> 5;
    const int lane = tid & 31;
    const int wm   = wid >> 2;
    const int wn   = wid & 3;
    const int m0   = blockIdx.y * 128;
    const int n0   = blockIdx.x * 128;

    const __nv_bfloat16* srcs[4];
    srcs[0] = Ahi + (size_t)m0 * K;
    srcs[1] = Alo + (size_t)m0 * K;
    size_t boff = (size_t)(mode ? (m0 >> 15) : 0) * 256 * INNER_ + (size_t)n0 * K;
    srcs[2] = Bhi + boff;
    srcs[3] = Blo + boff;

    const int srow0 = tid >> 2,         sq0 = tid & 3;
    const int srow1 = (tid + 256) >> 2, sq1 = (tid + 256) & 3;

    float acc[4][4][4];
#pragma unroll
    for (int i = 0; i < 4; i++)
#pragma unroll
        for (int j = 0; j < 4; j++)
#pragma unroll
            for (int e = 0; e < 4; e++) acc[i][j][e] = 0.f;

    const int lrow = lane & 15;
    const int lkq  = (lane >> 4) << 3;
    const int nch  = K >> 5;

    // prologue: stage chunk 0 into stage 0
#pragma unroll
    for (int arr = 0; arr < 4; arr++) {
        const __nv_bfloat16* s = srcs[arr];
        uint32_t d = sbase + arr * GK_ARR;
        CP_ASYNC16(d + srow0 * GK_ROWB + sq0 * 16, s + (size_t)srow0 * K + sq0 * 8);
        CP_ASYNC16(d + srow1 * GK_ROWB + sq1 * 16, s + (size_t)srow1 * K + sq1 * 8);
    }
    CP_COMMIT();

    for (int ch = 0; ch < nch; ch++) {
        CP_WAIT0();
        __syncthreads();
        if (ch + 1 < nch) {
            const int k1 = (ch + 1) << 5;
            const uint32_t stg = sbase + ((ch + 1) & 1) * GK_STG;
#pragma unroll
            for (int arr = 0; arr < 4; arr++) {
                const __nv_bfloat16* s = srcs[arr] + k1;
                uint32_t d = stg + arr * GK_ARR;
                CP_ASYNC16(d + srow0 * GK_ROWB + sq0 * 16, s + (size_t)srow0 * K + sq0 * 8);
                CP_ASYNC16(d + srow1 * GK_ROWB + sq1 * 16, s + (size_t)srow1 * K + sq1 * 8);
            }
            CP_COMMIT();
        }

        const uint32_t stg  = sbase + (ch & 1) * GK_STG;
        const uint32_t sahi = stg, salo = stg + GK_ARR;
        const uint32_t sbhi = stg + 2 * GK_ARR, sblo = stg + 3 * GK_ARR;

#pragma unroll
        for (int ks = 0; ks < 2; ks++) {
            const int khb = (ks * 16 + lkq) * 2;
            uint32_t a[4][4], bh[8], bl[8];
#pragma unroll
            for (int i = 0; i < 4; i++) {
                int row = wm * 64 + i * 16 + lrow;
                ldsm4(a[i][0], a[i][1], a[i][2], a[i][3], sahi + row * GK_ROWB + khb);
            }
#pragma unroll
            for (int jp = 0; jp < 2; jp++) {
                int row = wn * 32 + jp * 16 + lrow;
                ldsm4(bh[jp*4+0], bh[jp*4+1], bh[jp*4+2], bh[jp*4+3],
                      sbhi + row * GK_ROWB + khb);
            }
#pragma unroll
            for (int i = 0; i < 4; i++) {           // hh
                mma16816(acc[i][0], a[i][0], a[i][1], a[i][2], a[i][3], bh[0], bh[2]);
                mma16816(acc[i][1], a[i][0], a[i][1], a[i][2], a[i][3], bh[1], bh[3]);
                mma16816(acc[i][2], a[i][0], a[i][1], a[i][2], a[i][3], bh[4], bh[6]);
                mma16816(acc[i][3], a[i][0], a[i][1], a[i][2], a[i][3], bh[5], bh[7]);
            }
#pragma unroll
            for (int jp = 0; jp < 2; jp++) {
                int row = wn * 32 + jp * 16 + lrow;
                ldsm4(bl[jp*4+0], bl[jp*4+1], bl[jp*4+2], bl[jp*4+3],
                      sblo + row * GK_ROWB + khb);
            }
#pragma unroll
            for (int i = 0; i < 4; i++) {           // hl
                mma16816(acc[i][0], a[i][0], a[i][1], a[i][2], a[i][3], bl[0], bl[2]);
                mma16816(acc[i][1], a[i][0], a[i][1], a[i][2], a[i][3], bl[1], bl[3]);
                mma16816(acc[i][2], a[i][0], a[i][1], a[i][2], a[i][3], bl[4], bl[6]);
                mma16816(acc[i][3], a[i][0], a[i][1], a[i][2], a[i][3], bl[5], bl[7]);
            }
#pragma unroll
            for (int i = 0; i < 4; i++) {
                int row = wm * 64 + i * 16 + lrow;
                ldsm4(a[i][0], a[i][1], a[i][2], a[i][3], salo + row * GK_ROWB + khb);
            }
#pragma unroll
            for (int i = 0; i < 4; i++) {           // lh
                mma16816(acc[i][0], a[i][0], a[i][1], a[i][2], a[i][3], bh[0], bh[2]);
                mma16816(acc[i][1], a[i][0], a[i][1], a[i][2], a[i][3], bh[1], bh[3]);
                mma16816(acc[i][2], a[i][0], a[i][1], a[i][2], a[i][3], bh[4], bh[6]);
                mma16816(acc[i][3], a[i][0], a[i][1], a[i][2], a[i][3], bh[5], bh[7]);
            }
        }
    }

    // ---- epilogue ----
    const int r0 = lane >> 2;
    const int c0 = (lane & 3) * 2;
    if (mode == 1) {
#pragma unroll
        for (int j = 0; j < 4; j++) {
            const int col = n0 + wn * 32 + j * 8 + c0;
            const float2 bi = *(const float2*)&bias[col];
#pragma unroll
            for (int i = 0; i < 4; i++) {
                const int row = m0 + wm * 64 + i * 16 + r0;
                float2 o0 = {acc[i][j][0] + bi.x, acc[i][j][1] + bi.y};
                float2 o1 = {acc[i][j][2] + bi.x, acc[i][j][3] + bi.y};
                *(float2*)&OutF[(size_t)row * ldc + col] = o0;
                *(float2*)&OutF[(size_t)(row + 8) * ldc + col] = o1;
            }
        }
    } else {
#pragma unroll
        for (int j = 0; j < 4; j++) {
            const int col = n0 + wn * 32 + j * 8 + c0;
            const float2 bi = *(const float2*)&bias[col];
#pragma unroll
            for (int i = 0; i < 4; i++) {
                const int row = m0 + wm * 64 + i * 16 + r0;
                unsigned h0, l0, h1, l1;
                split_pair(acc[i][j][0] + bi.x, acc[i][j][1] + bi.y, h0, l0);
                split_pair(acc[i][j][2] + bi.x, acc[i][j][3] + bi.y, h1, l1);
                *(unsigned*)&g_fxhi[(size_t)row * 512 + col]       = h0;
                *(unsigned*)&g_fxlo[(size_t)row * 512 + col]       = l0;
                *(unsigned*)&g_fxhi[(size_t)(row + 8) * 512 + col] = h1;
                *(unsigned*)&g_fxlo[(size_t)(row + 8) * 512 + col] = l1;
            }
        }
    }
}

// ================= K_B: tensorized fused logits+softmax+pooling =================
// Phase 1 (1-pass): L = x_hi @ Wc_hi^T (K=256, 4 chunks) -> softmax -> w
// Phase 2 (3-pass): st = w^T @ fx -> atomicAdd partials

#define TOK 256
#define PA0  0                           // [256][144B] x chunks / fx_hi
#define PA1  36864                       // [256][144B] x chunks / fx_lo
#define PWC  73728                       // [64][528B]  Wc (hi)
#define PWTH 107520                      // [64][528B]  w^T hi
#define PWTL 141312                      // [64][528B]  w^T lo
#define PBSL 175104
#define PNRM 175360
#define SMEM_POOL 176640

__global__ void __launch_bounds__(256) k_pool(const float* __restrict__ temperature)
{
    char* sm = smem_dyn;
    const uint32_t sbase = smem_to_u32(sm);
    float* bslf = (float*)(sm + PBSL);
    float* nrmp = (float*)(sm + PNRM);

    const int h  = blockIdx.x;
    const int tb = blockIdx.y;
    const int b  = blockIdx.z;
    const int tid = threadIdx.x;
    const int wid = tid >> 5;
    const int lane = tid & 31;
    const int m0  = b * N_ + tb * TOK;
    const int lrow = lane & 15;
    const int lkq  = (lane >> 4) << 3;

    // prologue group: Wc (64x512B) + x chunk 0 -> PA0
#pragma unroll
    for (int it = 0; it < 8; it++) {
        int i = tid + it * 256;          // 2048 tasks
        int r = i >> 5, q = i & 31;
        CP_ASYNC16(sbase + PWC + r*528 + q*16, &g_Wc[(size_t)(h*64 + r)*256 + q*8]);
    }
#pragma unroll
    for (int it = 0; it < 8; it++) {
        int i = tid + it * 256;
        int r = i >> 3, q = i & 7;
        CP_ASYNC16(sbase + PA0 + r*144 + q*16,
                   &g_xhi[(size_t)(m0+r)*256 + q*8]);
    }
    CP_COMMIT();
    if (tid < 64) bslf[tid] = g_bcomb[h*64 + tid];

    // ---- phase 1 MMA (1-pass), K=256 in 4 chunks, distance-1 prefetch ----
    float acc[2][8][4];
#pragma unroll
    for (int i = 0; i < 2; i++)
#pragma unroll
        for (int j = 0; j < 8; j++)
#pragma unroll
            for (int e = 0; e < 4; e++) acc[i][j][e] = 0.f;

#pragma unroll
    for (int kc = 0; kc < 4; kc++) {
        CP_WAIT0();
        __syncthreads();
        if (kc + 1 < 4) {
            const uint32_t dstb = sbase + ((kc + 1) & 1 ? PA1 : PA0);
#pragma unroll
            for (int it = 0; it < 8; it++) {
                int i = tid + it * 256;
                int r = i >> 3, q = i & 7;
                CP_ASYNC16(dstb + r*144 + q*16,
                           &g_xhi[(size_t)(m0+r)*256 + (kc+1)*64 + q*8]);
            }
            CP_COMMIT();
        }
        const uint32_t abuf = sbase + ((kc & 1) ? PA1 : PA0);
#pragma unroll
        for (int ks = 0; ks < 4; ks++) {
            const int khA = (ks * 16 + lkq) * 2;
            const int khB = (kc * 64 + ks * 16 + lkq) * 2;
            uint32_t a[2][4], bh[16];
#pragma unroll
            for (int i = 0; i < 2; i++) {
                int row = wid * 32 + i * 16 + lrow;
                ldsm4(a[i][0], a[i][1], a[i][2], a[i][3], abuf + row*144 + khA);
            }
#pragma unroll
            for (int jp = 0; jp < 4; jp++) {
                int row = jp * 16 + lrow;
                ldsm4(bh[jp*4+0], bh[jp*4+1], bh[jp*4+2], bh[jp*4+3],
                      sbase + PWC + row*528 + khB);
            }
#pragma unroll
            for (int i = 0; i < 2; i++)
#pragma unroll
                for (int jj = 0; jj < 8; jj++) {
                    int jp = jj >> 1, o = jj & 1;
                    mma16816(acc[i][jj], a[i][0], a[i][1], a[i][2], a[i][3],
                             bh[jp*4+o], bh[jp*4+o+2]);
                }
        }
    }
    __syncthreads();   // all warps done reading PA0/PA1

    // prefetch fx hi/lo for phase 2 (overlaps softmax + w-writes)
#pragma unroll
    for (int it = 0; it < 8; it++) {
        int i = tid + it * 256;
        int r = i >> 3, q = i & 7;
        CP_ASYNC16(sbase + PA0 + r*144 + q*16,
                   &g_fxhi[(size_t)(m0+r)*512 + h*64 + q*8]);
        CP_ASYNC16(sbase + PA1 + r*144 + q*16,
                   &g_fxlo[(size_t)(m0+r)*512 + h*64 + q*8]);
    }
    CP_COMMIT();

    // ---- softmax over g (in registers, quad shuffles) ----
    float tmp = temperature[h];
    tmp = fminf(fmaxf(tmp, 0.1f), 5.0f);
    const float itemp = 1.0f / tmp;

#pragma unroll
    for (int i = 0; i < 2; i++)
#pragma unroll
        for (int j = 0; j < 8; j++) {
            float2 bi = *(float2*)&bslf[j*8 + (lane & 3)*2];
            acc[i][j][0] = (acc[i][j][0] + bi.x) * itemp;
            acc[i][j][1] = (acc[i][j][1] + bi.y) * itemp;
            acc[i][j][2] = (acc[i][j][2] + bi.x) * itemp;
            acc[i][j][3] = (acc[i][j][3] + bi.y) * itemp;
        }
    float inv0[2], inv1[2];
#pragma unroll
    for (int i = 0; i < 2; i++) {
        float m0v = -1e30f, m1v = -1e30f;
#pragma unroll
        for (int j = 0; j < 8; j++) {
            m0v = fmaxf(m0v, fmaxf(acc[i][j][0], acc[i][j][1]));
            m1v = fmaxf(m1v, fmaxf(acc[i][j][2], acc[i][j][3]));
        }
        m0v = fmaxf(m0v, __shfl_xor_sync(0xffffffff, m0v, 1));
        m0v = fmaxf(m0v, __shfl_xor_sync(0xffffffff, m0v, 2));
        m1v = fmaxf(m1v, __shfl_xor_sync(0xffffffff, m1v, 1));
        m1v = fmaxf(m1v, __shfl_xor_sync(0xffffffff, m1v, 2));
        float s0 = 0.f, s1 = 0.f;
#pragma unroll
        for (int j = 0; j < 8; j++) {
            acc[i][j][0] = __expf(acc[i][j][0] - m0v);
            acc[i][j][1] = __expf(acc[i][j][1] - m0v);
            acc[i][j][2] = __expf(acc[i][j][2] - m1v);
            acc[i][j][3] = __expf(acc[i][j][3] - m1v);
            s0 += acc[i][j][0] + acc[i][j][1];
            s1 += acc[i][j][2] + acc[i][j][3];
        }
        s0 += __shfl_xor_sync(0xffffffff, s0, 1);
        s0 += __shfl_xor_sync(0xffffffff, s0, 2);
        s1 += __shfl_xor_sync(0xffffffff, s1, 1);
        s1 += __shfl_xor_sync(0xffffffff, s1, 2);
        inv0[i] = 1.0f / s0;
        inv1[i] = 1.0f / s1;
    }

    // ---- write w: to WT smem (split, [g][t]) and to g_w gmem (split) ----
    {
        const int r = lane >> 2;
#pragma unroll
        for (int i = 0; i < 2; i++) {
            int t0 = wid * 32 + i * 16 + r;
            int t1 = t0 + 8;
#pragma unroll
            for (int j = 0; j < 8; j++) {
                int c = j * 8 + (lane & 3) * 2;
                float w00 = acc[i][j][0] * inv0[i], w01 = acc[i][j][1] * inv0[i];
                float w10 = acc[i][j][2] * inv1[i], w11 = acc[i][j][3] * inv1[i];
                unsigned h0, l0, h1, l1;
                split_pair(w00, w01, h0, l0);
                split_pair(w10, w11, h1, l1);
                *(unsigned*)&g_whi[(size_t)(m0 + t0)*512 + h*64 + c] = h0;
                *(unsigned*)&g_wlo[(size_t)(m0 + t0)*512 + h*64 + c] = l0;
                *(unsigned*)&g_whi[(size_t)(m0 + t1)*512 + h*64 + c] = h1;
                *(unsigned*)&g_wlo[(size_t)(m0 + t1)*512 + h*64 + c] = l1;
                *(__nv_bfloat16*)(sm + PWTH + c*528 + t0*2)     = __ushort_as_bfloat16((unsigned short)(h0 & 0xffff));
                *(__nv_bfloat16*)(sm + PWTH + (c+1)*528 + t0*2) = __ushort_as_bfloat16((unsigned short)(h0 >> 16));
                *(__nv_bfloat16*)(sm + PWTL + c*528 + t0*2)     = __ushort_as_bfloat16((unsigned short)(l0 & 0xffff));
                *(__nv_bfloat16*)(sm + PWTL + (c+1)*528 + t0*2) = __ushort_as_bfloat16((unsigned short)(l0 >> 16));
                *(__nv_bfloat16*)(sm + PWTH + c*528 + t1*2)     = __ushort_as_bfloat16((unsigned short)(h1 & 0xffff));
                *(__nv_bfloat16*)(sm + PWTH + (c+1)*528 + t1*2) = __ushort_as_bfloat16((unsigned short)(h1 >> 16));
                *(__nv_bfloat16*)(sm + PWTL + c*528 + t1*2)     = __ushort_as_bfloat16((unsigned short)(l1 & 0xffff));
                *(__nv_bfloat16*)(sm + PWTL + (c+1)*528 + t1*2) = __ushort_as_bfloat16((unsigned short)(l1 >> 16));
            }
        }
    }
    __syncthreads();   // WT visible to all

    // ---- norm partial sums (w^T row sums, hi+lo) ----
    {
        int g = tid & 63, q = tid >> 6;
        float s = 0.f;
        const __nv_bfloat16* ph = (const __nv_bfloat16*)(sm + PWTH + g*528);
        const __nv_bfloat16* pl = (const __nv_bfloat16*)(sm + PWTL + g*528);
#pragma unroll 8
        for (int t = q*64; t < q*64 + 64; t++)
            s += __bfloat162float(ph[t]) + __bfloat162float(pl[t]);
        nrmp[q*64 + g] = s;
    }
    __syncthreads();
    if (tid < 64) {
        float s = nrmp[tid] + nrmp[64+tid] + nrmp[128+tid] + nrmp[192+tid];
        atomicAdd(&g_nrm[(b*8 + h)*64 + tid], s);
    }
    CP_WAIT0();
    __syncthreads();

    // ---- phase 2 MMA: st[64x64] = w^T @ fx, K=256; warp tile 32x16; 3-pass ----
    const int wm2 = wid >> 2;
    const int wn2 = wid & 3;
    float ac2[2][2][4];
#pragma unroll
    for (int i = 0; i < 2; i++)
#pragma unroll
        for (int j = 0; j < 2; j++)
#pragma unroll
            for (int e = 0; e < 4; e++) ac2[i][j][e] = 0.f;

#pragma unroll
    for (int ks = 0; ks < 16; ks++) {
        const int khb = (ks * 16 + lkq) * 2;
        uint32_t a[2][4], bhv[4], blv[4];
#pragma unroll
        for (int i = 0; i < 2; i++) {
            int row = wm2 * 32 + i * 16 + lrow;
            ldsm4(a[i][0], a[i][1], a[i][2], a[i][3], sbase + PWTH + row*528 + khb);
        }
        {
            int trow = ks * 16 + lrow;
            uint32_t addr = sbase + PA0 + trow*144 + (wn2*16 + lkq)*2;
            ldsm4t(bhv[0], bhv[1], bhv[2], bhv[3], addr);
        }
#pragma unroll
        for (int i = 0; i < 2; i++) {
            mma16816(ac2[i][0], a[i][0], a[i][1], a[i][2], a[i][3], bhv[0], bhv[1]);
            mma16816(ac2[i][1], a[i][0], a[i][1], a[i][2], a[i][3], bhv[2], bhv[3]);
        }
        {
            int trow = ks * 16 + lrow;
            uint32_t addr = sbase + PA1 + trow*144 + (wn2*16 + lkq)*2;
            ldsm4t(blv[0], blv[1], blv[2], blv[3], addr);
        }
#pragma unroll
        for (int i = 0; i < 2; i++) {
            mma16816(ac2[i][0], a[i][0], a[i][1], a[i][2], a[i][3], blv[0], blv[1]);
            mma16816(ac2[i][1], a[i][0], a[i][1], a[i][2], a[i][3], blv[2], blv[3]);
        }
#pragma unroll
        for (int i = 0; i < 2; i++) {
            int row = wm2 * 32 + i * 16 + lrow;
            ldsm4(a[i][0], a[i][1], a[i][2], a[i][3], sbase + PWTL + row*528 + khb);
        }
#pragma unroll
        for (int i = 0; i < 2; i++) {
            mma16816(ac2[i][0], a[i][0], a[i][1], a[i][2], a[i][3], bhv[0], bhv[1]);
            mma16816(ac2[i][1], a[i][0], a[i][1], a[i][2], a[i][3], bhv[2], bhv[3]);
        }
    }

    // ---- atomic partial reduction into g_st ----
    {
        const int base = (b*8 + h) * 64;
        const int r = lane >> 2;
        const int cq = (lane & 3) * 2;
#pragma unroll
        for (int i = 0; i < 2; i++) {
            int g0r = wm2 * 32 + i * 16 + r;
#pragma unroll
            for (int jj = 0; jj < 2; jj++) {
                int d = wn2 * 16 + jj * 8 + cq;
                atomicAdd(&g_st[(base + g0r)*64 + d],     ac2[i][jj][0]);
                atomicAdd(&g_st[(base + g0r)*64 + d + 1], ac2[i][jj][1]);
                atomicAdd(&g_st[(base + g0r + 8)*64 + d],     ac2[i][jj][2]);
                atomicAdd(&g_st[(base + g0r + 8)*64 + d + 1], ac2[i][jj][3]);
            }
        }
    }
}

// ---------------- K_C1: tiny attention over slice tokens (256 thr) ----------------
#define SMEM_ATTN (5*64*65*4)            // 83200
__global__ void __launch_bounds__(256) k_attn(
    const float* __restrict__ Wq, const float* __restrict__ Wk,
    const float* __restrict__ Wv)
{
    float* sm = (float*)smem_dyn;
    float* S  = sm;
    float* Qs = sm + 64*65;
    float* Ks = sm + 2*64*65;
    float* Vs = sm + 3*64*65;
    float* Ps = sm + 4*64*65;

    const int h = blockIdx.x, b = blockIdx.y;
    const int tid = threadIdx.x;
    const int base = (b*8 + h) * 64;
    const int g  = tid >> 2;
    const int qd = (tid & 3) * 16;

    {
        float invn = 1.0f / (g_nrm[base + g] + 1e-5f);
#pragma unroll
        for (int j = 0; j < 16; j += 4) {
            float4 v = *(const float4*)&g_st[(base + g)*64 + qd + j];
            S[g*65 + qd + j]   = v.x * invn;
            S[g*65 + qd + j+1] = v.y * invn;
            S[g*65 + qd + j+2] = v.z * invn;
            S[g*65 + qd + j+3] = v.w * invn;
        }
    }
    __syncthreads();

    {
        float aq[16], ak[16], av[16];
#pragma unroll
        for (int j = 0; j < 16; j++) { aq[j] = 0.f; ak[j] = 0.f; av[j] = 0.f; }
        for (int k = 0; k < 64; k++) {
            float sv = S[g*65 + k];
            const float* wq = &Wq[k*64 + qd];
            const float* wk = &Wk[k*64 + qd];
            const float* wv = &Wv[k*64 + qd];
#pragma unroll
            for (int j = 0; j < 16; j++) {
                aq[j] += sv * wq[j];
                ak[j] += sv * wk[j];
                av[j] += sv * wv[j];
            }
        }
#pragma unroll
        for (int j = 0; j < 16; j++) {
            Qs[g*65 + qd + j] = aq[j];
            Ks[g*65 + qd + j] = ak[j];
            Vs[g*65 + qd + j] = av[j];
        }
    }
    __syncthreads();

    {
        float lg[16];
#pragma unroll
        for (int jj = 0; jj < 16; jj++) {
            int j = qd + jj;
            float dot = 0.f;
#pragma unroll
            for (int d = 0; d < 64; d++) dot += Qs[g*65 + d] * Ks[j*65 + d];
            lg[jj] = dot * 0.125f;
        }
        float mx = -1e30f;
#pragma unroll
        for (int jj = 0; jj < 16; jj++) mx = fmaxf(mx, lg[jj]);
        mx = fmaxf(mx, __shfl_xor_sync(0xffffffff, mx, 1));
        mx = fmaxf(mx, __shfl_xor_sync(0xffffffff, mx, 2));
        float s = 0.f;
#pragma unroll
        for (int jj = 0; jj < 16; jj++) { lg[jj] = __expf(lg[jj] - mx); s += lg[jj]; }
        s += __shfl_xor_sync(0xffffffff, s, 1);
        s += __shfl_xor_sync(0xffffffff, s, 2);
        float inv = 1.0f / s;
#pragma unroll
        for (int jj = 0; jj < 16; jj++) Ps[g*65 + qd + jj] = lg[jj] * inv;
    }
    __syncthreads();

    {
        float o[16];
#pragma unroll
        for (int d = 0; d < 16; d++) o[d] = 0.f;
        for (int j = 0; j < 64; j++) {
            float p = Ps[g*65 + j];
#pragma unroll
            for (int d = 0; d < 16; d++) o[d] += p * Vs[j*65 + qd + d];
        }
#pragma unroll
        for (int d = 0; d < 16; d++)
            g_os[(base + g)*64 + qd + d] = o[d];
    }
}

// ---------------- K_C2: P_t[b][c][h*64+g] split bf16 ----------------
#define SMEM_P ((64*68 + 64*256) * (int)sizeof(float))
__global__ void __launch_bounds__(256) k_P(const float* __restrict__ Wout)
{
    float* sm = (float*)smem_dyn;
    float* Os  = sm;
    float* Wsm = sm + 64*68;

    const int h = blockIdx.x, b = blockIdx.y;
    const int tid = threadIdx.x;
    const int base = (b*8 + h) * 64;

    for (int i = tid; i < 64*16; i += 256) {
        int r = i >> 4, c = i & 15;
        *(float4*)&Os[r*68 + c*4] = *(const float4*)&g_os[(size_t)(base + r)*64 + c*4];
    }
    for (int i = tid; i < 64*64; i += 256) {
        int r = i >> 6, c = i & 63;
        *(float4*)&Wsm[r*256 + c*4] = *(const float4*)&Wout[(size_t)(h*64 + r)*256 + c*4];
    }
    __syncthreads();

    const int gq = tid >> 3;
    const int cq = tid & 7;
    const int g0 = gq * 2;
    const int c0 = cq * 32;

    float acc[2][32];
#pragma unroll
    for (int i = 0; i < 2; i++)
#pragma unroll
        for (int j = 0; j < 32; j++) acc[i][j] = 0.f;

    for (int k = 0; k < 64; k++) {
        float a0 = Os[(g0+0)*68 + k];
        float a1 = Os[(g0+1)*68 + k];
#pragma unroll
        for (int c4 = 0; c4 < 8; c4++) {
            float4 w = *(float4*)&Wsm[k*256 + c0 + c4*4];
            acc[0][c4*4+0] += a0*w.x; acc[0][c4*4+1] += a0*w.y;
            acc[0][c4*4+2] += a0*w.z; acc[0][c4*4+3] += a0*w.w;
            acc[1][c4*4+0] += a1*w.x; acc[1][c4*4+1] += a1*w.y;
            acc[1][c4*4+2] += a1*w.z; acc[1][c4*4+3] += a1*w.w;
        }
    }
    __nv_bfloat16* Ph = &g_Pthi[(size_t)b * C_ * INNER_];
    __nv_bfloat16* Pl = &g_Ptlo[(size_t)b * C_ * INNER_];
#pragma unroll
    for (int i = 0; i < 2; i++)
#pragma unroll
        for (int c4 = 0; c4 < 8; c4++)
#pragma unroll
            for (int e = 0; e < 4; e++) {
                size_t off = (size_t)(c0 + c4*4 + e) * INNER_ + h*64 + g0 + i;
                __nv_bfloat16 hi, lo;
                split_one(acc[i][c4*4+e], hi, lo);
                Ph[off] = hi;
                Pl[off] = lo;
            }
}

// ---------------- launch ----------------
extern "C" void kernel_launch(void* const* d_in, const int* in_sizes, int n_in,
                              void* d_out, int out_size)
{
    const float* x    = (const float*)d_in[0];
    const float* Wfx  = (const float*)d_in[1];
    const float* bfx  = (const float*)d_in[2];
    const float* Wx   = (const float*)d_in[3];
    const float* bx   = (const float*)d_in[4];
    const float* Wsl  = (const float*)d_in[5];
    const float* bsl  = (const float*)d_in[6];
    const float* temp = (const float*)d_in[7];
    const float* Wq   = (const float*)d_in[8];
    const float* Wk   = (const float*)d_in[9];
    const float* Wv   = (const float*)d_in[10];
    const float* Wout = (const float*)d_in[11];
    const float* bout = (const float*)d_in[12];
    float* out = (float*)d_out;

    static bool init = false;
    static float *g_bias0_p;
    static __nv_bfloat16 *g_xhi_p, *g_xlo_p, *g_Whi_p, *g_Wlo_p;
    static __nv_bfloat16 *g_whi_p, *g_wlo_p, *g_Pthi_p, *g_Ptlo_p;
    if (!init) {
        cudaGetSymbolAddress((void**)&g_bias0_p, g_bias0);
        cudaGetSymbolAddress((void**)&g_xhi_p,   g_xhi);
        cudaGetSymbolAddress((void**)&g_xlo_p,   g_xlo);
        cudaGetSymbolAddress((void**)&g_Whi_p,   g_Whi);
        cudaGetSymbolAddress((void**)&g_Wlo_p,   g_Wlo);
        cudaGetSymbolAddress((void**)&g_whi_p,   g_whi);
        cudaGetSymbolAddress((void**)&g_wlo_p,   g_wlo);
        cudaGetSymbolAddress((void**)&g_Pthi_p,  g_Pthi);
        cudaGetSymbolAddress((void**)&g_Ptlo_p,  g_Ptlo);
        cudaFuncSetAttribute(k_gemm_ts, cudaFuncAttributeMaxDynamicSharedMemorySize, GK_SMEM);
        cudaFuncSetAttribute(k_pool, cudaFuncAttributeMaxDynamicSharedMemorySize, SMEM_POOL);
        cudaFuncSetAttribute(k_attn, cudaFuncAttributeMaxDynamicSharedMemorySize, SMEM_ATTN);
        cudaFuncSetAttribute(k_P,    cudaFuncAttributeMaxDynamicSharedMemorySize, SMEM_P);
        init = true;
    }

    // 0) zero accumulators + operand prep
    k_zero<<<(B_*H_*G_*D_ + 255)/256, 256>>>();
    k_split_x<<<(BNTOK * 256 / 4) / 256, 256>>>(x);
    k_split_W<<<131072 / 256, 256>>>(Wfx, bfx);
    k_comb<<<8, 256>>>(Wx, Wsl, bx, bsl);

    // 1) projections: fx only (tensor cores, 3-pass)
    k_gemm_ts<<<dim3(4, BNTOK/128), 256, GK_SMEM>>>(
        g_xhi_p, g_xlo_p, g_Whi_p, g_Wlo_p, 256, 0, g_bias0_p, nullptr, 0);

    // 2) fused logits/softmax/pooling (tensor cores; logits via W_comb)
    k_pool<<<dim3(H_, N_/TOK, B_), 256, SMEM_POOL>>>(temp);

    // 3) tiny attention over slice tokens
    k_attn<<<dim3(H_, B_), 256, SMEM_ATTN>>>(Wq, Wk, Wv);

    // 4) P precompute (transposed + split)
    k_P<<<dim3(H_, B_), 256, SMEM_P>>>(Wout);

    // 5) output GEMM (tensor cores, 3-pass)
    k_gemm_ts<<<dim3(2, BNTOK/128), 256, GK_SMEM>>>(
        g_whi_p, g_wlo_p, g_Pthi_p, g_Ptlo_p, 512, 1, bout, out, 256);
}

// round 9
// speedup vs baseline: 1.0865x; 1.0865x over previous
#include <cuda_runtime.h>
#include <cuda_bf16.h>
#include <cstdint>
#include <math.h>

#define B_      4
#define N_      32768
#define C_      256
#define H_      8
#define D_      64
#define G_      64
#define INNER_  512
#define BNTOK   (B_*N_)          // 131072

// single dynamic smem symbol shared by all kernels
extern __shared__ char smem_dyn[];

// ---------------- scratch (device globals; allocation-free) ----------------
__device__ __nv_bfloat16 g_fxhi[(size_t)BNTOK * 512]; // fx split hi  [m][512]
__device__ __nv_bfloat16 g_fxlo[(size_t)BNTOK * 512]; // fx split lo
__device__ __nv_bfloat16 g_xhi[(size_t)BNTOK * 256];
__device__ __nv_bfloat16 g_xlo[(size_t)BNTOK * 256];
__device__ __nv_bfloat16 g_Whi[512 * 256];           // [n][k] transposed W_fx
__device__ __nv_bfloat16 g_Wlo[512 * 256];
__device__ float g_bias0[512];
__device__ __nv_bfloat16 g_Wc[H_ * 64 * 256];        // combined W_x@Ws, [h][g][c]
__device__ float g_bcomb[H_ * 64];
__device__ __nv_bfloat16 g_whi[(size_t)BNTOK * 512]; // slice weights hi
__device__ __nv_bfloat16 g_wlo[(size_t)BNTOK * 512];
__device__ __nv_bfloat16 g_Pthi[B_ * C_ * INNER_];
__device__ __nv_bfloat16 g_Ptlo[B_ * C_ * INNER_];
__device__ float g_st [B_*H_*G_*D_];
__device__ float g_nrm[B_*H_*G_];
__device__ float g_os [B_*H_*G_*D_];

// ---------------- helpers ----------------
__device__ __forceinline__ uint32_t smem_to_u32(const void* p) {
    uint32_t a;
    asm("{ .reg .u64 t; cvta.to.shared.u64 t, %1; cvt.u32.u64 %0, t; }" : "=r"(a) : "l"(p));
    return a;
}
__device__ __forceinline__ void ldsm4(uint32_t &r0, uint32_t &r1, uint32_t &r2, uint32_t &r3,
                                      uint32_t addr) {
    asm volatile("ldmatrix.sync.aligned.m8n8.x4.shared.b16 {%0,%1,%2,%3}, [%4];"
        : "=r"(r0), "=r"(r1), "=r"(r2), "=r"(r3) : "r"(addr));
}
__device__ __forceinline__ void ldsm4t(uint32_t &r0, uint32_t &r1, uint32_t &r2, uint32_t &r3,
                                       uint32_t addr) {
    asm volatile("ldmatrix.sync.aligned.m8n8.x4.trans.shared.b16 {%0,%1,%2,%3}, [%4];"
        : "=r"(r0), "=r"(r1), "=r"(r2), "=r"(r3) : "r"(addr));
}
__device__ __forceinline__ void mma16816(float* c,
                                         uint32_t a0, uint32_t a1, uint32_t a2, uint32_t a3,
                                         uint32_t b0, uint32_t b1) {
    asm volatile(
        "mma.sync.aligned.m16n8k16.row.col.f32.bf16.bf16.f32 "
        "{%0,%1,%2,%3}, {%4,%5,%6,%7}, {%8,%9}, {%0,%1,%2,%3};"
        : "+f"(c[0]), "+f"(c[1]), "+f"(c[2]), "+f"(c[3])
        : "r"(a0), "r"(a1), "r"(a2), "r"(a3), "r"(b0), "r"(b1));
}
__device__ __forceinline__ void split_one(float a, __nv_bfloat16 &hi, __nv_bfloat16 &lo) {
    hi = __float2bfloat16(a);
    lo = __float2bfloat16(a - __bfloat162float(hi));
}
__device__ __forceinline__ void split_pair(float a, float b, unsigned &hi, unsigned &lo) {
    __nv_bfloat16 ah, al, bh, bl;
    split_one(a, ah, al);
    split_one(b, bh, bl);
    hi = ((unsigned)__bfloat16_as_ushort(bh) << 16) | (unsigned)__bfloat16_as_ushort(ah);
    lo = ((unsigned)__bfloat16_as_ushort(bl) << 16) | (unsigned)__bfloat16_as_ushort(al);
}
#define CP_ASYNC16(dst, src) \
    asm volatile("cp.async.cg.shared.global [%0], [%1], 16;" :: "r"(dst), "l"(src))
#define CP_COMMIT()  asm volatile("cp.async.commit_group;")
#define CP_WAIT0()   asm volatile("cp.async.wait_group 0;")

// ---------------- K0: zero accumulators ----------------
__global__ void k_zero() {
    int i = blockIdx.x * blockDim.x + threadIdx.x;
    if (i < B_*H_*G_*D_) g_st[i] = 0.f;
    if (i < B_*H_*G_)    g_nrm[i] = 0.f;
}

// ---------------- K_sx: split x into bf16 hi/lo ----------------
__global__ void __launch_bounds__(256) k_split_x(const float* __restrict__ x) {
    size_t i = (size_t)blockIdx.x * 256 + threadIdx.x;
    float4 v = *(const float4*)(x + i * 4);
    unsigned h0, l0, h1, l1;
    split_pair(v.x, v.y, h0, l0);
    split_pair(v.z, v.w, h1, l1);
    *(uint2*)&g_xhi[i * 4] = make_uint2(h0, h1);
    *(uint2*)&g_xlo[i * 4] = make_uint2(l0, l1);
}

// ---------------- K_sw: split + transpose W_fx, build bias ----------------
__global__ void __launch_bounds__(256) k_split_W(
    const float* __restrict__ Wfx, const float* __restrict__ bfx)
{
    int idx = blockIdx.x * 256 + threadIdx.x;     // 131072 total
    int n = idx & 511;
    int k = idx >> 9;
    float v = Wfx[k * 512 + n];
    __nv_bfloat16 hi, lo;
    split_one(v, hi, lo);
    g_Whi[n * 256 + k] = hi;
    g_Wlo[n * 256 + k] = lo;
    if (blockIdx.x == 0) {
        for (int j = threadIdx.x; j < 512; j += 256)
            g_bias0[j] = bfx[j];
    }
}

// ---------------- K_comb: Wc[h][g][c] = sum_d Wx[c][h64+d]*Ws[d][g] ----------------
// grid (H_, 16): each CTA handles one head x 16 c-columns. 128 CTAs total.
__global__ void __launch_bounds__(256) k_comb(
    const float* __restrict__ Wx, const float* __restrict__ Wsl,
    const float* __restrict__ bx, const float* __restrict__ bsl)
{
    __shared__ float sws[64*64];
    const int h = blockIdx.x;
    const int cb = blockIdx.y;           // 0..15 -> c base = cb*16
    const int tid = threadIdx.x;
    for (int i = tid; i < 4096; i += 256) sws[i] = Wsl[i];
    __syncthreads();
    const int g = tid & 63, cq = tid >> 6;   // cq: 0..3
#pragma unroll
    for (int cc = 0; cc < 4; cc++) {
        int c = cb * 16 + cq * 4 + cc;
        float s = 0.f;
        const float* wxr = &Wx[(size_t)c * 512 + h * 64];
#pragma unroll 16
        for (int d = 0; d < 64; d++) s += wxr[d] * sws[d*64 + g];
        g_Wc[(h*64 + g)*256 + c] = __float2bfloat16(s);
    }
    if (cb == 0 && tid < 64) {
        float s = bsl[tid];
        for (int d = 0; d < 64; d++) s += bx[h*64 + d] * sws[d*64 + tid];
        g_bcomb[h*64 + tid] = s;
    }
}

// ================= split-bf16 tensor-core GEMM, cp.async pipelined =================
// 3-pass (hh, hl, lh). CTA tile 128x128, K-chunk 32, distance-1 prefetch, 1 sync/chunk.
// mode 0: write g_fxhi/g_fxlo (bf16 split). mode 1: write fp32 OutF.

#define GK_ROWB 80                      // 32 halves + 8 pad (16B-aligned rows)
#define GK_ARR  (128 * GK_ROWB)         // 10240
#define GK_STG  (4 * GK_ARR)            // 40960 per stage
#define GK_SMEM (2 * GK_STG)            // 81920

__global__ void __launch_bounds__(256, 2) k_gemm_ts(
    const __nv_bfloat16* __restrict__ Ahi, const __nv_bfloat16* __restrict__ Alo,
    const __nv_bfloat16* __restrict__ Bhi, const __nv_bfloat16* __restrict__ Blo,
    int K, int mode,
    const float* __restrict__ bias,
    float* __restrict__ OutF, int ldc)
{
    char* sm = smem_dyn;
    const uint32_t sbase = smem_to_u32(sm);

    const int tid  = threadIdx.x;
    const int wid  = tid >> 5;
    const int lane = tid & 31;
    const int wm   = wid >> 2;
    const int wn   = wid & 3;
    const int m0   = blockIdx.y * 128;
    const int n0   = blockIdx.x * 128;

    const __nv_bfloat16* srcs[4];
    srcs[0] = Ahi + (size_t)m0 * K;
    srcs[1] = Alo + (size_t)m0 * K;
    size_t boff = (size_t)(mode ? (m0 >> 15) : 0) * 256 * INNER_ + (size_t)n0 * K;
    srcs[2] = Bhi + boff;
    srcs[3] = Blo + boff;

    const int srow0 = tid >> 2,         sq0 = tid & 3;
    const int srow1 = (tid + 256) >> 2, sq1 = (tid + 256) & 3;

    float acc[4][4][4];
#pragma unroll
    for (int i = 0; i < 4; i++)
#pragma unroll
        for (int j = 0; j < 4; j++)
#pragma unroll
            for (int e = 0; e < 4; e++) acc[i][j][e] = 0.f;

    const int lrow = lane & 15;
    const int lkq  = (lane >> 4) << 3;
    const int nch  = K >> 5;

    // prologue: stage chunk 0 into stage 0
#pragma unroll
    for (int arr = 0; arr < 4; arr++) {
        const __nv_bfloat16* s = srcs[arr];
        uint32_t d = sbase + arr * GK_ARR;
        CP_ASYNC16(d + srow0 * GK_ROWB + sq0 * 16, s + (size_t)srow0 * K + sq0 * 8);
        CP_ASYNC16(d + srow1 * GK_ROWB + sq1 * 16, s + (size_t)srow1 * K + sq1 * 8);
    }
    CP_COMMIT();

    for (int ch = 0; ch < nch; ch++) {
        CP_WAIT0();
        __syncthreads();
        if (ch + 1 < nch) {
            const int k1 = (ch + 1) << 5;
            const uint32_t stg = sbase + ((ch + 1) & 1) * GK_STG;
#pragma unroll
            for (int arr = 0; arr < 4; arr++) {
                const __nv_bfloat16* s = srcs[arr] + k1;
                uint32_t d = stg + arr * GK_ARR;
                CP_ASYNC16(d + srow0 * GK_ROWB + sq0 * 16, s + (size_t)srow0 * K + sq0 * 8);
                CP_ASYNC16(d + srow1 * GK_ROWB + sq1 * 16, s + (size_t)srow1 * K + sq1 * 8);
            }
            CP_COMMIT();
        }

        const uint32_t stg  = sbase + (ch & 1) * GK_STG;
        const uint32_t sahi = stg, salo = stg + GK_ARR;
        const uint32_t sbhi = stg + 2 * GK_ARR, sblo = stg + 3 * GK_ARR;

#pragma unroll
        for (int ks = 0; ks < 2; ks++) {
            const int khb = (ks * 16 + lkq) * 2;
            uint32_t a[4][4], bh[8], bl[8];
#pragma unroll
            for (int i = 0; i < 4; i++) {
                int row = wm * 64 + i * 16 + lrow;
                ldsm4(a[i][0], a[i][1], a[i][2], a[i][3], sahi + row * GK_ROWB + khb);
            }
#pragma unroll
            for (int jp = 0; jp < 2; jp++) {
                int row = wn * 32 + jp * 16 + lrow;
                ldsm4(bh[jp*4+0], bh[jp*4+1], bh[jp*4+2], bh[jp*4+3],
                      sbhi + row * GK_ROWB + khb);
            }
#pragma unroll
            for (int i = 0; i < 4; i++) {           // hh
                mma16816(acc[i][0], a[i][0], a[i][1], a[i][2], a[i][3], bh[0], bh[2]);
                mma16816(acc[i][1], a[i][0], a[i][1], a[i][2], a[i][3], bh[1], bh[3]);
                mma16816(acc[i][2], a[i][0], a[i][1], a[i][2], a[i][3], bh[4], bh[6]);
                mma16816(acc[i][3], a[i][0], a[i][1], a[i][2], a[i][3], bh[5], bh[7]);
            }
#pragma unroll
            for (int jp = 0; jp < 2; jp++) {
                int row = wn * 32 + jp * 16 + lrow;
                ldsm4(bl[jp*4+0], bl[jp*4+1], bl[jp*4+2], bl[jp*4+3],
                      sblo + row * GK_ROWB + khb);
            }
#pragma unroll
            for (int i = 0; i < 4; i++) {           // hl
                mma16816(acc[i][0], a[i][0], a[i][1], a[i][2], a[i][3], bl[0], bl[2]);
                mma16816(acc[i][1], a[i][0], a[i][1], a[i][2], a[i][3], bl[1], bl[3]);
                mma16816(acc[i][2], a[i][0], a[i][1], a[i][2], a[i][3], bl[4], bl[6]);
                mma16816(acc[i][3], a[i][0], a[i][1], a[i][2], a[i][3], bl[5], bl[7]);
            }
#pragma unroll
            for (int i = 0; i < 4; i++) {
                int row = wm * 64 + i * 16 + lrow;
                ldsm4(a[i][0], a[i][1], a[i][2], a[i][3], salo + row * GK_ROWB + khb);
            }
#pragma unroll
            for (int i = 0; i < 4; i++) {           // lh
                mma16816(acc[i][0], a[i][0], a[i][1], a[i][2], a[i][3], bh[0], bh[2]);
                mma16816(acc[i][1], a[i][0], a[i][1], a[i][2], a[i][3], bh[1], bh[3]);
                mma16816(acc[i][2], a[i][0], a[i][1], a[i][2], a[i][3], bh[4], bh[6]);
                mma16816(acc[i][3], a[i][0], a[i][1], a[i][2], a[i][3], bh[5], bh[7]);
            }
        }
    }

    // ---- epilogue ----
    const int r0 = lane >> 2;
    const int c0 = (lane & 3) * 2;
    if (mode == 1) {
#pragma unroll
        for (int j = 0; j < 4; j++) {
            const int col = n0 + wn * 32 + j * 8 + c0;
            const float2 bi = *(const float2*)&bias[col];
#pragma unroll
            for (int i = 0; i < 4; i++) {
                const int row = m0 + wm * 64 + i * 16 + r0;
                float2 o0 = {acc[i][j][0] + bi.x, acc[i][j][1] + bi.y};
                float2 o1 = {acc[i][j][2] + bi.x, acc[i][j][3] + bi.y};
                *(float2*)&OutF[(size_t)row * ldc + col] = o0;
                *(float2*)&OutF[(size_t)(row + 8) * ldc + col] = o1;
            }
        }
    } else {
#pragma unroll
        for (int j = 0; j < 4; j++) {
            const int col = n0 + wn * 32 + j * 8 + c0;
            const float2 bi = *(const float2*)&bias[col];
#pragma unroll
            for (int i = 0; i < 4; i++) {
                const int row = m0 + wm * 64 + i * 16 + r0;
                unsigned h0, l0, h1, l1;
                split_pair(acc[i][j][0] + bi.x, acc[i][j][1] + bi.y, h0, l0);
                split_pair(acc[i][j][2] + bi.x, acc[i][j][3] + bi.y, h1, l1);
                *(unsigned*)&g_fxhi[(size_t)row * 512 + col]       = h0;
                *(unsigned*)&g_fxlo[(size_t)row * 512 + col]       = l0;
                *(unsigned*)&g_fxhi[(size_t)(row + 8) * 512 + col] = h1;
                *(unsigned*)&g_fxlo[(size_t)(row + 8) * 512 + col] = l1;
            }
        }
    }
}

// ================= K_B: tensorized fused logits+softmax+pooling =================
// Phase 1 (1-pass): L = x_hi @ Wc_hi^T (K=256, 4 chunks) -> softmax -> w
// Phase 2 (3-pass): st = w^T @ fx -> atomicAdd partials

#define TOK 256
#define PA0  0                           // [256][144B] x chunks / fx_hi
#define PA1  36864                       // [256][144B] x chunks / fx_lo
#define PWC  73728                       // [64][528B]  Wc (hi)
#define PWTH 107520                      // [64][528B]  w^T hi
#define PWTL 141312                      // [64][528B]  w^T lo
#define PBSL 175104
#define PNRM 175360
#define SMEM_POOL 176640

__global__ void __launch_bounds__(256) k_pool(const float* __restrict__ temperature)
{
    char* sm = smem_dyn;
    const uint32_t sbase = smem_to_u32(sm);
    float* bslf = (float*)(sm + PBSL);
    float* nrmp = (float*)(sm + PNRM);

    const int h  = blockIdx.x;
    const int tb = blockIdx.y;
    const int b  = blockIdx.z;
    const int tid = threadIdx.x;
    const int wid = tid >> 5;
    const int lane = tid & 31;
    const int m0  = b * N_ + tb * TOK;
    const int lrow = lane & 15;
    const int lkq  = (lane >> 4) << 3;

    // prologue group: Wc (64x512B) + x chunk 0 -> PA0
#pragma unroll
    for (int it = 0; it < 8; it++) {
        int i = tid + it * 256;          // 2048 tasks
        int r = i >> 5, q = i & 31;
        CP_ASYNC16(sbase + PWC + r*528 + q*16, &g_Wc[(size_t)(h*64 + r)*256 + q*8]);
    }
#pragma unroll
    for (int it = 0; it < 8; it++) {
        int i = tid + it * 256;
        int r = i >> 3, q = i & 7;
        CP_ASYNC16(sbase + PA0 + r*144 + q*16,
                   &g_xhi[(size_t)(m0+r)*256 + q*8]);
    }
    CP_COMMIT();
    if (tid < 64) bslf[tid] = g_bcomb[h*64 + tid];

    // ---- phase 1 MMA (1-pass), K=256 in 4 chunks, distance-1 prefetch ----
    float acc[2][8][4];
#pragma unroll
    for (int i = 0; i < 2; i++)
#pragma unroll
        for (int j = 0; j < 8; j++)
#pragma unroll
            for (int e = 0; e < 4; e++) acc[i][j][e] = 0.f;

#pragma unroll
    for (int kc = 0; kc < 4; kc++) {
        CP_WAIT0();
        __syncthreads();
        if (kc + 1 < 4) {
            const uint32_t dstb = sbase + ((kc + 1) & 1 ? PA1 : PA0);
#pragma unroll
            for (int it = 0; it < 8; it++) {
                int i = tid + it * 256;
                int r = i >> 3, q = i & 7;
                CP_ASYNC16(dstb + r*144 + q*16,
                           &g_xhi[(size_t)(m0+r)*256 + (kc+1)*64 + q*8]);
            }
            CP_COMMIT();
        }
        const uint32_t abuf = sbase + ((kc & 1) ? PA1 : PA0);
#pragma unroll
        for (int ks = 0; ks < 4; ks++) {
            const int khA = (ks * 16 + lkq) * 2;
            const int khB = (kc * 64 + ks * 16 + lkq) * 2;
            uint32_t a[2][4], bh[16];
#pragma unroll
            for (int i = 0; i < 2; i++) {
                int row = wid * 32 + i * 16 + lrow;
                ldsm4(a[i][0], a[i][1], a[i][2], a[i][3], abuf + row*144 + khA);
            }
#pragma unroll
            for (int jp = 0; jp < 4; jp++) {
                int row = jp * 16 + lrow;
                ldsm4(bh[jp*4+0], bh[jp*4+1], bh[jp*4+2], bh[jp*4+3],
                      sbase + PWC + row*528 + khB);
            }
#pragma unroll
            for (int i = 0; i < 2; i++)
#pragma unroll
                for (int jj = 0; jj < 8; jj++) {
                    int jp = jj >> 1, o = jj & 1;
                    mma16816(acc[i][jj], a[i][0], a[i][1], a[i][2], a[i][3],
                             bh[jp*4+o], bh[jp*4+o+2]);
                }
        }
    }
    __syncthreads();   // all warps done reading PA0/PA1

    // prefetch fx hi/lo for phase 2 (overlaps softmax + w-writes)
#pragma unroll
    for (int it = 0; it < 8; it++) {
        int i = tid + it * 256;
        int r = i >> 3, q = i & 7;
        CP_ASYNC16(sbase + PA0 + r*144 + q*16,
                   &g_fxhi[(size_t)(m0+r)*512 + h*64 + q*8]);
        CP_ASYNC16(sbase + PA1 + r*144 + q*16,
                   &g_fxlo[(size_t)(m0+r)*512 + h*64 + q*8]);
    }
    CP_COMMIT();

    // ---- softmax over g (in registers, quad shuffles) ----
    float tmp = temperature[h];
    tmp = fminf(fmaxf(tmp, 0.1f), 5.0f);
    const float itemp = 1.0f / tmp;

#pragma unroll
    for (int i = 0; i < 2; i++)
#pragma unroll
        for (int j = 0; j < 8; j++) {
            float2 bi = *(float2*)&bslf[j*8 + (lane & 3)*2];
            acc[i][j][0] = (acc[i][j][0] + bi.x) * itemp;
            acc[i][j][1] = (acc[i][j][1] + bi.y) * itemp;
            acc[i][j][2] = (acc[i][j][2] + bi.x) * itemp;
            acc[i][j][3] = (acc[i][j][3] + bi.y) * itemp;
        }
    float inv0[2], inv1[2];
#pragma unroll
    for (int i = 0; i < 2; i++) {
        float m0v = -1e30f, m1v = -1e30f;
#pragma unroll
        for (int j = 0; j < 8; j++) {
            m0v = fmaxf(m0v, fmaxf(acc[i][j][0], acc[i][j][1]));
            m1v = fmaxf(m1v, fmaxf(acc[i][j][2], acc[i][j][3]));
        }
        m0v = fmaxf(m0v, __shfl_xor_sync(0xffffffff, m0v, 1));
        m0v = fmaxf(m0v, __shfl_xor_sync(0xffffffff, m0v, 2));
        m1v = fmaxf(m1v, __shfl_xor_sync(0xffffffff, m1v, 1));
        m1v = fmaxf(m1v, __shfl_xor_sync(0xffffffff, m1v, 2));
        float s0 = 0.f, s1 = 0.f;
#pragma unroll
        for (int j = 0; j < 8; j++) {
            acc[i][j][0] = __expf(acc[i][j][0] - m0v);
            acc[i][j][1] = __expf(acc[i][j][1] - m0v);
            acc[i][j][2] = __expf(acc[i][j][2] - m1v);
            acc[i][j][3] = __expf(acc[i][j][3] - m1v);
            s0 += acc[i][j][0] + acc[i][j][1];
            s1 += acc[i][j][2] + acc[i][j][3];
        }
        s0 += __shfl_xor_sync(0xffffffff, s0, 1);
        s0 += __shfl_xor_sync(0xffffffff, s0, 2);
        s1 += __shfl_xor_sync(0xffffffff, s1, 1);
        s1 += __shfl_xor_sync(0xffffffff, s1, 2);
        inv0[i] = 1.0f / s0;
        inv1[i] = 1.0f / s1;
    }

    // ---- write w: to WT smem (split, [g][t]) and to g_w gmem (split) ----
    {
        const int r = lane >> 2;
#pragma unroll
        for (int i = 0; i < 2; i++) {
            int t0 = wid * 32 + i * 16 + r;
            int t1 = t0 + 8;
#pragma unroll
            for (int j = 0; j < 8; j++) {
                int c = j * 8 + (lane & 3) * 2;
                float w00 = acc[i][j][0] * inv0[i], w01 = acc[i][j][1] * inv0[i];
                float w10 = acc[i][j][2] * inv1[i], w11 = acc[i][j][3] * inv1[i];
                unsigned h0, l0, h1, l1;
                split_pair(w00, w01, h0, l0);
                split_pair(w10, w11, h1, l1);
                *(unsigned*)&g_whi[(size_t)(m0 + t0)*512 + h*64 + c] = h0;
                *(unsigned*)&g_wlo[(size_t)(m0 + t0)*512 + h*64 + c] = l0;
                *(unsigned*)&g_whi[(size_t)(m0 + t1)*512 + h*64 + c] = h1;
                *(unsigned*)&g_wlo[(size_t)(m0 + t1)*512 + h*64 + c] = l1;
                *(__nv_bfloat16*)(sm + PWTH + c*528 + t0*2)     = __ushort_as_bfloat16((unsigned short)(h0 & 0xffff));
                *(__nv_bfloat16*)(sm + PWTH + (c+1)*528 + t0*2) = __ushort_as_bfloat16((unsigned short)(h0 >> 16));
                *(__nv_bfloat16*)(sm + PWTL + c*528 + t0*2)     = __ushort_as_bfloat16((unsigned short)(l0 & 0xffff));
                *(__nv_bfloat16*)(sm + PWTL + (c+1)*528 + t0*2) = __ushort_as_bfloat16((unsigned short)(l0 >> 16));
                *(__nv_bfloat16*)(sm + PWTH + c*528 + t1*2)     = __ushort_as_bfloat16((unsigned short)(h1 & 0xffff));
                *(__nv_bfloat16*)(sm + PWTH + (c+1)*528 + t1*2) = __ushort_as_bfloat16((unsigned short)(h1 >> 16));
                *(__nv_bfloat16*)(sm + PWTL + c*528 + t1*2)     = __ushort_as_bfloat16((unsigned short)(l1 & 0xffff));
                *(__nv_bfloat16*)(sm + PWTL + (c+1)*528 + t1*2) = __ushort_as_bfloat16((unsigned short)(l1 >> 16));
            }
        }
    }
    __syncthreads();   // WT visible to all

    // ---- norm partial sums (w^T row sums, hi+lo) ----
    {
        int g = tid & 63, q = tid >> 6;
        float s = 0.f;
        const __nv_bfloat16* ph = (const __nv_bfloat16*)(sm + PWTH + g*528);
        const __nv_bfloat16* pl = (const __nv_bfloat16*)(sm + PWTL + g*528);
#pragma unroll 8
        for (int t = q*64; t < q*64 + 64; t++)
            s += __bfloat162float(ph[t]) + __bfloat162float(pl[t]);
        nrmp[q*64 + g] = s;
    }
    __syncthreads();
    if (tid < 64) {
        float s = nrmp[tid] + nrmp[64+tid] + nrmp[128+tid] + nrmp[192+tid];
        atomicAdd(&g_nrm[(b*8 + h)*64 + tid], s);
    }
    CP_WAIT0();
    __syncthreads();

    // ---- phase 2 MMA: st[64x64] = w^T @ fx, K=256; warp tile 32x16; 3-pass ----
    const int wm2 = wid >> 2;
    const int wn2 = wid & 3;
    float ac2[2][2][4];
#pragma unroll
    for (int i = 0; i < 2; i++)
#pragma unroll
        for (int j = 0; j < 2; j++)
#pragma unroll
            for (int e = 0; e < 4; e++) ac2[i][j][e] = 0.f;

#pragma unroll
    for (int ks = 0; ks < 16; ks++) {
        const int khb = (ks * 16 + lkq) * 2;
        uint32_t a[2][4], bhv[4], blv[4];
#pragma unroll
        for (int i = 0; i < 2; i++) {
            int row = wm2 * 32 + i * 16 + lrow;
            ldsm4(a[i][0], a[i][1], a[i][2], a[i][3], sbase + PWTH + row*528 + khb);
        }
        {
            int trow = ks * 16 + lrow;
            uint32_t addr = sbase + PA0 + trow*144 + (wn2*16 + lkq)*2;
            ldsm4t(bhv[0], bhv[1], bhv[2], bhv[3], addr);
        }
#pragma unroll
        for (int i = 0; i < 2; i++) {
            mma16816(ac2[i][0], a[i][0], a[i][1], a[i][2], a[i][3], bhv[0], bhv[1]);
            mma16816(ac2[i][1], a[i][0], a[i][1], a[i][2], a[i][3], bhv[2], bhv[3]);
        }
        {
            int trow = ks * 16 + lrow;
            uint32_t addr = sbase + PA1 + trow*144 + (wn2*16 + lkq)*2;
            ldsm4t(blv[0], blv[1], blv[2], blv[3], addr);
        }
#pragma unroll
        for (int i = 0; i < 2; i++) {
            mma16816(ac2[i][0], a[i][0], a[i][1], a[i][2], a[i][3], blv[0], blv[1]);
            mma16816(ac2[i][1], a[i][0], a[i][1], a[i][2], a[i][3], blv[2], blv[3]);
        }
#pragma unroll
        for (int i = 0; i < 2; i++) {
            int row = wm2 * 32 + i * 16 + lrow;
            ldsm4(a[i][0], a[i][1], a[i][2], a[i][3], sbase + PWTL + row*528 + khb);
        }
#pragma unroll
        for (int i = 0; i < 2; i++) {
            mma16816(ac2[i][0], a[i][0], a[i][1], a[i][2], a[i][3], bhv[0], bhv[1]);
            mma16816(ac2[i][1], a[i][0], a[i][1], a[i][2], a[i][3], bhv[2], bhv[3]);
        }
    }

    // ---- atomic partial reduction into g_st ----
    {
        const int base = (b*8 + h) * 64;
        const int r = lane >> 2;
        const int cq = (lane & 3) * 2;
#pragma unroll
        for (int i = 0; i < 2; i++) {
            int g0r = wm2 * 32 + i * 16 + r;
#pragma unroll
            for (int jj = 0; jj < 2; jj++) {
                int d = wn2 * 16 + jj * 8 + cq;
                atomicAdd(&g_st[(base + g0r)*64 + d],     ac2[i][jj][0]);
                atomicAdd(&g_st[(base + g0r)*64 + d + 1], ac2[i][jj][1]);
                atomicAdd(&g_st[(base + g0r + 8)*64 + d],     ac2[i][jj][2]);
                atomicAdd(&g_st[(base + g0r + 8)*64 + d + 1], ac2[i][jj][3]);
            }
        }
    }
}

// ---------------- K_C1: tiny attention over slice tokens (256 thr) ----------------
#define SMEM_ATTN (5*64*65*4)            // 83200
__global__ void __launch_bounds__(256) k_attn(
    const float* __restrict__ Wq, const float* __restrict__ Wk,
    const float* __restrict__ Wv)
{
    float* sm = (float*)smem_dyn;
    float* S  = sm;
    float* Qs = sm + 64*65;
    float* Ks = sm + 2*64*65;
    float* Vs = sm + 3*64*65;
    float* Ps = sm + 4*64*65;

    const int h = blockIdx.x, b = blockIdx.y;
    const int tid = threadIdx.x;
    const int base = (b*8 + h) * 64;
    const int g  = tid >> 2;
    const int qd = (tid & 3) * 16;

    {
        float invn = 1.0f / (g_nrm[base + g] + 1e-5f);
#pragma unroll
        for (int j = 0; j < 16; j += 4) {
            float4 v = *(const float4*)&g_st[(base + g)*64 + qd + j];
            S[g*65 + qd + j]   = v.x * invn;
            S[g*65 + qd + j+1] = v.y * invn;
            S[g*65 + qd + j+2] = v.z * invn;
            S[g*65 + qd + j+3] = v.w * invn;
        }
    }
    __syncthreads();

    {
        float aq[16], ak[16], av[16];
#pragma unroll
        for (int j = 0; j < 16; j++) { aq[j] = 0.f; ak[j] = 0.f; av[j] = 0.f; }
        for (int k = 0; k < 64; k++) {
            float sv = S[g*65 + k];
            const float* wq = &Wq[k*64 + qd];
            const float* wk = &Wk[k*64 + qd];
            const float* wv = &Wv[k*64 + qd];
#pragma unroll
            for (int j = 0; j < 16; j++) {
                aq[j] += sv * wq[j];
                ak[j] += sv * wk[j];
                av[j] += sv * wv[j];
            }
        }
#pragma unroll
        for (int j = 0; j < 16; j++) {
            Qs[g*65 + qd + j] = aq[j];
            Ks[g*65 + qd + j] = ak[j];
            Vs[g*65 + qd + j] = av[j];
        }
    }
    __syncthreads();

    {
        float lg[16];
#pragma unroll
        for (int jj = 0; jj < 16; jj++) {
            int j = qd + jj;
            float dot = 0.f;
#pragma unroll
            for (int d = 0; d < 64; d++) dot += Qs[g*65 + d] * Ks[j*65 + d];
            lg[jj] = dot * 0.125f;
        }
        float mx = -1e30f;
#pragma unroll
        for (int jj = 0; jj < 16; jj++) mx = fmaxf(mx, lg[jj]);
        mx = fmaxf(mx, __shfl_xor_sync(0xffffffff, mx, 1));
        mx = fmaxf(mx, __shfl_xor_sync(0xffffffff, mx, 2));
        float s = 0.f;
#pragma unroll
        for (int jj = 0; jj < 16; jj++) { lg[jj] = __expf(lg[jj] - mx); s += lg[jj]; }
        s += __shfl_xor_sync(0xffffffff, s, 1);
        s += __shfl_xor_sync(0xffffffff, s, 2);
        float inv = 1.0f / s;
#pragma unroll
        for (int jj = 0; jj < 16; jj++) Ps[g*65 + qd + jj] = lg[jj] * inv;
    }
    __syncthreads();

    {
        float o[16];
#pragma unroll
        for (int d = 0; d < 16; d++) o[d] = 0.f;
        for (int j = 0; j < 64; j++) {
            float p = Ps[g*65 + j];
#pragma unroll
            for (int d = 0; d < 16; d++) o[d] += p * Vs[j*65 + qd + d];
        }
#pragma unroll
        for (int d = 0; d < 16; d++)
            g_os[(base + g)*64 + qd + d] = o[d];
    }
}

// ---------------- K_C2: P_t[b][c][h*64+g] split bf16 ----------------
#define SMEM_P ((64*68 + 64*256) * (int)sizeof(float))
__global__ void __launch_bounds__(256) k_P(const float* __restrict__ Wout)
{
    float* sm = (float*)smem_dyn;
    float* Os  = sm;
    float* Wsm = sm + 64*68;

    const int h = blockIdx.x, b = blockIdx.y;
    const int tid = threadIdx.x;
    const int base = (b*8 + h) * 64;

    for (int i = tid; i < 64*16; i += 256) {
        int r = i >> 4, c = i & 15;
        *(float4*)&Os[r*68 + c*4] = *(const float4*)&g_os[(size_t)(base + r)*64 + c*4];
    }
    for (int i = tid; i < 64*64; i += 256) {
        int r = i >> 6, c = i & 63;
        *(float4*)&Wsm[r*256 + c*4] = *(const float4*)&Wout[(size_t)(h*64 + r)*256 + c*4];
    }
    __syncthreads();

    const int gq = tid >> 3;
    const int cq = tid & 7;
    const int g0 = gq * 2;
    const int c0 = cq * 32;

    float acc[2][32];
#pragma unroll
    for (int i = 0; i < 2; i++)
#pragma unroll
        for (int j = 0; j < 32; j++) acc[i][j] = 0.f;

    for (int k = 0; k < 64; k++) {
        float a0 = Os[(g0+0)*68 + k];
        float a1 = Os[(g0+1)*68 + k];
#pragma unroll
        for (int c4 = 0; c4 < 8; c4++) {
            float4 w = *(float4*)&Wsm[k*256 + c0 + c4*4];
            acc[0][c4*4+0] += a0*w.x; acc[0][c4*4+1] += a0*w.y;
            acc[0][c4*4+2] += a0*w.z; acc[0][c4*4+3] += a0*w.w;
            acc[1][c4*4+0] += a1*w.x; acc[1][c4*4+1] += a1*w.y;
            acc[1][c4*4+2] += a1*w.z; acc[1][c4*4+3] += a1*w.w;
        }
    }
    __nv_bfloat16* Ph = &g_Pthi[(size_t)b * C_ * INNER_];
    __nv_bfloat16* Pl = &g_Ptlo[(size_t)b * C_ * INNER_];
#pragma unroll
    for (int i = 0; i < 2; i++)
#pragma unroll
        for (int c4 = 0; c4 < 8; c4++)
#pragma unroll
            for (int e = 0; e < 4; e++) {
                size_t off = (size_t)(c0 + c4*4 + e) * INNER_ + h*64 + g0 + i;
                __nv_bfloat16 hi, lo;
                split_one(acc[i][c4*4+e], hi, lo);
                Ph[off] = hi;
                Pl[off] = lo;
            }
}

// ---------------- launch ----------------
extern "C" void kernel_launch(void* const* d_in, const int* in_sizes, int n_in,
                              void* d_out, int out_size)
{
    const float* x    = (const float*)d_in[0];
    const float* Wfx  = (const float*)d_in[1];
    const float* bfx  = (const float*)d_in[2];
    const float* Wx   = (const float*)d_in[3];
    const float* bx   = (const float*)d_in[4];
    const float* Wsl  = (const float*)d_in[5];
    const float* bsl  = (const float*)d_in[6];
    const float* temp = (const float*)d_in[7];
    const float* Wq   = (const float*)d_in[8];
    const float* Wk   = (const float*)d_in[9];
    const float* Wv   = (const float*)d_in[10];
    const float* Wout = (const float*)d_in[11];
    const float* bout = (const float*)d_in[12];
    float* out = (float*)d_out;

    static bool init = false;
    static float *g_bias0_p;
    static __nv_bfloat16 *g_xhi_p, *g_xlo_p, *g_Whi_p, *g_Wlo_p;
    static __nv_bfloat16 *g_whi_p, *g_wlo_p, *g_Pthi_p, *g_Ptlo_p;
    if (!init) {
        cudaGetSymbolAddress((void**)&g_bias0_p, g_bias0);
        cudaGetSymbolAddress((void**)&g_xhi_p,   g_xhi);
        cudaGetSymbolAddress((void**)&g_xlo_p,   g_xlo);
        cudaGetSymbolAddress((void**)&g_Whi_p,   g_Whi);
        cudaGetSymbolAddress((void**)&g_Wlo_p,   g_Wlo);
        cudaGetSymbolAddress((void**)&g_whi_p,   g_whi);
        cudaGetSymbolAddress((void**)&g_wlo_p,   g_wlo);
        cudaGetSymbolAddress((void**)&g_Pthi_p,  g_Pthi);
        cudaGetSymbolAddress((void**)&g_Ptlo_p,  g_Ptlo);
        cudaFuncSetAttribute(k_gemm_ts, cudaFuncAttributeMaxDynamicSharedMemorySize, GK_SMEM);
        cudaFuncSetAttribute(k_pool, cudaFuncAttributeMaxDynamicSharedMemorySize, SMEM_POOL);
        cudaFuncSetAttribute(k_attn, cudaFuncAttributeMaxDynamicSharedMemorySize, SMEM_ATTN);
        cudaFuncSetAttribute(k_P,    cudaFuncAttributeMaxDynamicSharedMemorySize, SMEM_P);
        init = true;
    }

    // 0) zero accumulators + operand prep
    k_zero<<<(B_*H_*G_*D_ + 255)/256, 256>>>();
    k_split_x<<<(BNTOK * 256 / 4) / 256, 256>>>(x);
    k_split_W<<<131072 / 256, 256>>>(Wfx, bfx);
    k_comb<<<dim3(8, 16), 256>>>(Wx, Wsl, bx, bsl);

    // 1) projections: fx only (tensor cores, 3-pass)
    k_gemm_ts<<<dim3(4, BNTOK/128), 256, GK_SMEM>>>(
        g_xhi_p, g_xlo_p, g_Whi_p, g_Wlo_p, 256, 0, g_bias0_p, nullptr, 0);

    // 2) fused logits/softmax/pooling (tensor cores; logits via W_comb)
    k_pool<<<dim3(H_, N_/TOK, B_), 256, SMEM_POOL>>>(temp);

    // 3) tiny attention over slice tokens
    k_attn<<<dim3(H_, B_), 256, SMEM_ATTN>>>(Wq, Wk, Wv);

    // 4) P precompute (transposed + split)
    k_P<<<dim3(H_, B_), 256, SMEM_P>>>(Wout);

    // 5) output GEMM (tensor cores, 3-pass)
    k_gemm_ts<<<dim3(2, BNTOK/128), 256, GK_SMEM>>>(
        g_whi_p, g_wlo_p, g_Pthi_p, g_Ptlo_p, 512, 1, bout, out, 256);
}

// round 10
// speedup vs baseline: 1.0882x; 1.0015x over previous
#include <cuda_runtime.h>
#include <cuda_bf16.h>
#include <cstdint>
#include <math.h>

#define B_      4
#define N_      32768
#define C_      256
#define H_      8
#define D_      64
#define G_      64
#define INNER_  512
#define BNTOK   (B_*N_)          // 131072

// single dynamic smem symbol shared by all kernels
extern __shared__ char smem_dyn[];

// ---------------- scratch (device globals; allocation-free) ----------------
__device__ __nv_bfloat16 g_fxhi[(size_t)BNTOK * 512]; // fx split hi  [m][512]
__device__ __nv_bfloat16 g_fxlo[(size_t)BNTOK * 512]; // fx split lo
__device__ __nv_bfloat16 g_xhi[(size_t)BNTOK * 256];
__device__ __nv_bfloat16 g_xlo[(size_t)BNTOK * 256];
__device__ __nv_bfloat16 g_Whi[512 * 256];           // [n][k] transposed W_fx
__device__ __nv_bfloat16 g_Wlo[512 * 256];
__device__ float g_bias0[512];
__device__ __nv_bfloat16 g_Wc[H_ * 64 * 256];        // combined W_x@Ws, [h][g][c]
__device__ float g_bcomb[H_ * 64];
__device__ __nv_bfloat16 g_whi[(size_t)BNTOK * 512]; // slice weights hi
__device__ __nv_bfloat16 g_wlo[(size_t)BNTOK * 512];
__device__ __nv_bfloat16 g_Pthi[B_ * C_ * INNER_];
__device__ __nv_bfloat16 g_Ptlo[B_ * C_ * INNER_];
__device__ float g_st [B_*H_*G_*D_];
__device__ float g_nrm[B_*H_*G_];
__device__ float g_os [B_*H_*G_*D_];

// ---------------- helpers ----------------
__device__ __forceinline__ uint32_t smem_to_u32(const void* p) {
    uint32_t a;
    asm("{ .reg .u64 t; cvta.to.shared.u64 t, %1; cvt.u32.u64 %0, t; }" : "=r"(a) : "l"(p));
    return a;
}
__device__ __forceinline__ void ldsm4(uint32_t &r0, uint32_t &r1, uint32_t &r2, uint32_t &r3,
                                      uint32_t addr) {
    asm volatile("ldmatrix.sync.aligned.m8n8.x4.shared.b16 {%0,%1,%2,%3}, [%4];"
        : "=r"(r0), "=r"(r1), "=r"(r2), "=r"(r3) : "r"(addr));
}
__device__ __forceinline__ void ldsm4t(uint32_t &r0, uint32_t &r1, uint32_t &r2, uint32_t &r3,
                                       uint32_t addr) {
    asm volatile("ldmatrix.sync.aligned.m8n8.x4.trans.shared.b16 {%0,%1,%2,%3}, [%4];"
        : "=r"(r0), "=r"(r1), "=r"(r2), "=r"(r3) : "r"(addr));
}
__device__ __forceinline__ void mma16816(float* c,
                                         uint32_t a0, uint32_t a1, uint32_t a2, uint32_t a3,
                                         uint32_t b0, uint32_t b1) {
    asm volatile(
        "mma.sync.aligned.m16n8k16.row.col.f32.bf16.bf16.f32 "
        "{%0,%1,%2,%3}, {%4,%5,%6,%7}, {%8,%9}, {%0,%1,%2,%3};"
        : "+f"(c[0]), "+f"(c[1]), "+f"(c[2]), "+f"(c[3])
        : "r"(a0), "r"(a1), "r"(a2), "r"(a3), "r"(b0), "r"(b1));
}
__device__ __forceinline__ void split_one(float a, __nv_bfloat16 &hi, __nv_bfloat16 &lo) {
    hi = __float2bfloat16(a);
    lo = __float2bfloat16(a - __bfloat162float(hi));
}
__device__ __forceinline__ void split_pair(float a, float b, unsigned &hi, unsigned &lo) {
    __nv_bfloat16 ah, al, bh, bl;
    split_one(a, ah, al);
    split_one(b, bh, bl);
    hi = ((unsigned)__bfloat16_as_ushort(bh) << 16) | (unsigned)__bfloat16_as_ushort(ah);
    lo = ((unsigned)__bfloat16_as_ushort(bl) << 16) | (unsigned)__bfloat16_as_ushort(al);
}
#define CP_ASYNC16(dst, src) \
    asm volatile("cp.async.cg.shared.global [%0], [%1], 16;" :: "r"(dst), "l"(src))
#define CP_COMMIT()  asm volatile("cp.async.commit_group;")
#define CP_WAIT0()   asm volatile("cp.async.wait_group 0;")

// ---------------- K_sx: split x into bf16 hi/lo ----------------
__global__ void __launch_bounds__(256) k_split_x(const float* __restrict__ x) {
    size_t i = (size_t)blockIdx.x * 256 + threadIdx.x;
    float4 v = *(const float4*)(x + i * 4);
    unsigned h0, l0, h1, l1;
    split_pair(v.x, v.y, h0, l0);
    split_pair(v.z, v.w, h1, l1);
    *(uint2*)&g_xhi[i * 4] = make_uint2(h0, h1);
    *(uint2*)&g_xlo[i * 4] = make_uint2(l0, l1);
}

// ---------------- K_prep: fused zero + split_W + comb (grid role split) --------
// blocks [0,512): zero accumulators; [512,1024): split W_fx; [1024,1152): W_comb
__global__ void __launch_bounds__(256) k_prep(
    const float* __restrict__ Wfx, const float* __restrict__ bfx,
    const float* __restrict__ Wx, const float* __restrict__ Wsl,
    const float* __restrict__ bx, const float* __restrict__ bsl)
{
    __shared__ float sws[64*64];
    const int bid = blockIdx.x;
    const int tid = threadIdx.x;

    if (bid < 512) {
        int i = bid * 256 + tid;
        g_st[i] = 0.f;
        if (i < B_*H_*G_) g_nrm[i] = 0.f;
        return;
    }
    if (bid < 1024) {
        int idx = (bid - 512) * 256 + tid;    // 131072 total
        int n = idx & 511;
        int k = idx >> 9;
        float v = Wfx[k * 512 + n];
        __nv_bfloat16 hi, lo;
        split_one(v, hi, lo);
        g_Whi[n * 256 + k] = hi;
        g_Wlo[n * 256 + k] = lo;
        if (bid == 512) {
            for (int j = tid; j < 512; j += 256)
                g_bias0[j] = bfx[j];
        }
        return;
    }
    // comb: r in [0,128): h = r&7, cb = r>>3
    const int r  = bid - 1024;
    const int h  = r & 7;
    const int cb = r >> 3;
    for (int i = tid; i < 4096; i += 256) sws[i] = Wsl[i];
    __syncthreads();
    const int g = tid & 63, cq = tid >> 6;
#pragma unroll
    for (int cc = 0; cc < 4; cc++) {
        int c = cb * 16 + cq * 4 + cc;
        float s = 0.f;
        const float* wxr = &Wx[(size_t)c * 512 + h * 64];
#pragma unroll 16
        for (int d = 0; d < 64; d++) s += wxr[d] * sws[d*64 + g];
        g_Wc[(h*64 + g)*256 + c] = __float2bfloat16(s);
    }
    if (cb == 0 && tid < 64) {
        float s = bsl[tid];
        for (int d = 0; d < 64; d++) s += bx[h*64 + d] * sws[d*64 + tid];
        g_bcomb[h*64 + tid] = s;
    }
}

// ================= split-bf16 tensor-core GEMM, cp.async pipelined =================
#define GK_ROWB 80
#define GK_ARR  (128 * GK_ROWB)
#define GK_STG  (4 * GK_ARR)
#define GK_SMEM (2 * GK_STG)

__global__ void __launch_bounds__(256, 2) k_gemm_ts(
    const __nv_bfloat16* __restrict__ Ahi, const __nv_bfloat16* __restrict__ Alo,
    const __nv_bfloat16* __restrict__ Bhi, const __nv_bfloat16* __restrict__ Blo,
    int K, int mode,
    const float* __restrict__ bias,
    float* __restrict__ OutF, int ldc)
{
    char* sm = smem_dyn;
    const uint32_t sbase = smem_to_u32(sm);

    const int tid  = threadIdx.x;
    const int wid  = tid >> 5;
    const int lane = tid & 31;
    const int wm   = wid >> 2;
    const int wn   = wid & 3;
    const int m0   = blockIdx.y * 128;
    const int n0   = blockIdx.x * 128;

    const __nv_bfloat16* srcs[4];
    srcs[0] = Ahi + (size_t)m0 * K;
    srcs[1] = Alo + (size_t)m0 * K;
    size_t boff = (size_t)(mode ? (m0 >> 15) : 0) * 256 * INNER_ + (size_t)n0 * K;
    srcs[2] = Bhi + boff;
    srcs[3] = Blo + boff;

    const int srow0 = tid >> 2,         sq0 = tid & 3;
    const int srow1 = (tid + 256) >> 2, sq1 = (tid + 256) & 3;

    float acc[4][4][4];
#pragma unroll
    for (int i = 0; i < 4; i++)
#pragma unroll
        for (int j = 0; j < 4; j++)
#pragma unroll
            for (int e = 0; e < 4; e++) acc[i][j][e] = 0.f;

    const int lrow = lane & 15;
    const int lkq  = (lane >> 4) << 3;
    const int nch  = K >> 5;

#pragma unroll
    for (int arr = 0; arr < 4; arr++) {
        const __nv_bfloat16* s = srcs[arr];
        uint32_t d = sbase + arr * GK_ARR;
        CP_ASYNC16(d + srow0 * GK_ROWB + sq0 * 16, s + (size_t)srow0 * K + sq0 * 8);
        CP_ASYNC16(d + srow1 * GK_ROWB + sq1 * 16, s + (size_t)srow1 * K + sq1 * 8);
    }
    CP_COMMIT();

    for (int ch = 0; ch < nch; ch++) {
        CP_WAIT0();
        __syncthreads();
        if (ch + 1 < nch) {
            const int k1 = (ch + 1) << 5;
            const uint32_t stg = sbase + ((ch + 1) & 1) * GK_STG;
#pragma unroll
            for (int arr = 0; arr < 4; arr++) {
                const __nv_bfloat16* s = srcs[arr] + k1;
                uint32_t d = stg + arr * GK_ARR;
                CP_ASYNC16(d + srow0 * GK_ROWB + sq0 * 16, s + (size_t)srow0 * K + sq0 * 8);
                CP_ASYNC16(d + srow1 * GK_ROWB + sq1 * 16, s + (size_t)srow1 * K + sq1 * 8);
            }
            CP_COMMIT();
        }

        const uint32_t stg  = sbase + (ch & 1) * GK_STG;
        const uint32_t sahi = stg, salo = stg + GK_ARR;
        const uint32_t sbhi = stg + 2 * GK_ARR, sblo = stg + 3 * GK_ARR;

#pragma unroll
        for (int ks = 0; ks < 2; ks++) {
            const int khb = (ks * 16 + lkq) * 2;
            uint32_t a[4][4], bh[8], bl[8];
#pragma unroll
            for (int i = 0; i < 4; i++) {
                int row = wm * 64 + i * 16 + lrow;
                ldsm4(a[i][0], a[i][1], a[i][2], a[i][3], sahi + row * GK_ROWB + khb);
            }
#pragma unroll
            for (int jp = 0; jp < 2; jp++) {
                int row = wn * 32 + jp * 16 + lrow;
                ldsm4(bh[jp*4+0], bh[jp*4+1], bh[jp*4+2], bh[jp*4+3],
                      sbhi + row * GK_ROWB + khb);
            }
#pragma unroll
            for (int i = 0; i < 4; i++) {
                mma16816(acc[i][0], a[i][0], a[i][1], a[i][2], a[i][3], bh[0], bh[2]);
                mma16816(acc[i][1], a[i][0], a[i][1], a[i][2], a[i][3], bh[1], bh[3]);
                mma16816(acc[i][2], a[i][0], a[i][1], a[i][2], a[i][3], bh[4], bh[6]);
                mma16816(acc[i][3], a[i][0], a[i][1], a[i][2], a[i][3], bh[5], bh[7]);
            }
#pragma unroll
            for (int jp = 0; jp < 2; jp++) {
                int row = wn * 32 + jp * 16 + lrow;
                ldsm4(bl[jp*4+0], bl[jp*4+1], bl[jp*4+2], bl[jp*4+3],
                      sblo + row * GK_ROWB + khb);
            }
#pragma unroll
            for (int i = 0; i < 4; i++) {
                mma16816(acc[i][0], a[i][0], a[i][1], a[i][2], a[i][3], bl[0], bl[2]);
                mma16816(acc[i][1], a[i][0], a[i][1], a[i][2], a[i][3], bl[1], bl[3]);
                mma16816(acc[i][2], a[i][0], a[i][1], a[i][2], a[i][3], bl[4], bl[6]);
                mma16816(acc[i][3], a[i][0], a[i][1], a[i][2], a[i][3], bl[5], bl[7]);
            }
#pragma unroll
            for (int i = 0; i < 4; i++) {
                int row = wm * 64 + i * 16 + lrow;
                ldsm4(a[i][0], a[i][1], a[i][2], a[i][3], salo + row * GK_ROWB + khb);
            }
#pragma unroll
            for (int i = 0; i < 4; i++) {
                mma16816(acc[i][0], a[i][0], a[i][1], a[i][2], a[i][3], bh[0], bh[2]);
                mma16816(acc[i][1], a[i][0], a[i][1], a[i][2], a[i][3], bh[1], bh[3]);
                mma16816(acc[i][2], a[i][0], a[i][1], a[i][2], a[i][3], bh[4], bh[6]);
                mma16816(acc[i][3], a[i][0], a[i][1], a[i][2], a[i][3], bh[5], bh[7]);
            }
        }
    }

    // ---- epilogue ----
    const int r0 = lane >> 2;
    const int c0 = (lane & 3) * 2;
    if (mode == 1) {
#pragma unroll
        for (int j = 0; j < 4; j++) {
            const int col = n0 + wn * 32 + j * 8 + c0;
            const float2 bi = *(const float2*)&bias[col];
#pragma unroll
            for (int i = 0; i < 4; i++) {
                const int row = m0 + wm * 64 + i * 16 + r0;
                float2 o0 = {acc[i][j][0] + bi.x, acc[i][j][1] + bi.y};
                float2 o1 = {acc[i][j][2] + bi.x, acc[i][j][3] + bi.y};
                *(float2*)&OutF[(size_t)row * ldc + col] = o0;
                *(float2*)&OutF[(size_t)(row + 8) * ldc + col] = o1;
            }
        }
    } else {
#pragma unroll
        for (int j = 0; j < 4; j++) {
            const int col = n0 + wn * 32 + j * 8 + c0;
            const float2 bi = *(const float2*)&bias[col];
#pragma unroll
            for (int i = 0; i < 4; i++) {
                const int row = m0 + wm * 64 + i * 16 + r0;
                unsigned h0, l0, h1, l1;
                split_pair(acc[i][j][0] + bi.x, acc[i][j][1] + bi.y, h0, l0);
                split_pair(acc[i][j][2] + bi.x, acc[i][j][3] + bi.y, h1, l1);
                *(unsigned*)&g_fxhi[(size_t)row * 512 + col]       = h0;
                *(unsigned*)&g_fxlo[(size_t)row * 512 + col]       = l0;
                *(unsigned*)&g_fxhi[(size_t)(row + 8) * 512 + col] = h1;
                *(unsigned*)&g_fxlo[(size_t)(row + 8) * 512 + col] = l1;
            }
        }
    }
}

// ================= K_B: tensorized fused logits+softmax+pooling =================
// Phase 1 (1-pass): L = x_hi @ Wc_hi^T (K=256, 4 chunks) -> softmax -> w
// w stored in SMEM as [t][g] (natural layout, 4B stores); phase-2 A via ldsm.trans.
// Phase 2 (3-pass): st = w^T @ fx -> atomicAdd partials

#define TOK 256
#define PA0   0                          // [256][144B] x chunks / fx_hi
#define PA1   36864                      // [256][144B] x chunks / fx_lo
#define PWC   73728                      // [64][528B]  Wc (hi)
#define PWTH  107520                     // [256][144B] w hi, [t][g]
#define PWTL  144384                     // [256][144B] w lo, [t][g]
#define PBSL  181248
#define PNRM  181504
#define SMEM_POOL 182528

__global__ void __launch_bounds__(256) k_pool(const float* __restrict__ temperature)
{
    char* sm = smem_dyn;
    const uint32_t sbase = smem_to_u32(sm);
    float* bslf = (float*)(sm + PBSL);
    float* nrmp = (float*)(sm + PNRM);

    const int h  = blockIdx.x;
    const int tb = blockIdx.y;
    const int b  = blockIdx.z;
    const int tid = threadIdx.x;
    const int wid = tid >> 5;
    const int lane = tid & 31;
    const int m0  = b * N_ + tb * TOK;
    const int lrow = lane & 15;
    const int lkq  = (lane >> 4) << 3;

    // prologue group: Wc (64x512B) + x chunk 0 -> PA0
#pragma unroll
    for (int it = 0; it < 8; it++) {
        int i = tid + it * 256;
        int r = i >> 5, q = i & 31;
        CP_ASYNC16(sbase + PWC + r*528 + q*16, &g_Wc[(size_t)(h*64 + r)*256 + q*8]);
    }
#pragma unroll
    for (int it = 0; it < 8; it++) {
        int i = tid + it * 256;
        int r = i >> 3, q = i & 7;
        CP_ASYNC16(sbase + PA0 + r*144 + q*16,
                   &g_xhi[(size_t)(m0+r)*256 + q*8]);
    }
    CP_COMMIT();
    if (tid < 64) bslf[tid] = g_bcomb[h*64 + tid];

    // ---- phase 1 MMA (1-pass), K=256 in 4 chunks, distance-1 prefetch ----
    float acc[2][8][4];
#pragma unroll
    for (int i = 0; i < 2; i++)
#pragma unroll
        for (int j = 0; j < 8; j++)
#pragma unroll
            for (int e = 0; e < 4; e++) acc[i][j][e] = 0.f;

#pragma unroll
    for (int kc = 0; kc < 4; kc++) {
        CP_WAIT0();
        __syncthreads();
        if (kc + 1 < 4) {
            const uint32_t dstb = sbase + ((kc + 1) & 1 ? PA1 : PA0);
#pragma unroll
            for (int it = 0; it < 8; it++) {
                int i = tid + it * 256;
                int r = i >> 3, q = i & 7;
                CP_ASYNC16(dstb + r*144 + q*16,
                           &g_xhi[(size_t)(m0+r)*256 + (kc+1)*64 + q*8]);
            }
            CP_COMMIT();
        }
        const uint32_t abuf = sbase + ((kc & 1) ? PA1 : PA0);
#pragma unroll
        for (int ks = 0; ks < 4; ks++) {
            const int khA = (ks * 16 + lkq) * 2;
            const int khB = (kc * 64 + ks * 16 + lkq) * 2;
            uint32_t a[2][4], bh[16];
#pragma unroll
            for (int i = 0; i < 2; i++) {
                int row = wid * 32 + i * 16 + lrow;
                ldsm4(a[i][0], a[i][1], a[i][2], a[i][3], abuf + row*144 + khA);
            }
#pragma unroll
            for (int jp = 0; jp < 4; jp++) {
                int row = jp * 16 + lrow;
                ldsm4(bh[jp*4+0], bh[jp*4+1], bh[jp*4+2], bh[jp*4+3],
                      sbase + PWC + row*528 + khB);
            }
#pragma unroll
            for (int i = 0; i < 2; i++)
#pragma unroll
                for (int jj = 0; jj < 8; jj++) {
                    int jp = jj >> 1, o = jj & 1;
                    mma16816(acc[i][jj], a[i][0], a[i][1], a[i][2], a[i][3],
                             bh[jp*4+o], bh[jp*4+o+2]);
                }
        }
    }
    __syncthreads();   // all warps done reading PA0/PA1

    // prefetch fx hi/lo for phase 2 (overlaps softmax + w-writes)
#pragma unroll
    for (int it = 0; it < 8; it++) {
        int i = tid + it * 256;
        int r = i >> 3, q = i & 7;
        CP_ASYNC16(sbase + PA0 + r*144 + q*16,
                   &g_fxhi[(size_t)(m0+r)*512 + h*64 + q*8]);
        CP_ASYNC16(sbase + PA1 + r*144 + q*16,
                   &g_fxlo[(size_t)(m0+r)*512 + h*64 + q*8]);
    }
    CP_COMMIT();

    // ---- softmax over g (in registers, quad shuffles) ----
    float tmp = temperature[h];
    tmp = fminf(fmaxf(tmp, 0.1f), 5.0f);
    const float itemp = 1.0f / tmp;

#pragma unroll
    for (int i = 0; i < 2; i++)
#pragma unroll
        for (int j = 0; j < 8; j++) {
            float2 bi = *(float2*)&bslf[j*8 + (lane & 3)*2];
            acc[i][j][0] = (acc[i][j][0] + bi.x) * itemp;
            acc[i][j][1] = (acc[i][j][1] + bi.y) * itemp;
            acc[i][j][2] = (acc[i][j][2] + bi.x) * itemp;
            acc[i][j][3] = (acc[i][j][3] + bi.y) * itemp;
        }
    float inv0[2], inv1[2];
#pragma unroll
    for (int i = 0; i < 2; i++) {
        float m0v = -1e30f, m1v = -1e30f;
#pragma unroll
        for (int j = 0; j < 8; j++) {
            m0v = fmaxf(m0v, fmaxf(acc[i][j][0], acc[i][j][1]));
            m1v = fmaxf(m1v, fmaxf(acc[i][j][2], acc[i][j][3]));
        }
        m0v = fmaxf(m0v, __shfl_xor_sync(0xffffffff, m0v, 1));
        m0v = fmaxf(m0v, __shfl_xor_sync(0xffffffff, m0v, 2));
        m1v = fmaxf(m1v, __shfl_xor_sync(0xffffffff, m1v, 1));
        m1v = fmaxf(m1v, __shfl_xor_sync(0xffffffff, m1v, 2));
        float s0 = 0.f, s1 = 0.f;
#pragma unroll
        for (int j = 0; j < 8; j++) {
            acc[i][j][0] = __expf(acc[i][j][0] - m0v);
            acc[i][j][1] = __expf(acc[i][j][1] - m0v);
            acc[i][j][2] = __expf(acc[i][j][2] - m1v);
            acc[i][j][3] = __expf(acc[i][j][3] - m1v);
            s0 += acc[i][j][0] + acc[i][j][1];
            s1 += acc[i][j][2] + acc[i][j][3];
        }
        s0 += __shfl_xor_sync(0xffffffff, s0, 1);
        s0 += __shfl_xor_sync(0xffffffff, s0, 2);
        s1 += __shfl_xor_sync(0xffffffff, s1, 1);
        s1 += __shfl_xor_sync(0xffffffff, s1, 2);
        inv0[i] = 1.0f / s0;
        inv1[i] = 1.0f / s1;
    }

    // ---- write w: to [t][g] smem (packed 4B) and to g_w gmem (split) ----
    {
        const int r = lane >> 2;
#pragma unroll
        for (int i = 0; i < 2; i++) {
            int t0 = wid * 32 + i * 16 + r;
            int t1 = t0 + 8;
#pragma unroll
            for (int j = 0; j < 8; j++) {
                int c = j * 8 + (lane & 3) * 2;
                float w00 = acc[i][j][0] * inv0[i], w01 = acc[i][j][1] * inv0[i];
                float w10 = acc[i][j][2] * inv1[i], w11 = acc[i][j][3] * inv1[i];
                unsigned h0, l0, h1, l1;
                split_pair(w00, w01, h0, l0);
                split_pair(w10, w11, h1, l1);
                *(unsigned*)&g_whi[(size_t)(m0 + t0)*512 + h*64 + c] = h0;
                *(unsigned*)&g_wlo[(size_t)(m0 + t0)*512 + h*64 + c] = l0;
                *(unsigned*)&g_whi[(size_t)(m0 + t1)*512 + h*64 + c] = h1;
                *(unsigned*)&g_wlo[(size_t)(m0 + t1)*512 + h*64 + c] = l1;
                *(unsigned*)(sm + PWTH + t0*144 + c*2) = h0;
                *(unsigned*)(sm + PWTL + t0*144 + c*2) = l0;
                *(unsigned*)(sm + PWTH + t1*144 + c*2) = h1;
                *(unsigned*)(sm + PWTL + t1*144 + c*2) = l1;
            }
        }
    }
    __syncthreads();   // w visible to all

    // ---- norm partial sums (column sums over t in [t][g] layout) ----
    {
        int g = tid & 63, q = tid >> 6;
        float s = 0.f;
#pragma unroll 8
        for (int t = q*64; t < q*64 + 64; t++) {
            s += __bfloat162float(*(__nv_bfloat16*)(sm + PWTH + t*144 + g*2));
            s += __bfloat162float(*(__nv_bfloat16*)(sm + PWTL + t*144 + g*2));
        }
        nrmp[q*64 + g] = s;
    }
    __syncthreads();
    if (tid < 64) {
        float s = nrmp[tid] + nrmp[64+tid] + nrmp[128+tid] + nrmp[192+tid];
        atomicAdd(&g_nrm[(b*8 + h)*64 + tid], s);
    }
    CP_WAIT0();
    __syncthreads();

    // ---- phase 2 MMA: st[64x64] = w^T @ fx, K=256 (t); warp tile 32x16; 3-pass ----
    // A = w^T (g x t) loaded from [t][g] storage via ldsm.trans.
    const int wm2 = wid >> 2;
    const int wn2 = wid & 3;
    // trans-A lane mapping: tiles r0..r3 <- (t0-7,g0-7),(t0-7,g8-15),(t8-15,g0-7),(t8-15,g8-15)
    const int trowA = (lane & 7) | ((lane >> 1) & 8);   // lanes 16+ -> +8 t-rows
    const int gselA = (lane & 8) * 2;                    // lanes 8-15,24-31 -> +16 bytes (g+8)

    float ac2[2][2][4];
#pragma unroll
    for (int i = 0; i < 2; i++)
#pragma unroll
        for (int j = 0; j < 2; j++)
#pragma unroll
            for (int e = 0; e < 4; e++) ac2[i][j][e] = 0.f;

#pragma unroll
    for (int ks = 0; ks < 16; ks++) {
        uint32_t a[2][4], bhv[4], blv[4];
#pragma unroll
        for (int i = 0; i < 2; i++) {
            int g0w = wm2 * 32 + i * 16;
            uint32_t addr = sbase + PWTH + (ks*16 + trowA)*144 + g0w*2 + gselA;
            ldsm4t(a[i][0], a[i][1], a[i][2], a[i][3], addr);
        }
        {
            int trow = ks * 16 + lrow;
            uint32_t addr = sbase + PA0 + trow*144 + (wn2*16 + lkq)*2;
            ldsm4t(bhv[0], bhv[1], bhv[2], bhv[3], addr);
        }
#pragma unroll
        for (int i = 0; i < 2; i++) {
            mma16816(ac2[i][0], a[i][0], a[i][1], a[i][2], a[i][3], bhv[0], bhv[1]);
            mma16816(ac2[i][1], a[i][0], a[i][1], a[i][2], a[i][3], bhv[2], bhv[3]);
        }
        {
            int trow = ks * 16 + lrow;
            uint32_t addr = sbase + PA1 + trow*144 + (wn2*16 + lkq)*2;
            ldsm4t(blv[0], blv[1], blv[2], blv[3], addr);
        }
#pragma unroll
        for (int i = 0; i < 2; i++) {
            mma16816(ac2[i][0], a[i][0], a[i][1], a[i][2], a[i][3], blv[0], blv[1]);
            mma16816(ac2[i][1], a[i][0], a[i][1], a[i][2], a[i][3], blv[2], blv[3]);
        }
#pragma unroll
        for (int i = 0; i < 2; i++) {
            int g0w = wm2 * 32 + i * 16;
            uint32_t addr = sbase + PWTL + (ks*16 + trowA)*144 + g0w*2 + gselA;
            ldsm4t(a[i][0], a[i][1], a[i][2], a[i][3], addr);
        }
#pragma unroll
        for (int i = 0; i < 2; i++) {
            mma16816(ac2[i][0], a[i][0], a[i][1], a[i][2], a[i][3], bhv[0], bhv[1]);
            mma16816(ac2[i][1], a[i][0], a[i][1], a[i][2], a[i][3], bhv[2], bhv[3]);
        }
    }

    // ---- atomic partial reduction into g_st ----
    {
        const int base = (b*8 + h) * 64;
        const int r = lane >> 2;
        const int cq = (lane & 3) * 2;
#pragma unroll
        for (int i = 0; i < 2; i++) {
            int g0r = wm2 * 32 + i * 16 + r;
#pragma unroll
            for (int jj = 0; jj < 2; jj++) {
                int d = wn2 * 16 + jj * 8 + cq;
                atomicAdd(&g_st[(base + g0r)*64 + d],     ac2[i][jj][0]);
                atomicAdd(&g_st[(base + g0r)*64 + d + 1], ac2[i][jj][1]);
                atomicAdd(&g_st[(base + g0r + 8)*64 + d],     ac2[i][jj][2]);
                atomicAdd(&g_st[(base + g0r + 8)*64 + d + 1], ac2[i][jj][3]);
            }
        }
    }
}

// ---------------- K_C1: tiny attention over slice tokens (256 thr) ----------------
#define SMEM_ATTN (5*64*65*4)
__global__ void __launch_bounds__(256) k_attn(
    const float* __restrict__ Wq, const float* __restrict__ Wk,
    const float* __restrict__ Wv)
{
    float* sm = (float*)smem_dyn;
    float* S  = sm;
    float* Qs = sm + 64*65;
    float* Ks = sm + 2*64*65;
    float* Vs = sm + 3*64*65;
    float* Ps = sm + 4*64*65;

    const int h = blockIdx.x, b = blockIdx.y;
    const int tid = threadIdx.x;
    const int base = (b*8 + h) * 64;
    const int g  = tid >> 2;
    const int qd = (tid & 3) * 16;

    {
        float invn = 1.0f / (g_nrm[base + g] + 1e-5f);
#pragma unroll
        for (int j = 0; j < 16; j += 4) {
            float4 v = *(const float4*)&g_st[(base + g)*64 + qd + j];
            S[g*65 + qd + j]   = v.x * invn;
            S[g*65 + qd + j+1] = v.y * invn;
            S[g*65 + qd + j+2] = v.z * invn;
            S[g*65 + qd + j+3] = v.w * invn;
        }
    }
    __syncthreads();

    {
        float aq[16], ak[16], av[16];
#pragma unroll
        for (int j = 0; j < 16; j++) { aq[j] = 0.f; ak[j] = 0.f; av[j] = 0.f; }
        for (int k = 0; k < 64; k++) {
            float sv = S[g*65 + k];
            const float* wq = &Wq[k*64 + qd];
            const float* wk = &Wk[k*64 + qd];
            const float* wv = &Wv[k*64 + qd];
#pragma unroll
            for (int j = 0; j < 16; j++) {
                aq[j] += sv * wq[j];
                ak[j] += sv * wk[j];
                av[j] += sv * wv[j];
            }
        }
#pragma unroll
        for (int j = 0; j < 16; j++) {
            Qs[g*65 + qd + j] = aq[j];
            Ks[g*65 + qd + j] = ak[j];
            Vs[g*65 + qd + j] = av[j];
        }
    }
    __syncthreads();

    {
        float lg[16];
#pragma unroll
        for (int jj = 0; jj < 16; jj++) {
            int j = qd + jj;
            float dot = 0.f;
#pragma unroll
            for (int d = 0; d < 64; d++) dot += Qs[g*65 + d] * Ks[j*65 + d];
            lg[jj] = dot * 0.125f;
        }
        float mx = -1e30f;
#pragma unroll
        for (int jj = 0; jj < 16; jj++) mx = fmaxf(mx, lg[jj]);
        mx = fmaxf(mx, __shfl_xor_sync(0xffffffff, mx, 1));
        mx = fmaxf(mx, __shfl_xor_sync(0xffffffff, mx, 2));
        float s = 0.f;
#pragma unroll
        for (int jj = 0; jj < 16; jj++) { lg[jj] = __expf(lg[jj] - mx); s += lg[jj]; }
        s += __shfl_xor_sync(0xffffffff, s, 1);
        s += __shfl_xor_sync(0xffffffff, s, 2);
        float inv = 1.0f / s;
#pragma unroll
        for (int jj = 0; jj < 16; jj++) Ps[g*65 + qd + jj] = lg[jj] * inv;
    }
    __syncthreads();

    {
        float o[16];
#pragma unroll
        for (int d = 0; d < 16; d++) o[d] = 0.f;
        for (int j = 0; j < 64; j++) {
            float p = Ps[g*65 + j];
#pragma unroll
            for (int d = 0; d < 16; d++) o[d] += p * Vs[j*65 + qd + d];
        }
#pragma unroll
        for (int d = 0; d < 16; d++)
            g_os[(base + g)*64 + qd + d] = o[d];
    }
}

// ---------------- K_C2: P_t[b][c][h*64+g] split bf16 ----------------
#define SMEM_P ((64*68 + 64*256) * (int)sizeof(float))
__global__ void __launch_bounds__(256) k_P(const float* __restrict__ Wout)
{
    float* sm = (float*)smem_dyn;
    float* Os  = sm;
    float* Wsm = sm + 64*68;

    const int h = blockIdx.x, b = blockIdx.y;
    const int tid = threadIdx.x;
    const int base = (b*8 + h) * 64;

    for (int i = tid; i < 64*16; i += 256) {
        int r = i >> 4, c = i & 15;
        *(float4*)&Os[r*68 + c*4] = *(const float4*)&g_os[(size_t)(base + r)*64 + c*4];
    }
    for (int i = tid; i < 64*64; i += 256) {
        int r = i >> 6, c = i & 63;
        *(float4*)&Wsm[r*256 + c*4] = *(const float4*)&Wout[(size_t)(h*64 + r)*256 + c*4];
    }
    __syncthreads();

    const int gq = tid >> 3;
    const int cq = tid & 7;
    const int g0 = gq * 2;
    const int c0 = cq * 32;

    float acc[2][32];
#pragma unroll
    for (int i = 0; i < 2; i++)
#pragma unroll
        for (int j = 0; j < 32; j++) acc[i][j] = 0.f;

    for (int k = 0; k < 64; k++) {
        float a0 = Os[(g0+0)*68 + k];
        float a1 = Os[(g0+1)*68 + k];
#pragma unroll
        for (int c4 = 0; c4 < 8; c4++) {
            float4 w = *(float4*)&Wsm[k*256 + c0 + c4*4];
            acc[0][c4*4+0] += a0*w.x; acc[0][c4*4+1] += a0*w.y;
            acc[0][c4*4+2] += a0*w.z; acc[0][c4*4+3] += a0*w.w;
            acc[1][c4*4+0] += a1*w.x; acc[1][c4*4+1] += a1*w.y;
            acc[1][c4*4+2] += a1*w.z; acc[1][c4*4+3] += a1*w.w;
        }
    }
    __nv_bfloat16* Ph = &g_Pthi[(size_t)b * C_ * INNER_];
    __nv_bfloat16* Pl = &g_Ptlo[(size_t)b * C_ * INNER_];
#pragma unroll
    for (int i = 0; i < 2; i++)
#pragma unroll
        for (int c4 = 0; c4 < 8; c4++)
#pragma unroll
            for (int e = 0; e < 4; e++) {
                size_t off = (size_t)(c0 + c4*4 + e) * INNER_ + h*64 + g0 + i;
                __nv_bfloat16 hi, lo;
                split_one(acc[i][c4*4+e], hi, lo);
                Ph[off] = hi;
                Pl[off] = lo;
            }
}

// ---------------- launch ----------------
extern "C" void kernel_launch(void* const* d_in, const int* in_sizes, int n_in,
                              void* d_out, int out_size)
{
    const float* x    = (const float*)d_in[0];
    const float* Wfx  = (const float*)d_in[1];
    const float* bfx  = (const float*)d_in[2];
    const float* Wx   = (const float*)d_in[3];
    const float* bx   = (const float*)d_in[4];
    const float* Wsl  = (const float*)d_in[5];
    const float* bsl  = (const float*)d_in[6];
    const float* temp = (const float*)d_in[7];
    const float* Wq   = (const float*)d_in[8];
    const float* Wk   = (const float*)d_in[9];
    const float* Wv   = (const float*)d_in[10];
    const float* Wout = (const float*)d_in[11];
    const float* bout = (const float*)d_in[12];
    float* out = (float*)d_out;

    static bool init = false;
    static float *g_bias0_p;
    static __nv_bfloat16 *g_xhi_p, *g_xlo_p, *g_Whi_p, *g_Wlo_p;
    static __nv_bfloat16 *g_whi_p, *g_wlo_p, *g_Pthi_p, *g_Ptlo_p;
    if (!init) {
        cudaGetSymbolAddress((void**)&g_bias0_p, g_bias0);
        cudaGetSymbolAddress((void**)&g_xhi_p,   g_xhi);
        cudaGetSymbolAddress((void**)&g_xlo_p,   g_xlo);
        cudaGetSymbolAddress((void**)&g_Whi_p,   g_Whi);
        cudaGetSymbolAddress((void**)&g_Wlo_p,   g_Wlo);
        cudaGetSymbolAddress((void**)&g_whi_p,   g_whi);
        cudaGetSymbolAddress((void**)&g_wlo_p,   g_wlo);
        cudaGetSymbolAddress((void**)&g_Pthi_p,  g_Pthi);
        cudaGetSymbolAddress((void**)&g_Ptlo_p,  g_Ptlo);
        cudaFuncSetAttribute(k_gemm_ts, cudaFuncAttributeMaxDynamicSharedMemorySize, GK_SMEM);
        cudaFuncSetAttribute(k_pool, cudaFuncAttributeMaxDynamicSharedMemorySize, SMEM_POOL);
        cudaFuncSetAttribute(k_attn, cudaFuncAttributeMaxDynamicSharedMemorySize, SMEM_ATTN);
        cudaFuncSetAttribute(k_P,    cudaFuncAttributeMaxDynamicSharedMemorySize, SMEM_P);
        init = true;
    }

    // 0) fused prep (zero + split W + comb) + x split
    k_split_x<<<(BNTOK * 256 / 4) / 256, 256>>>(x);
    k_prep<<<1152, 256>>>(Wfx, bfx, Wx, Wsl, bx, bsl);

    // 1) projections: fx only (tensor cores, 3-pass)
    k_gemm_ts<<<dim3(4, BNTOK/128), 256, GK_SMEM>>>(
        g_xhi_p, g_xlo_p, g_Whi_p, g_Wlo_p, 256, 0, g_bias0_p, nullptr, 0);

    // 2) fused logits/softmax/pooling (tensor cores; logits via W_comb)
    k_pool<<<dim3(H_, N_/TOK, B_), 256, SMEM_POOL>>>(temp);

    // 3) tiny attention over slice tokens
    k_attn<<<dim3(H_, B_), 256, SMEM_ATTN>>>(Wq, Wk, Wv);

    // 4) P precompute (transposed + split)
    k_P<<<dim3(H_, B_), 256, SMEM_P>>>(Wout);

    // 5) output GEMM (tensor cores, 3-pass)
    k_gemm_ts<<<dim3(2, BNTOK/128), 256, GK_SMEM>>>(
        g_whi_p, g_wlo_p, g_Pthi_p, g_Ptlo_p, 512, 1, bout, out, 256);
}

// round 12
// speedup vs baseline: 1.1718x; 1.0769x over previous
#include <cuda_runtime.h>
#include <cuda_bf16.h>
#include <cstdint>
#include <math.h>

#define B_      4
#define N_      32768
#define C_      256
#define H_      8
#define D_      64
#define G_      64
#define INNER_  512
#define BNTOK   (B_*N_)          // 131072

// single dynamic smem symbol shared by all kernels
extern __shared__ char smem_dyn[];

// ---------------- scratch (device globals; allocation-free) ----------------
__device__ __nv_bfloat16 g_xhi[(size_t)BNTOK * 256];
__device__ __nv_bfloat16 g_xlo[(size_t)BNTOK * 256];
__device__ __nv_bfloat16 g_Wc[H_ * 64 * 256];        // combined W_x@Ws, [h][g][c]
__device__ float g_bcomb[H_ * 64];
__device__ __nv_bfloat16 g_whi[(size_t)BNTOK * 512]; // slice weights hi
__device__ __nv_bfloat16 g_wlo[(size_t)BNTOK * 512];
__device__ __nv_bfloat16 g_Pthi[B_ * C_ * INNER_];
__device__ __nv_bfloat16 g_Ptlo[B_ * C_ * INNER_];
__device__ float g_px [B_*H_*G_*C_];                 // pooled x: [bh][g][c], 2MB
__device__ float g_st [B_*H_*G_*D_];
__device__ float g_nrm[B_*H_*G_];
__device__ float g_os [B_*H_*G_*D_];

// ---------------- helpers ----------------
__device__ __forceinline__ uint32_t smem_to_u32(const void* p) {
    uint32_t a;
    asm("{ .reg .u64 t; cvta.to.shared.u64 t, %1; cvt.u32.u64 %0, t; }" : "=r"(a) : "l"(p));
    return a;
}
__device__ __forceinline__ void ldsm4(uint32_t &r0, uint32_t &r1, uint32_t &r2, uint32_t &r3,
                                      uint32_t addr) {
    asm volatile("ldmatrix.sync.aligned.m8n8.x4.shared.b16 {%0,%1,%2,%3}, [%4];"
        : "=r"(r0), "=r"(r1), "=r"(r2), "=r"(r3) : "r"(addr));
}
__device__ __forceinline__ void ldsm4t(uint32_t &r0, uint32_t &r1, uint32_t &r2, uint32_t &r3,
                                       uint32_t addr) {
    asm volatile("ldmatrix.sync.aligned.m8n8.x4.trans.shared.b16 {%0,%1,%2,%3}, [%4];"
        : "=r"(r0), "=r"(r1), "=r"(r2), "=r"(r3) : "r"(addr));
}
__device__ __forceinline__ void mma16816(float* c,
                                         uint32_t a0, uint32_t a1, uint32_t a2, uint32_t a3,
                                         uint32_t b0, uint32_t b1) {
    asm volatile(
        "mma.sync.aligned.m16n8k16.row.col.f32.bf16.bf16.f32 "
        "{%0,%1,%2,%3}, {%4,%5,%6,%7}, {%8,%9}, {%0,%1,%2,%3};"
        : "+f"(c[0]), "+f"(c[1]), "+f"(c[2]), "+f"(c[3])
        : "r"(a0), "r"(a1), "r"(a2), "r"(a3), "r"(b0), "r"(b1));
}
__device__ __forceinline__ void split_one(float a, __nv_bfloat16 &hi, __nv_bfloat16 &lo) {
    hi = __float2bfloat16(a);
    lo = __float2bfloat16(a - __bfloat162float(hi));
}
__device__ __forceinline__ void split_pair(float a, float b, unsigned &hi, unsigned &lo) {
    __nv_bfloat16 ah, al, bh, bl;
    split_one(a, ah, al);
    split_one(b, bh, bl);
    hi = ((unsigned)__bfloat16_as_ushort(bh) << 16) | (unsigned)__bfloat16_as_ushort(ah);
    lo = ((unsigned)__bfloat16_as_ushort(bl) << 16) | (unsigned)__bfloat16_as_ushort(al);
}
#define CP_ASYNC16(dst, src) \
    asm volatile("cp.async.cg.shared.global [%0], [%1], 16;" :: "r"(dst), "l"(src))
#define CP_COMMIT()  asm volatile("cp.async.commit_group;")
#define CP_WAIT0()   asm volatile("cp.async.wait_group 0;")

// ---------------- K_sx: split x into bf16 hi/lo ----------------
__global__ void __launch_bounds__(256) k_split_x(const float* __restrict__ x) {
    size_t i = (size_t)blockIdx.x * 256 + threadIdx.x;
    float4 v = *(const float4*)(x + i * 4);
    unsigned h0, l0, h1, l1;
    split_pair(v.x, v.y, h0, l0);
    split_pair(v.z, v.w, h1, l1);
    *(uint2*)&g_xhi[i * 4] = make_uint2(h0, h1);
    *(uint2*)&g_xlo[i * 4] = make_uint2(l0, l1);
}

// ---------------- K_prep: fused zero(px, nrm) + comb ----------------
__global__ void __launch_bounds__(256) k_prep(
    const float* __restrict__ Wx, const float* __restrict__ Wsl,
    const float* __restrict__ bx, const float* __restrict__ bsl)
{
    __shared__ float sws[64*64];
    const int bid = blockIdx.x;
    const int tid = threadIdx.x;

    if (bid < 512) {
        ((float4*)g_px)[bid * 256 + tid] = make_float4(0.f, 0.f, 0.f, 0.f);
        return;
    }
    if (bid == 512) {
        ((float4*)g_nrm)[tid]       = make_float4(0.f, 0.f, 0.f, 0.f);
        ((float4*)g_nrm)[tid + 256] = make_float4(0.f, 0.f, 0.f, 0.f);
        return;
    }
    const int r  = bid - 513;
    const int h  = r & 7;
    const int cb = r >> 3;
    for (int i = tid; i < 4096; i += 256) sws[i] = Wsl[i];
    __syncthreads();
    const int g = tid & 63, cq = tid >> 6;
#pragma unroll
    for (int cc = 0; cc < 4; cc++) {
        int c = cb * 16 + cq * 4 + cc;
        float s = 0.f;
        const float* wxr = &Wx[(size_t)c * 512 + h * 64];
#pragma unroll 16
        for (int d = 0; d < 64; d++) s += wxr[d] * sws[d*64 + g];
        g_Wc[(h*64 + g)*256 + c] = __float2bfloat16(s);
    }
    if (cb == 0 && tid < 64) {
        float s = bsl[tid];
        for (int d = 0; d < 64; d++) s += bx[h*64 + d] * sws[d*64 + tid];
        g_bcomb[h*64 + tid] = s;
    }
}

// ================= split-bf16 tensor-core GEMM (output GEMM only) =================
#define GK_ROWB 80
#define GK_ARR  (128 * GK_ROWB)
#define GK_STG  (4 * GK_ARR)
#define GK_SMEM (2 * GK_STG)

__global__ void __launch_bounds__(256, 2) k_gemm_ts(
    const __nv_bfloat16* __restrict__ Ahi, const __nv_bfloat16* __restrict__ Alo,
    const __nv_bfloat16* __restrict__ Bhi, const __nv_bfloat16* __restrict__ Blo,
    int K,
    const float* __restrict__ bias,
    float* __restrict__ OutF, int ldc)
{
    char* sm = smem_dyn;
    const uint32_t sbase = smem_to_u32(sm);

    const int tid  = threadIdx.x;
    const int wid  = tid >> 5;
    const int lane = tid & 31;
    const int wm   = wid >> 2;
    const int wn   = wid & 3;
    const int m0   = blockIdx.y * 128;
    const int n0   = blockIdx.x * 128;

    const __nv_bfloat16* srcs[4];
    srcs[0] = Ahi + (size_t)m0 * K;
    srcs[1] = Alo + (size_t)m0 * K;
    size_t boff = (size_t)(m0 >> 15) * 256 * INNER_ + (size_t)n0 * K;
    srcs[2] = Bhi + boff;
    srcs[3] = Blo + boff;

    const int srow0 = tid >> 2,         sq0 = tid & 3;
    const int srow1 = (tid + 256) >> 2, sq1 = (tid + 256) & 3;

    float acc[4][4][4];
#pragma unroll
    for (int i = 0; i < 4; i++)
#pragma unroll
        for (int j = 0; j < 4; j++)
#pragma unroll
            for (int e = 0; e < 4; e++) acc[i][j][e] = 0.f;

    const int lrow = lane & 15;
    const int lkq  = (lane >> 4) << 3;
    const int nch  = K >> 5;

#pragma unroll
    for (int arr = 0; arr < 4; arr++) {
        const __nv_bfloat16* s = srcs[arr];
        uint32_t d = sbase + arr * GK_ARR;
        CP_ASYNC16(d + srow0 * GK_ROWB + sq0 * 16, s + (size_t)srow0 * K + sq0 * 8);
        CP_ASYNC16(d + srow1 * GK_ROWB + sq1 * 16, s + (size_t)srow1 * K + sq1 * 8);
    }
    CP_COMMIT();

    for (int ch = 0; ch < nch; ch++) {
        CP_WAIT0();
        __syncthreads();
        if (ch + 1 < nch) {
            const int k1 = (ch + 1) << 5;
            const uint32_t stg = sbase + ((ch + 1) & 1) * GK_STG;
#pragma unroll
            for (int arr = 0; arr < 4; arr++) {
                const __nv_bfloat16* s = srcs[arr] + k1;
                uint32_t d = stg + arr * GK_ARR;
                CP_ASYNC16(d + srow0 * GK_ROWB + sq0 * 16, s + (size_t)srow0 * K + sq0 * 8);
                CP_ASYNC16(d + srow1 * GK_ROWB + sq1 * 16, s + (size_t)srow1 * K + sq1 * 8);
            }
            CP_COMMIT();
        }

        const uint32_t stg  = sbase + (ch & 1) * GK_STG;
        const uint32_t sahi = stg, salo = stg + GK_ARR;
        const uint32_t sbhi = stg + 2 * GK_ARR, sblo = stg + 3 * GK_ARR;

#pragma unroll
        for (int ks = 0; ks < 2; ks++) {
            const int khb = (ks * 16 + lkq) * 2;
            uint32_t a[4][4], bh[8], bl[8];
#pragma unroll
            for (int i = 0; i < 4; i++) {
                int row = wm * 64 + i * 16 + lrow;
                ldsm4(a[i][0], a[i][1], a[i][2], a[i][3], sahi + row * GK_ROWB + khb);
            }
#pragma unroll
            for (int jp = 0; jp < 2; jp++) {
                int row = wn * 32 + jp * 16 + lrow;
                ldsm4(bh[jp*4+0], bh[jp*4+1], bh[jp*4+2], bh[jp*4+3],
                      sbhi + row * GK_ROWB + khb);
            }
#pragma unroll
            for (int i = 0; i < 4; i++) {
                mma16816(acc[i][0], a[i][0], a[i][1], a[i][2], a[i][3], bh[0], bh[2]);
                mma16816(acc[i][1], a[i][0], a[i][1], a[i][2], a[i][3], bh[1], bh[3]);
                mma16816(acc[i][2], a[i][0], a[i][1], a[i][2], a[i][3], bh[4], bh[6]);
                mma16816(acc[i][3], a[i][0], a[i][1], a[i][2], a[i][3], bh[5], bh[7]);
            }
#pragma unroll
            for (int jp = 0; jp < 2; jp++) {
                int row = wn * 32 + jp * 16 + lrow;
                ldsm4(bl[jp*4+0], bl[jp*4+1], bl[jp*4+2], bl[jp*4+3],
                      sblo + row * GK_ROWB + khb);
            }
#pragma unroll
            for (int i = 0; i < 4; i++) {
                mma16816(acc[i][0], a[i][0], a[i][1], a[i][2], a[i][3], bl[0], bl[2]);
                mma16816(acc[i][1], a[i][0], a[i][1], a[i][2], a[i][3], bl[1], bl[3]);
                mma16816(acc[i][2], a[i][0], a[i][1], a[i][2], a[i][3], bl[4], bl[6]);
                mma16816(acc[i][3], a[i][0], a[i][1], a[i][2], a[i][3], bl[5], bl[7]);
            }
#pragma unroll
            for (int i = 0; i < 4; i++) {
                int row = wm * 64 + i * 16 + lrow;
                ldsm4(a[i][0], a[i][1], a[i][2], a[i][3], salo + row * GK_ROWB + khb);
            }
#pragma unroll
            for (int i = 0; i < 4; i++) {
                mma16816(acc[i][0], a[i][0], a[i][1], a[i][2], a[i][3], bh[0], bh[2]);
                mma16816(acc[i][1], a[i][0], a[i][1], a[i][2], a[i][3], bh[1], bh[3]);
                mma16816(acc[i][2], a[i][0], a[i][1], a[i][2], a[i][3], bh[4], bh[6]);
                mma16816(acc[i][3], a[i][0], a[i][1], a[i][2], a[i][3], bh[5], bh[7]);
            }
        }
    }

    const int r0 = lane >> 2;
    const int c0 = (lane & 3) * 2;
#pragma unroll
    for (int j = 0; j < 4; j++) {
        const int col = n0 + wn * 32 + j * 8 + c0;
        const float2 bi = *(const float2*)&bias[col];
#pragma unroll
        for (int i = 0; i < 4; i++) {
            const int row = m0 + wm * 64 + i * 16 + r0;
            float2 o0 = {acc[i][j][0] + bi.x, acc[i][j][1] + bi.y};
            float2 o1 = {acc[i][j][2] + bi.x, acc[i][j][3] + bi.y};
            *(float2*)&OutF[(size_t)row * ldc + col] = o0;
            *(float2*)&OutF[(size_t)(row + 8) * ldc + col] = o1;
        }
    }
}

// ================= K_B: fused logits+softmax+pool-x =================
#define TOK 256
#define PWTH  0
#define PWTL  36864
#define PWC   73728
#define S0H   73728
#define S0L   107520
#define S1H   141312
#define S1L   175104
#define PBSL  208896
#define PNRM  209152
#define SMEM_POOL 210432

__global__ void __launch_bounds__(256) k_pool(const float* __restrict__ temperature)
{
    char* sm = smem_dyn;
    const uint32_t sbase = smem_to_u32(sm);
    float* bslf = (float*)(sm + PBSL);
    float* nrmp = (float*)(sm + PNRM);

    const int h  = blockIdx.x;
    const int tb = blockIdx.y;
    const int b  = blockIdx.z;
    const int tid = threadIdx.x;
    const int wid = tid >> 5;
    const int lane = tid & 31;
    const int m0  = b * N_ + tb * TOK;
    const int lrow = lane & 15;
    const int lkq  = (lane >> 4) << 3;

    // prologue: Wc -> PWC, x chunk0 -> PWTH region
#pragma unroll
    for (int it = 0; it < 8; it++) {
        int i = tid + it * 256;
        int r = i >> 5, q = i & 31;
        CP_ASYNC16(sbase + PWC + r*528 + q*16, &g_Wc[(size_t)(h*64 + r)*256 + q*8]);
    }
#pragma unroll
    for (int it = 0; it < 8; it++) {
        int i = tid + it * 256;
        int r = i >> 3, q = i & 7;
        CP_ASYNC16(sbase + PWTH + r*144 + q*16, &g_xhi[(size_t)(m0+r)*256 + q*8]);
    }
    CP_COMMIT();
    if (tid < 64) bslf[tid] = g_bcomb[h*64 + tid];

    // ---- phase 1 MMA (1-pass), K=256 in 4 chunks ----
    float acc[2][8][4];
#pragma unroll
    for (int i = 0; i < 2; i++)
#pragma unroll
        for (int j = 0; j < 8; j++)
#pragma unroll
            for (int e = 0; e < 4; e++) acc[i][j][e] = 0.f;

#pragma unroll
    for (int kc = 0; kc < 4; kc++) {
        CP_WAIT0();
        __syncthreads();
        if (kc + 1 < 4) {
            const uint32_t dstb = sbase + (((kc + 1) & 1) ? PWTL : PWTH);
#pragma unroll
            for (int it = 0; it < 8; it++) {
                int i = tid + it * 256;
                int r = i >> 3, q = i & 7;
                CP_ASYNC16(dstb + r*144 + q*16,
                           &g_xhi[(size_t)(m0+r)*256 + (kc+1)*64 + q*8]);
            }
            CP_COMMIT();
        }
        const uint32_t abuf = sbase + ((kc & 1) ? PWTL : PWTH);
#pragma unroll
        for (int ks = 0; ks < 4; ks++) {
            const int khA = (ks * 16 + lkq) * 2;
            const int khB = (kc * 64 + ks * 16 + lkq) * 2;
            uint32_t a[2][4], bh[16];
#pragma unroll
            for (int i = 0; i < 2; i++) {
                int row = wid * 32 + i * 16 + lrow;
                ldsm4(a[i][0], a[i][1], a[i][2], a[i][3], abuf + row*144 + khA);
            }
#pragma unroll
            for (int jp = 0; jp < 4; jp++) {
                int row = jp * 16 + lrow;
                ldsm4(bh[jp*4+0], bh[jp*4+1], bh[jp*4+2], bh[jp*4+3],
                      sbase + PWC + row*528 + khB);
            }
#pragma unroll
            for (int i = 0; i < 2; i++)
#pragma unroll
                for (int jj = 0; jj < 8; jj++) {
                    int jp = jj >> 1, o = jj & 1;
                    mma16816(acc[i][jj], a[i][0], a[i][1], a[i][2], a[i][3],
                             bh[jp*4+o], bh[jp*4+o+2]);   // non-trans pairing
                }
        }
    }
    __syncthreads();   // PWTH/PWTL/PWC regions free now

    // kick x t-slice 0 staging into S0 (overlaps softmax + w writes)
#pragma unroll
    for (int it = 0; it < 8; it++) {
        int i = tid + it * 256;
        int r = i >> 5, q = i & 31;
        CP_ASYNC16(sbase + S0H + r*528 + q*16, &g_xhi[(size_t)(m0 + r)*256 + q*8]);
        CP_ASYNC16(sbase + S0L + r*528 + q*16, &g_xlo[(size_t)(m0 + r)*256 + q*8]);
    }
    CP_COMMIT();

    // ---- softmax over g ----
    float tmp = temperature[h];
    tmp = fminf(fmaxf(tmp, 0.1f), 5.0f);
    const float itemp = 1.0f / tmp;

#pragma unroll
    for (int i = 0; i < 2; i++)
#pragma unroll
        for (int j = 0; j < 8; j++) {
            float2 bi = *(float2*)&bslf[j*8 + (lane & 3)*2];
            acc[i][j][0] = (acc[i][j][0] + bi.x) * itemp;
            acc[i][j][1] = (acc[i][j][1] + bi.y) * itemp;
            acc[i][j][2] = (acc[i][j][2] + bi.x) * itemp;
            acc[i][j][3] = (acc[i][j][3] + bi.y) * itemp;
        }
    float inv0[2], inv1[2];
#pragma unroll
    for (int i = 0; i < 2; i++) {
        float m0v = -1e30f, m1v = -1e30f;
#pragma unroll
        for (int j = 0; j < 8; j++) {
            m0v = fmaxf(m0v, fmaxf(acc[i][j][0], acc[i][j][1]));
            m1v = fmaxf(m1v, fmaxf(acc[i][j][2], acc[i][j][3]));
        }
        m0v = fmaxf(m0v, __shfl_xor_sync(0xffffffff, m0v, 1));
        m0v = fmaxf(m0v, __shfl_xor_sync(0xffffffff, m0v, 2));
        m1v = fmaxf(m1v, __shfl_xor_sync(0xffffffff, m1v, 1));
        m1v = fmaxf(m1v, __shfl_xor_sync(0xffffffff, m1v, 2));
        float s0 = 0.f, s1 = 0.f;
#pragma unroll
        for (int j = 0; j < 8; j++) {
            acc[i][j][0] = __expf(acc[i][j][0] - m0v);
            acc[i][j][1] = __expf(acc[i][j][1] - m0v);
            acc[i][j][2] = __expf(acc[i][j][2] - m1v);
            acc[i][j][3] = __expf(acc[i][j][3] - m1v);
            s0 += acc[i][j][0] + acc[i][j][1];
            s1 += acc[i][j][2] + acc[i][j][3];
        }
        s0 += __shfl_xor_sync(0xffffffff, s0, 1);
        s0 += __shfl_xor_sync(0xffffffff, s0, 2);
        s1 += __shfl_xor_sync(0xffffffff, s1, 1);
        s1 += __shfl_xor_sync(0xffffffff, s1, 2);
        inv0[i] = 1.0f / s0;
        inv1[i] = 1.0f / s1;
    }

    // ---- write w: to [t][g] smem (packed 4B) and to g_w gmem (split) ----
    {
        const int r = lane >> 2;
#pragma unroll
        for (int i = 0; i < 2; i++) {
            int t0 = wid * 32 + i * 16 + r;
            int t1 = t0 + 8;
#pragma unroll
            for (int j = 0; j < 8; j++) {
                int c = j * 8 + (lane & 3) * 2;
                float w00 = acc[i][j][0] * inv0[i], w01 = acc[i][j][1] * inv0[i];
                float w10 = acc[i][j][2] * inv1[i], w11 = acc[i][j][3] * inv1[i];
                unsigned h0, l0, h1, l1;
                split_pair(w00, w01, h0, l0);
                split_pair(w10, w11, h1, l1);
                *(unsigned*)&g_whi[(size_t)(m0 + t0)*512 + h*64 + c] = h0;
                *(unsigned*)&g_wlo[(size_t)(m0 + t0)*512 + h*64 + c] = l0;
                *(unsigned*)&g_whi[(size_t)(m0 + t1)*512 + h*64 + c] = h1;
                *(unsigned*)&g_wlo[(size_t)(m0 + t1)*512 + h*64 + c] = l1;
                *(unsigned*)(sm + PWTH + t0*144 + c*2) = h0;
                *(unsigned*)(sm + PWTL + t0*144 + c*2) = l0;
                *(unsigned*)(sm + PWTH + t1*144 + c*2) = h1;
                *(unsigned*)(sm + PWTL + t1*144 + c*2) = l1;
            }
        }
    }
    __syncthreads();

    // ---- norm partial sums ----
    {
        int g = tid & 63, q = tid >> 6;
        float s = 0.f;
#pragma unroll 8
        for (int t = q*64; t < q*64 + 64; t++) {
            s += __bfloat162float(*(__nv_bfloat16*)(sm + PWTH + t*144 + g*2));
            s += __bfloat162float(*(__nv_bfloat16*)(sm + PWTL + t*144 + g*2));
        }
        nrmp[q*64 + g] = s;
    }
    __syncthreads();
    if (tid < 64) {
        float s = nrmp[tid] + nrmp[64+tid] + nrmp[128+tid] + nrmp[192+tid];
        atomicAdd(&g_nrm[(b*8 + h)*64 + tid], s);
    }

    // ---- phase 2: px[64g][256c] = w^T @ x over 4 t-slices (3-pass) ----
    const int wm2 = wid >> 2;
    const int wn2 = wid & 3;
    const int trowA = (lane & 7) | ((lane >> 1) & 8);
    const int gselA = (lane & 8) * 2;

    float ac2[2][8][4];
#pragma unroll
    for (int i = 0; i < 2; i++)
#pragma unroll
        for (int j = 0; j < 8; j++)
#pragma unroll
            for (int e = 0; e < 4; e++) ac2[i][j][e] = 0.f;

    for (int ts = 0; ts < 4; ts++) {
        CP_WAIT0();
        __syncthreads();
        if (ts + 1 < 4) {
            const uint32_t dh = sbase + (((ts + 1) & 1) ? S1H : S0H);
            const uint32_t dl = sbase + (((ts + 1) & 1) ? S1L : S0L);
            const int t1 = (ts + 1) * 64;
#pragma unroll
            for (int it = 0; it < 8; it++) {
                int i = tid + it * 256;
                int r = i >> 5, q = i & 31;
                CP_ASYNC16(dh + r*528 + q*16, &g_xhi[(size_t)(m0 + t1 + r)*256 + q*8]);
                CP_ASYNC16(dl + r*528 + q*16, &g_xlo[(size_t)(m0 + t1 + r)*256 + q*8]);
            }
            CP_COMMIT();
        }
        const uint32_t sh = sbase + ((ts & 1) ? S1H : S0H);
        const uint32_t sl = sbase + ((ts & 1) ? S1L : S0L);
        const int tbs = ts * 64;

#pragma unroll
        for (int ks = 0; ks < 4; ks++) {
            uint32_t a[2][4], bh[16], bl[16];
#pragma unroll
            for (int i = 0; i < 2; i++) {
                uint32_t addr = sbase + PWTH + (tbs + ks*16 + trowA)*144
                              + (wm2*32 + i*16)*2 + gselA;
                ldsm4t(a[i][0], a[i][1], a[i][2], a[i][3], addr);
            }
#pragma unroll
            for (int jp = 0; jp < 4; jp++) {
                uint32_t addr = sh + (ks*16 + lrow)*528 + (wn2*64 + jp*16 + lkq)*2;
                ldsm4t(bh[jp*4+0], bh[jp*4+1], bh[jp*4+2], bh[jp*4+3], addr);
            }
#pragma unroll
            for (int i = 0; i < 2; i++)
#pragma unroll
                for (int jj = 0; jj < 8; jj++) {
                    int jp = jj >> 1, o = jj & 1;
                    mma16816(ac2[i][jj], a[i][0], a[i][1], a[i][2], a[i][3],
                             bh[jp*4 + o*2], bh[jp*4 + o*2 + 1]);   // TRANS pairing
                }
#pragma unroll
            for (int jp = 0; jp < 4; jp++) {
                uint32_t addr = sl + (ks*16 + lrow)*528 + (wn2*64 + jp*16 + lkq)*2;
                ldsm4t(bl[jp*4+0], bl[jp*4+1], bl[jp*4+2], bl[jp*4+3], addr);
            }
#pragma unroll
            for (int i = 0; i < 2; i++)
#pragma unroll
                for (int jj = 0; jj < 8; jj++) {
                    int jp = jj >> 1, o = jj & 1;
                    mma16816(ac2[i][jj], a[i][0], a[i][1], a[i][2], a[i][3],
                             bl[jp*4 + o*2], bl[jp*4 + o*2 + 1]);   // TRANS pairing
                }
#pragma unroll
            for (int i = 0; i < 2; i++) {
                uint32_t addr = sbase + PWTL + (tbs + ks*16 + trowA)*144
                              + (wm2*32 + i*16)*2 + gselA;
                ldsm4t(a[i][0], a[i][1], a[i][2], a[i][3], addr);
            }
#pragma unroll
            for (int i = 0; i < 2; i++)
#pragma unroll
                for (int jj = 0; jj < 8; jj++) {
                    int jp = jj >> 1, o = jj & 1;
                    mma16816(ac2[i][jj], a[i][0], a[i][1], a[i][2], a[i][3],
                             bh[jp*4 + o*2], bh[jp*4 + o*2 + 1]);   // TRANS pairing
                }
        }
    }

    // ---- atomic accumulation into g_px ----
    {
        const int base = (b*8 + h) * 64;
        const int r = lane >> 2;
        const int c2 = (lane & 3) * 2;
#pragma unroll
        for (int i = 0; i < 2; i++) {
            int g0r = wm2 * 32 + i * 16 + r;
#pragma unroll
            for (int j = 0; j < 8; j++) {
                int col = wn2 * 64 + j * 8 + c2;
                float* p0 = &g_px[(size_t)(base + g0r)*256 + col];
                float* p1 = &g_px[(size_t)(base + g0r + 8)*256 + col];
                atomicAdd(p0,     ac2[i][j][0]);
                atomicAdd(p0 + 1, ac2[i][j][1]);
                atomicAdd(p1,     ac2[i][j][2]);
                atomicAdd(p1 + 1, ac2[i][j][3]);
            }
        }
    }
}

// ---------------- K_st: st = px @ W_fx + nrm * b_fx ----------------
#define SMEM_ST (64*260*4 + 256*68*4)
__global__ void __launch_bounds__(256) k_st(
    const float* __restrict__ Wfx, const float* __restrict__ bfx)
{
    float* spx = (float*)smem_dyn;              // [64][260]
    float* sw  = (float*)smem_dyn + 64*260;     // [256][68]
    const int h = blockIdx.x, b = blockIdx.y;
    const int tid = threadIdx.x;
    const int bh = b*8 + h;

#pragma unroll
    for (int it = 0; it < 16; it++) {
        int i = tid + it * 256;
        int r = i >> 6, c4 = i & 63;
        *(float4*)&spx[r*260 + c4*4] = *(const float4*)&g_px[(size_t)(bh*64 + r)*256 + c4*4];
    }
#pragma unroll
    for (int it = 0; it < 16; it++) {
        int i = tid + it * 256;
        int r = i >> 4, cq = i & 15;
        *(float4*)&sw[r*68 + cq*4] = *(const float4*)&Wfx[(size_t)r*512 + h*64 + cq*4];
    }
    __syncthreads();

    const int g  = tid >> 2;
    const int dq = (tid & 3) * 16;
    const float nv = g_nrm[bh*64 + g];
    float a16[16];
#pragma unroll
    for (int j = 0; j < 16; j++) a16[j] = nv * bfx[h*64 + dq + j];

    for (int c = 0; c < 256; c++) {
        float av = spx[g*260 + c];
#pragma unroll
        for (int c4 = 0; c4 < 4; c4++) {
            float4 w = *(float4*)&sw[c*68 + dq + c4*4];
            a16[c4*4+0] += av * w.x;
            a16[c4*4+1] += av * w.y;
            a16[c4*4+2] += av * w.z;
            a16[c4*4+3] += av * w.w;
        }
    }
#pragma unroll
    for (int j = 0; j < 16; j += 4)
        *(float4*)&g_st[(size_t)(bh*64 + g)*64 + dq + j] =
            make_float4(a16[j], a16[j+1], a16[j+2], a16[j+3]);
}

// ---------------- K_C1: tiny attention over slice tokens (256 thr) ----------------
#define SMEM_ATTN (5*64*65*4)
__global__ void __launch_bounds__(256) k_attn(
    const float* __restrict__ Wq, const float* __restrict__ Wk,
    const float* __restrict__ Wv)
{
    float* sm = (float*)smem_dyn;
    float* S  = sm;
    float* Qs = sm + 64*65;
    float* Ks = sm + 2*64*65;
    float* Vs = sm + 3*64*65;
    float* Ps = sm + 4*64*65;

    const int h = blockIdx.x, b = blockIdx.y;
    const int tid = threadIdx.x;
    const int base = (b*8 + h) * 64;
    const int g  = tid >> 2;
    const int qd = (tid & 3) * 16;

    {
        float invn = 1.0f / (g_nrm[base + g] + 1e-5f);
#pragma unroll
        for (int j = 0; j < 16; j += 4) {
            float4 v = *(const float4*)&g_st[(base + g)*64 + qd + j];
            S[g*65 + qd + j]   = v.x * invn;
            S[g*65 + qd + j+1] = v.y * invn;
            S[g*65 + qd + j+2] = v.z * invn;
            S[g*65 + qd + j+3] = v.w * invn;
        }
    }
    __syncthreads();

    {
        float aq[16], ak[16], av[16];
#pragma unroll
        for (int j = 0; j < 16; j++) { aq[j] = 0.f; ak[j] = 0.f; av[j] = 0.f; }
        for (int k = 0; k < 64; k++) {
            float sv = S[g*65 + k];
            const float* wq = &Wq[k*64 + qd];
            const float* wk = &Wk[k*64 + qd];
            const float* wv = &Wv[k*64 + qd];
#pragma unroll
            for (int j = 0; j < 16; j++) {
                aq[j] += sv * wq[j];
                ak[j] += sv * wk[j];
                av[j] += sv * wv[j];
            }
        }
#pragma unroll
        for (int j = 0; j < 16; j++) {
            Qs[g*65 + qd + j] = aq[j];
            Ks[g*65 + qd + j] = ak[j];
            Vs[g*65 + qd + j] = av[j];
        }
    }
    __syncthreads();

    {
        float lg[16];
#pragma unroll
        for (int jj = 0; jj < 16; jj++) {
            int j = qd + jj;
            float dot = 0.f;
#pragma unroll
            for (int d = 0; d < 64; d++) dot += Qs[g*65 + d] * Ks[j*65 + d];
            lg[jj] = dot * 0.125f;
        }
        float mx = -1e30f;
#pragma unroll
        for (int jj = 0; jj < 16; jj++) mx = fmaxf(mx, lg[jj]);
        mx = fmaxf(mx, __shfl_xor_sync(0xffffffff, mx, 1));
        mx = fmaxf(mx, __shfl_xor_sync(0xffffffff, mx, 2));
        float s = 0.f;
#pragma unroll
        for (int jj = 0; jj < 16; jj++) { lg[jj] = __expf(lg[jj] - mx); s += lg[jj]; }
        s += __shfl_xor_sync(0xffffffff, s, 1);
        s += __shfl_xor_sync(0xffffffff, s, 2);
        float inv = 1.0f / s;
#pragma unroll
        for (int jj = 0; jj < 16; jj++) Ps[g*65 + qd + jj] = lg[jj] * inv;
    }
    __syncthreads();

    {
        float o[16];
#pragma unroll
        for (int d = 0; d < 16; d++) o[d] = 0.f;
        for (int j = 0; j < 64; j++) {
            float p = Ps[g*65 + j];
#pragma unroll
            for (int d = 0; d < 16; d++) o[d] += p * Vs[j*65 + qd + d];
        }
#pragma unroll
        for (int d = 0; d < 16; d++)
            g_os[(base + g)*64 + qd + d] = o[d];
    }
}

// ---------------- K_C2: P_t[b][c][h*64+g] split bf16 ----------------
#define SMEM_P ((64*68 + 64*256) * (int)sizeof(float))
__global__ void __launch_bounds__(256) k_P(const float* __restrict__ Wout)
{
    float* sm = (float*)smem_dyn;
    float* Os  = sm;
    float* Wsm = sm + 64*68;

    const int h = blockIdx.x, b = blockIdx.y;
    const int tid = threadIdx.x;
    const int base = (b*8 + h) * 64;

    for (int i = tid; i < 64*16; i += 256) {
        int r = i >> 4, c = i & 15;
        *(float4*)&Os[r*68 + c*4] = *(const float4*)&g_os[(size_t)(base + r)*64 + c*4];
    }
    for (int i = tid; i < 64*64; i += 256) {
        int r = i >> 6, c = i & 63;
        *(float4*)&Wsm[r*256 + c*4] = *(const float4*)&Wout[(size_t)(h*64 + r)*256 + c*4];
    }
    __syncthreads();

    const int gq = tid >> 3;
    const int cq = tid & 7;
    const int g0 = gq * 2;
    const int c0 = cq * 32;

    float acc[2][32];
#pragma unroll
    for (int i = 0; i < 2; i++)
#pragma unroll
        for (int j = 0; j < 32; j++) acc[i][j] = 0.f;

    for (int k = 0; k < 64; k++) {
        float a0 = Os[(g0+0)*68 + k];
        float a1 = Os[(g0+1)*68 + k];
#pragma unroll
        for (int c4 = 0; c4 < 8; c4++) {
            float4 w = *(float4*)&Wsm[k*256 + c0 + c4*4];
            acc[0][c4*4+0] += a0*w.x; acc[0][c4*4+1] += a0*w.y;
            acc[0][c4*4+2] += a0*w.z; acc[0][c4*4+3] += a0*w.w;
            acc[1][c4*4+0] += a1*w.x; acc[1][c4*4+1] += a1*w.y;
            acc[1][c4*4+2] += a1*w.z; acc[1][c4*4+3] += a1*w.w;
        }
    }
    __nv_bfloat16* Ph = &g_Pthi[(size_t)b * C_ * INNER_];
    __nv_bfloat16* Pl = &g_Ptlo[(size_t)b * C_ * INNER_];
#pragma unroll
    for (int i = 0; i < 2; i++)
#pragma unroll
        for (int c4 = 0; c4 < 8; c4++)
#pragma unroll
            for (int e = 0; e < 4; e++) {
                size_t off = (size_t)(c0 + c4*4 + e) * INNER_ + h*64 + g0 + i;
                __nv_bfloat16 hi, lo;
                split_one(acc[i][c4*4+e], hi, lo);
                Ph[off] = hi;
                Pl[off] = lo;
            }
}

// ---------------- launch ----------------
extern "C" void kernel_launch(void* const* d_in, const int* in_sizes, int n_in,
                              void* d_out, int out_size)
{
    const float* x    = (const float*)d_in[0];
    const float* Wfx  = (const float*)d_in[1];
    const float* bfx  = (const float*)d_in[2];
    const float* Wx   = (const float*)d_in[3];
    const float* bx   = (const float*)d_in[4];
    const float* Wsl  = (const float*)d_in[5];
    const float* bsl  = (const float*)d_in[6];
    const float* temp = (const float*)d_in[7];
    const float* Wq   = (const float*)d_in[8];
    const float* Wk   = (const float*)d_in[9];
    const float* Wv   = (const float*)d_in[10];
    const float* Wout = (const float*)d_in[11];
    const float* bout = (const float*)d_in[12];
    float* out = (float*)d_out;

    static bool init = false;
    static __nv_bfloat16 *g_whi_p, *g_wlo_p, *g_Pthi_p, *g_Ptlo_p;
    if (!init) {
        cudaGetSymbolAddress((void**)&g_whi_p,   g_whi);
        cudaGetSymbolAddress((void**)&g_wlo_p,   g_wlo);
        cudaGetSymbolAddress((void**)&g_Pthi_p,  g_Pthi);
        cudaGetSymbolAddress((void**)&g_Ptlo_p,  g_Ptlo);
        cudaFuncSetAttribute(k_gemm_ts, cudaFuncAttributeMaxDynamicSharedMemorySize, GK_SMEM);
        cudaFuncSetAttribute(k_pool, cudaFuncAttributeMaxDynamicSharedMemorySize, SMEM_POOL);
        cudaFuncSetAttribute(k_st,   cudaFuncAttributeMaxDynamicSharedMemorySize, SMEM_ST);
        cudaFuncSetAttribute(k_attn, cudaFuncAttributeMaxDynamicSharedMemorySize, SMEM_ATTN);
        cudaFuncSetAttribute(k_P,    cudaFuncAttributeMaxDynamicSharedMemorySize, SMEM_P);
        init = true;
    }

    // 0) x split + prep (zero px/nrm + W_comb)
    k_split_x<<<(BNTOK * 256 / 4) / 256, 256>>>(x);
    k_prep<<<641, 256>>>(Wx, Wsl, bx, bsl);

    // 1) fused logits/softmax/pool-x (tensor cores)
    k_pool<<<dim3(H_, N_/TOK, B_), 256, SMEM_POOL>>>(temp);

    // 2) st = px @ W_fx + nrm*b_fx
    k_st<<<dim3(H_, B_), 256, SMEM_ST>>>(Wfx, bfx);

    // 3) tiny attention over slice tokens
    k_attn<<<dim3(H_, B_), 256, SMEM_ATTN>>>(Wq, Wk, Wv);

    // 4) P precompute (transposed + split)
    k_P<<<dim3(H_, B_), 256, SMEM_P>>>(Wout);

    // 5) output GEMM (tensor cores, 3-pass)
    k_gemm_ts<<<dim3(2, BNTOK/128), 256, GK_SMEM>>>(
        g_whi_p, g_wlo_p, g_Pthi_p, g_Ptlo_p, 512, bout, out, 256);
}

// round 13
// speedup vs baseline: 1.2097x; 1.0323x over previous
#include <cuda_runtime.h>
#include <cuda_bf16.h>
#include <cstdint>
#include <math.h>

#define B_      4
#define N_      32768
#define C_      256
#define H_      8
#define D_      64
#define G_      64
#define INNER_  512
#define BNTOK   (B_*N_)          // 131072

// single dynamic smem symbol shared by all kernels
extern __shared__ char smem_dyn[];

// ---------------- scratch (device globals; allocation-free) ----------------
__device__ __nv_bfloat16 g_xhi[(size_t)BNTOK * 256];
__device__ __nv_bfloat16 g_xlo[(size_t)BNTOK * 256];
__device__ __nv_bfloat16 g_Wc[H_ * 64 * 256];        // combined W_x@Ws, [h][g][c]
__device__ float g_bcomb[H_ * 64];
__device__ __nv_bfloat16 g_whi[(size_t)BNTOK * 512]; // slice weights hi
__device__ __nv_bfloat16 g_wlo[(size_t)BNTOK * 512];
__device__ __nv_bfloat16 g_Pthi[B_ * C_ * INNER_];
__device__ __nv_bfloat16 g_Ptlo[B_ * C_ * INNER_];
__device__ float g_px [B_*H_*G_*C_];                 // pooled x: [bh][g][c], 2MB
__device__ float g_st [B_*H_*G_*D_];
__device__ float g_nrm[B_*H_*G_];
__device__ float g_os [B_*H_*G_*D_];

// ---------------- helpers ----------------
__device__ __forceinline__ uint32_t smem_to_u32(const void* p) {
    uint32_t a;
    asm("{ .reg .u64 t; cvta.to.shared.u64 t, %1; cvt.u32.u64 %0, t; }" : "=r"(a) : "l"(p));
    return a;
}
__device__ __forceinline__ void ldsm4(uint32_t &r0, uint32_t &r1, uint32_t &r2, uint32_t &r3,
                                      uint32_t addr) {
    asm volatile("ldmatrix.sync.aligned.m8n8.x4.shared.b16 {%0,%1,%2,%3}, [%4];"
        : "=r"(r0), "=r"(r1), "=r"(r2), "=r"(r3) : "r"(addr));
}
__device__ __forceinline__ void ldsm4t(uint32_t &r0, uint32_t &r1, uint32_t &r2, uint32_t &r3,
                                       uint32_t addr) {
    asm volatile("ldmatrix.sync.aligned.m8n8.x4.trans.shared.b16 {%0,%1,%2,%3}, [%4];"
        : "=r"(r0), "=r"(r1), "=r"(r2), "=r"(r3) : "r"(addr));
}
__device__ __forceinline__ void mma16816(float* c,
                                         uint32_t a0, uint32_t a1, uint32_t a2, uint32_t a3,
                                         uint32_t b0, uint32_t b1) {
    asm volatile(
        "mma.sync.aligned.m16n8k16.row.col.f32.bf16.bf16.f32 "
        "{%0,%1,%2,%3}, {%4,%5,%6,%7}, {%8,%9}, {%0,%1,%2,%3};"
        : "+f"(c[0]), "+f"(c[1]), "+f"(c[2]), "+f"(c[3])
        : "r"(a0), "r"(a1), "r"(a2), "r"(a3), "r"(b0), "r"(b1));
}
__device__ __forceinline__ void split_one(float a, __nv_bfloat16 &hi, __nv_bfloat16 &lo) {
    hi = __float2bfloat16(a);
    lo = __float2bfloat16(a - __bfloat162float(hi));
}
__device__ __forceinline__ void split_pair(float a, float b, unsigned &hi, unsigned &lo) {
    __nv_bfloat16 ah, al, bh, bl;
    split_one(a, ah, al);
    split_one(b, bh, bl);
    hi = ((unsigned)__bfloat16_as_ushort(bh) << 16) | (unsigned)__bfloat16_as_ushort(ah);
    lo = ((unsigned)__bfloat16_as_ushort(bl) << 16) | (unsigned)__bfloat16_as_ushort(al);
}
#define CP_ASYNC16(dst, src) \
    asm volatile("cp.async.cg.shared.global [%0], [%1], 16;" :: "r"(dst), "l"(src))
#define CP_COMMIT()  asm volatile("cp.async.commit_group;")
#define CP_WAIT0()   asm volatile("cp.async.wait_group 0;")

// ---------------- K_sx: split x into bf16 hi/lo ----------------
__global__ void __launch_bounds__(256) k_split_x(const float* __restrict__ x) {
    size_t i = (size_t)blockIdx.x * 256 + threadIdx.x;
    float4 v = *(const float4*)(x + i * 4);
    unsigned h0, l0, h1, l1;
    split_pair(v.x, v.y, h0, l0);
    split_pair(v.z, v.w, h1, l1);
    *(uint2*)&g_xhi[i * 4] = make_uint2(h0, h1);
    *(uint2*)&g_xlo[i * 4] = make_uint2(l0, l1);
}

// ---------------- K_prep: fused zero(px, nrm) + comb ----------------
__global__ void __launch_bounds__(256) k_prep(
    const float* __restrict__ Wx, const float* __restrict__ Wsl,
    const float* __restrict__ bx, const float* __restrict__ bsl)
{
    __shared__ float sws[64*64];
    const int bid = blockIdx.x;
    const int tid = threadIdx.x;

    if (bid < 512) {
        ((float4*)g_px)[bid * 256 + tid] = make_float4(0.f, 0.f, 0.f, 0.f);
        return;
    }
    if (bid == 512) {
        ((float4*)g_nrm)[tid]       = make_float4(0.f, 0.f, 0.f, 0.f);
        ((float4*)g_nrm)[tid + 256] = make_float4(0.f, 0.f, 0.f, 0.f);
        return;
    }
    const int r  = bid - 513;
    const int h  = r & 7;
    const int cb = r >> 3;
    for (int i = tid; i < 4096; i += 256) sws[i] = Wsl[i];
    __syncthreads();
    const int g = tid & 63, cq = tid >> 6;
#pragma unroll
    for (int cc = 0; cc < 4; cc++) {
        int c = cb * 16 + cq * 4 + cc;
        float s = 0.f;
        const float* wxr = &Wx[(size_t)c * 512 + h * 64];
#pragma unroll 16
        for (int d = 0; d < 64; d++) s += wxr[d] * sws[d*64 + g];
        g_Wc[(h*64 + g)*256 + c] = __float2bfloat16(s);
    }
    if (cb == 0 && tid < 64) {
        float s = bsl[tid];
        for (int d = 0; d < 64; d++) s += bx[h*64 + d] * sws[d*64 + tid];
        g_bcomb[h*64 + tid] = s;
    }
}

// ================= split-bf16 tensor-core GEMM (output GEMM only) =================
#define GK_ROWB 80
#define GK_ARR  (128 * GK_ROWB)
#define GK_STG  (4 * GK_ARR)
#define GK_SMEM (2 * GK_STG)

__global__ void __launch_bounds__(256, 2) k_gemm_ts(
    const __nv_bfloat16* __restrict__ Ahi, const __nv_bfloat16* __restrict__ Alo,
    const __nv_bfloat16* __restrict__ Bhi, const __nv_bfloat16* __restrict__ Blo,
    int K,
    const float* __restrict__ bias,
    float* __restrict__ OutF, int ldc)
{
    char* sm = smem_dyn;
    const uint32_t sbase = smem_to_u32(sm);

    const int tid  = threadIdx.x;
    const int wid  = tid >> 5;
    const int lane = tid & 31;
    const int wm   = wid >> 2;
    const int wn   = wid & 3;
    const int m0   = blockIdx.y * 128;
    const int n0   = blockIdx.x * 128;

    const __nv_bfloat16* srcs[4];
    srcs[0] = Ahi + (size_t)m0 * K;
    srcs[1] = Alo + (size_t)m0 * K;
    size_t boff = (size_t)(m0 >> 15) * 256 * INNER_ + (size_t)n0 * K;
    srcs[2] = Bhi + boff;
    srcs[3] = Blo + boff;

    const int srow0 = tid >> 2,         sq0 = tid & 3;
    const int srow1 = (tid + 256) >> 2, sq1 = (tid + 256) & 3;

    float acc[4][4][4];
#pragma unroll
    for (int i = 0; i < 4; i++)
#pragma unroll
        for (int j = 0; j < 4; j++)
#pragma unroll
            for (int e = 0; e < 4; e++) acc[i][j][e] = 0.f;

    const int lrow = lane & 15;
    const int lkq  = (lane >> 4) << 3;
    const int nch  = K >> 5;

#pragma unroll
    for (int arr = 0; arr < 4; arr++) {
        const __nv_bfloat16* s = srcs[arr];
        uint32_t d = sbase + arr * GK_ARR;
        CP_ASYNC16(d + srow0 * GK_ROWB + sq0 * 16, s + (size_t)srow0 * K + sq0 * 8);
        CP_ASYNC16(d + srow1 * GK_ROWB + sq1 * 16, s + (size_t)srow1 * K + sq1 * 8);
    }
    CP_COMMIT();

    for (int ch = 0; ch < nch; ch++) {
        CP_WAIT0();
        __syncthreads();
        if (ch + 1 < nch) {
            const int k1 = (ch + 1) << 5;
            const uint32_t stg = sbase + ((ch + 1) & 1) * GK_STG;
#pragma unroll
            for (int arr = 0; arr < 4; arr++) {
                const __nv_bfloat16* s = srcs[arr] + k1;
                uint32_t d = stg + arr * GK_ARR;
                CP_ASYNC16(d + srow0 * GK_ROWB + sq0 * 16, s + (size_t)srow0 * K + sq0 * 8);
                CP_ASYNC16(d + srow1 * GK_ROWB + sq1 * 16, s + (size_t)srow1 * K + sq1 * 8);
            }
            CP_COMMIT();
        }

        const uint32_t stg  = sbase + (ch & 1) * GK_STG;
        const uint32_t sahi = stg, salo = stg + GK_ARR;
        const uint32_t sbhi = stg + 2 * GK_ARR, sblo = stg + 3 * GK_ARR;

#pragma unroll
        for (int ks = 0; ks < 2; ks++) {
            const int khb = (ks * 16 + lkq) * 2;
            uint32_t a[4][4], bh[8], bl[8];
#pragma unroll
            for (int i = 0; i < 4; i++) {
                int row = wm * 64 + i * 16 + lrow;
                ldsm4(a[i][0], a[i][1], a[i][2], a[i][3], sahi + row * GK_ROWB + khb);
            }
#pragma unroll
            for (int jp = 0; jp < 2; jp++) {
                int row = wn * 32 + jp * 16 + lrow;
                ldsm4(bh[jp*4+0], bh[jp*4+1], bh[jp*4+2], bh[jp*4+3],
                      sbhi + row * GK_ROWB + khb);
            }
#pragma unroll
            for (int i = 0; i < 4; i++) {
                mma16816(acc[i][0], a[i][0], a[i][1], a[i][2], a[i][3], bh[0], bh[2]);
                mma16816(acc[i][1], a[i][0], a[i][1], a[i][2], a[i][3], bh[1], bh[3]);
                mma16816(acc[i][2], a[i][0], a[i][1], a[i][2], a[i][3], bh[4], bh[6]);
                mma16816(acc[i][3], a[i][0], a[i][1], a[i][2], a[i][3], bh[5], bh[7]);
            }
#pragma unroll
            for (int jp = 0; jp < 2; jp++) {
                int row = wn * 32 + jp * 16 + lrow;
                ldsm4(bl[jp*4+0], bl[jp*4+1], bl[jp*4+2], bl[jp*4+3],
                      sblo + row * GK_ROWB + khb);
            }
#pragma unroll
            for (int i = 0; i < 4; i++) {
                mma16816(acc[i][0], a[i][0], a[i][1], a[i][2], a[i][3], bl[0], bl[2]);
                mma16816(acc[i][1], a[i][0], a[i][1], a[i][2], a[i][3], bl[1], bl[3]);
                mma16816(acc[i][2], a[i][0], a[i][1], a[i][2], a[i][3], bl[4], bl[6]);
                mma16816(acc[i][3], a[i][0], a[i][1], a[i][2], a[i][3], bl[5], bl[7]);
            }
#pragma unroll
            for (int i = 0; i < 4; i++) {
                int row = wm * 64 + i * 16 + lrow;
                ldsm4(a[i][0], a[i][1], a[i][2], a[i][3], salo + row * GK_ROWB + khb);
            }
#pragma unroll
            for (int i = 0; i < 4; i++) {
                mma16816(acc[i][0], a[i][0], a[i][1], a[i][2], a[i][3], bh[0], bh[2]);
                mma16816(acc[i][1], a[i][0], a[i][1], a[i][2], a[i][3], bh[1], bh[3]);
                mma16816(acc[i][2], a[i][0], a[i][1], a[i][2], a[i][3], bh[4], bh[6]);
                mma16816(acc[i][3], a[i][0], a[i][1], a[i][2], a[i][3], bh[5], bh[7]);
            }
        }
    }

    const int r0 = lane >> 2;
    const int c0 = (lane & 3) * 2;
#pragma unroll
    for (int j = 0; j < 4; j++) {
        const int col = n0 + wn * 32 + j * 8 + c0;
        const float2 bi = *(const float2*)&bias[col];
#pragma unroll
        for (int i = 0; i < 4; i++) {
            const int row = m0 + wm * 64 + i * 16 + r0;
            float2 o0 = {acc[i][j][0] + bi.x, acc[i][j][1] + bi.y};
            float2 o1 = {acc[i][j][2] + bi.x, acc[i][j][3] + bi.y};
            *(float2*)&OutF[(size_t)row * ldc + col] = o0;
            *(float2*)&OutF[(size_t)(row + 8) * ldc + col] = o1;
        }
    }
}

// ================= K_B: fused logits+softmax+pool-x =================
#define TOK 256
#define PWTH  0
#define PWTL  36864
#define PWC   73728
#define S0H   73728
#define S0L   107520
#define S1H   141312
#define S1L   175104
#define PBSL  208896
#define PNRM  209152
#define SMEM_POOL 210432

__global__ void __launch_bounds__(256) k_pool(const float* __restrict__ temperature)
{
    char* sm = smem_dyn;
    const uint32_t sbase = smem_to_u32(sm);
    float* bslf = (float*)(sm + PBSL);
    float* nrmp = (float*)(sm + PNRM);

    const int h  = blockIdx.x;
    const int tb = blockIdx.y;
    const int b  = blockIdx.z;
    const int tid = threadIdx.x;
    const int wid = tid >> 5;
    const int lane = tid & 31;
    const int m0  = b * N_ + tb * TOK;
    const int lrow = lane & 15;
    const int lkq  = (lane >> 4) << 3;

    // prologue: Wc -> PWC, x chunk0 -> PWTH region
#pragma unroll
    for (int it = 0; it < 8; it++) {
        int i = tid + it * 256;
        int r = i >> 5, q = i & 31;
        CP_ASYNC16(sbase + PWC + r*528 + q*16, &g_Wc[(size_t)(h*64 + r)*256 + q*8]);
    }
#pragma unroll
    for (int it = 0; it < 8; it++) {
        int i = tid + it * 256;
        int r = i >> 3, q = i & 7;
        CP_ASYNC16(sbase + PWTH + r*144 + q*16, &g_xhi[(size_t)(m0+r)*256 + q*8]);
    }
    CP_COMMIT();
    if (tid < 64) bslf[tid] = g_bcomb[h*64 + tid];

    // ---- phase 1 MMA (1-pass), K=256 in 4 chunks ----
    float acc[2][8][4];
#pragma unroll
    for (int i = 0; i < 2; i++)
#pragma unroll
        for (int j = 0; j < 8; j++)
#pragma unroll
            for (int e = 0; e < 4; e++) acc[i][j][e] = 0.f;

#pragma unroll
    for (int kc = 0; kc < 4; kc++) {
        CP_WAIT0();
        __syncthreads();
        if (kc + 1 < 4) {
            const uint32_t dstb = sbase + (((kc + 1) & 1) ? PWTL : PWTH);
#pragma unroll
            for (int it = 0; it < 8; it++) {
                int i = tid + it * 256;
                int r = i >> 3, q = i & 7;
                CP_ASYNC16(dstb + r*144 + q*16,
                           &g_xhi[(size_t)(m0+r)*256 + (kc+1)*64 + q*8]);
            }
            CP_COMMIT();
        }
        const uint32_t abuf = sbase + ((kc & 1) ? PWTL : PWTH);
#pragma unroll
        for (int ks = 0; ks < 4; ks++) {
            const int khA = (ks * 16 + lkq) * 2;
            const int khB = (kc * 64 + ks * 16 + lkq) * 2;
            uint32_t a[2][4], bh[16];
#pragma unroll
            for (int i = 0; i < 2; i++) {
                int row = wid * 32 + i * 16 + lrow;
                ldsm4(a[i][0], a[i][1], a[i][2], a[i][3], abuf + row*144 + khA);
            }
#pragma unroll
            for (int jp = 0; jp < 4; jp++) {
                int row = jp * 16 + lrow;
                ldsm4(bh[jp*4+0], bh[jp*4+1], bh[jp*4+2], bh[jp*4+3],
                      sbase + PWC + row*528 + khB);
            }
#pragma unroll
            for (int i = 0; i < 2; i++)
#pragma unroll
                for (int jj = 0; jj < 8; jj++) {
                    int jp = jj >> 1, o = jj & 1;
                    mma16816(acc[i][jj], a[i][0], a[i][1], a[i][2], a[i][3],
                             bh[jp*4+o], bh[jp*4+o+2]);   // non-trans pairing
                }
        }
    }
    __syncthreads();   // PWTH/PWTL/PWC regions free now

    // kick x t-slice 0 staging into S0 (overlaps softmax + w writes)
#pragma unroll
    for (int it = 0; it < 8; it++) {
        int i = tid + it * 256;
        int r = i >> 5, q = i & 31;
        CP_ASYNC16(sbase + S0H + r*528 + q*16, &g_xhi[(size_t)(m0 + r)*256 + q*8]);
        CP_ASYNC16(sbase + S0L + r*528 + q*16, &g_xlo[(size_t)(m0 + r)*256 + q*8]);
    }
    CP_COMMIT();

    // ---- softmax over g ----
    float tmp = temperature[h];
    tmp = fminf(fmaxf(tmp, 0.1f), 5.0f);
    const float itemp = 1.0f / tmp;

#pragma unroll
    for (int i = 0; i < 2; i++)
#pragma unroll
        for (int j = 0; j < 8; j++) {
            float2 bi = *(float2*)&bslf[j*8 + (lane & 3)*2];
            acc[i][j][0] = (acc[i][j][0] + bi.x) * itemp;
            acc[i][j][1] = (acc[i][j][1] + bi.y) * itemp;
            acc[i][j][2] = (acc[i][j][2] + bi.x) * itemp;
            acc[i][j][3] = (acc[i][j][3] + bi.y) * itemp;
        }
    float inv0[2], inv1[2];
#pragma unroll
    for (int i = 0; i < 2; i++) {
        float m0v = -1e30f, m1v = -1e30f;
#pragma unroll
        for (int j = 0; j < 8; j++) {
            m0v = fmaxf(m0v, fmaxf(acc[i][j][0], acc[i][j][1]));
            m1v = fmaxf(m1v, fmaxf(acc[i][j][2], acc[i][j][3]));
        }
        m0v = fmaxf(m0v, __shfl_xor_sync(0xffffffff, m0v, 1));
        m0v = fmaxf(m0v, __shfl_xor_sync(0xffffffff, m0v, 2));
        m1v = fmaxf(m1v, __shfl_xor_sync(0xffffffff, m1v, 1));
        m1v = fmaxf(m1v, __shfl_xor_sync(0xffffffff, m1v, 2));
        float s0 = 0.f, s1 = 0.f;
#pragma unroll
        for (int j = 0; j < 8; j++) {
            acc[i][j][0] = __expf(acc[i][j][0] - m0v);
            acc[i][j][1] = __expf(acc[i][j][1] - m0v);
            acc[i][j][2] = __expf(acc[i][j][2] - m1v);
            acc[i][j][3] = __expf(acc[i][j][3] - m1v);
            s0 += acc[i][j][0] + acc[i][j][1];
            s1 += acc[i][j][2] + acc[i][j][3];
        }
        s0 += __shfl_xor_sync(0xffffffff, s0, 1);
        s0 += __shfl_xor_sync(0xffffffff, s0, 2);
        s1 += __shfl_xor_sync(0xffffffff, s1, 1);
        s1 += __shfl_xor_sync(0xffffffff, s1, 2);
        inv0[i] = 1.0f / s0;
        inv1[i] = 1.0f / s1;
    }

    // ---- write w: to [t][g] smem (packed 4B) and to g_w gmem (split) ----
    {
        const int r = lane >> 2;
#pragma unroll
        for (int i = 0; i < 2; i++) {
            int t0 = wid * 32 + i * 16 + r;
            int t1 = t0 + 8;
#pragma unroll
            for (int j = 0; j < 8; j++) {
                int c = j * 8 + (lane & 3) * 2;
                float w00 = acc[i][j][0] * inv0[i], w01 = acc[i][j][1] * inv0[i];
                float w10 = acc[i][j][2] * inv1[i], w11 = acc[i][j][3] * inv1[i];
                unsigned h0, l0, h1, l1;
                split_pair(w00, w01, h0, l0);
                split_pair(w10, w11, h1, l1);
                *(unsigned*)&g_whi[(size_t)(m0 + t0)*512 + h*64 + c] = h0;
                *(unsigned*)&g_wlo[(size_t)(m0 + t0)*512 + h*64 + c] = l0;
                *(unsigned*)&g_whi[(size_t)(m0 + t1)*512 + h*64 + c] = h1;
                *(unsigned*)&g_wlo[(size_t)(m0 + t1)*512 + h*64 + c] = l1;
                *(unsigned*)(sm + PWTH + t0*144 + c*2) = h0;
                *(unsigned*)(sm + PWTL + t0*144 + c*2) = l0;
                *(unsigned*)(sm + PWTH + t1*144 + c*2) = h1;
                *(unsigned*)(sm + PWTL + t1*144 + c*2) = l1;
            }
        }
    }
    __syncthreads();

    // ---- norm partial sums ----
    {
        int g = tid & 63, q = tid >> 6;
        float s = 0.f;
#pragma unroll 8
        for (int t = q*64; t < q*64 + 64; t++) {
            s += __bfloat162float(*(__nv_bfloat16*)(sm + PWTH + t*144 + g*2));
            s += __bfloat162float(*(__nv_bfloat16*)(sm + PWTL + t*144 + g*2));
        }
        nrmp[q*64 + g] = s;
    }
    __syncthreads();
    if (tid < 64) {
        float s = nrmp[tid] + nrmp[64+tid] + nrmp[128+tid] + nrmp[192+tid];
        atomicAdd(&g_nrm[(b*8 + h)*64 + tid], s);
    }

    // ---- phase 2: px[64g][256c] = w^T @ x over 4 t-slices (3-pass) ----
    const int wm2 = wid >> 2;
    const int wn2 = wid & 3;
    const int trowA = (lane & 7) | ((lane >> 1) & 8);
    const int gselA = (lane & 8) * 2;

    float ac2[2][8][4];
#pragma unroll
    for (int i = 0; i < 2; i++)
#pragma unroll
        for (int j = 0; j < 8; j++)
#pragma unroll
            for (int e = 0; e < 4; e++) ac2[i][j][e] = 0.f;

    for (int ts = 0; ts < 4; ts++) {
        CP_WAIT0();
        __syncthreads();
        if (ts + 1 < 4) {
            const uint32_t dh = sbase + (((ts + 1) & 1) ? S1H : S0H);
            const uint32_t dl = sbase + (((ts + 1) & 1) ? S1L : S0L);
            const int t1 = (ts + 1) * 64;
#pragma unroll
            for (int it = 0; it < 8; it++) {
                int i = tid + it * 256;
                int r = i >> 5, q = i & 31;
                CP_ASYNC16(dh + r*528 + q*16, &g_xhi[(size_t)(m0 + t1 + r)*256 + q*8]);
                CP_ASYNC16(dl + r*528 + q*16, &g_xlo[(size_t)(m0 + t1 + r)*256 + q*8]);
            }
            CP_COMMIT();
        }
        const uint32_t sh = sbase + ((ts & 1) ? S1H : S0H);
        const uint32_t sl = sbase + ((ts & 1) ? S1L : S0L);
        const int tbs = ts * 64;

#pragma unroll
        for (int ks = 0; ks < 4; ks++) {
            uint32_t a[2][4], bh[16], bl[16];
#pragma unroll
            for (int i = 0; i < 2; i++) {
                uint32_t addr = sbase + PWTH + (tbs + ks*16 + trowA)*144
                              + (wm2*32 + i*16)*2 + gselA;
                ldsm4t(a[i][0], a[i][1], a[i][2], a[i][3], addr);
            }
#pragma unroll
            for (int jp = 0; jp < 4; jp++) {
                uint32_t addr = sh + (ks*16 + lrow)*528 + (wn2*64 + jp*16 + lkq)*2;
                ldsm4t(bh[jp*4+0], bh[jp*4+1], bh[jp*4+2], bh[jp*4+3], addr);
            }
#pragma unroll
            for (int i = 0; i < 2; i++)
#pragma unroll
                for (int jj = 0; jj < 8; jj++) {
                    int jp = jj >> 1, o = jj & 1;
                    mma16816(ac2[i][jj], a[i][0], a[i][1], a[i][2], a[i][3],
                             bh[jp*4 + o*2], bh[jp*4 + o*2 + 1]);   // TRANS pairing
                }
#pragma unroll
            for (int jp = 0; jp < 4; jp++) {
                uint32_t addr = sl + (ks*16 + lrow)*528 + (wn2*64 + jp*16 + lkq)*2;
                ldsm4t(bl[jp*4+0], bl[jp*4+1], bl[jp*4+2], bl[jp*4+3], addr);
            }
#pragma unroll
            for (int i = 0; i < 2; i++)
#pragma unroll
                for (int jj = 0; jj < 8; jj++) {
                    int jp = jj >> 1, o = jj & 1;
                    mma16816(ac2[i][jj], a[i][0], a[i][1], a[i][2], a[i][3],
                             bl[jp*4 + o*2], bl[jp*4 + o*2 + 1]);   // TRANS pairing
                }
#pragma unroll
            for (int i = 0; i < 2; i++) {
                uint32_t addr = sbase + PWTL + (tbs + ks*16 + trowA)*144
                              + (wm2*32 + i*16)*2 + gselA;
                ldsm4t(a[i][0], a[i][1], a[i][2], a[i][3], addr);
            }
#pragma unroll
            for (int i = 0; i < 2; i++)
#pragma unroll
                for (int jj = 0; jj < 8; jj++) {
                    int jp = jj >> 1, o = jj & 1;
                    mma16816(ac2[i][jj], a[i][0], a[i][1], a[i][2], a[i][3],
                             bh[jp*4 + o*2], bh[jp*4 + o*2 + 1]);   // TRANS pairing
                }
        }
    }

    // ---- stage ac2 into smem px [64][264], then vectorized red into g_px ----
    __syncthreads();   // all phase-2 reads of PWTH/PWTL complete
    {
        float* spx = (float*)sm;    // [64][264] floats, 67584B (over PWTH+PWTL)
        const int r = lane >> 2;
        const int c2 = (lane & 3) * 2;
#pragma unroll
        for (int i = 0; i < 2; i++) {
            int g0r = wm2 * 32 + i * 16 + r;
#pragma unroll
            for (int j = 0; j < 8; j++) {
                int col = wn2 * 64 + j * 8 + c2;
                *(float2*)&spx[g0r*264 + col]       = make_float2(ac2[i][j][0], ac2[i][j][1]);
                *(float2*)&spx[(g0r + 8)*264 + col] = make_float2(ac2[i][j][2], ac2[i][j][3]);
            }
        }
    }
    __syncthreads();
    {
        const int base = (b*8 + h) * 64;
        float* spx = (float*)sm;
#pragma unroll
        for (int it = 0; it < 16; it++) {
            int lin = tid + it * 256;        // float4 index, 4096 total
            int row = lin >> 6, c4 = lin & 63;
            float4 v = *(float4*)&spx[row*264 + c4*4];
            asm volatile("red.global.add.v4.f32 [%0], {%1,%2,%3,%4};"
                :: "l"(&g_px[(size_t)(base + row)*256 + c4*4]),
                   "f"(v.x), "f"(v.y), "f"(v.z), "f"(v.w) : "memory");
        }
    }
}

// ---------------- K_st: st = px @ W_fx + nrm * b_fx (d-split x4) ----------------
#define SMEM_ST (64*260*4 + 256*20*4)    // 66560 + 20480 = 87040
__global__ void __launch_bounds__(256) k_st(
    const float* __restrict__ Wfx, const float* __restrict__ bfx)
{
    float* spx = (float*)smem_dyn;              // [64][260]
    float* sw  = (float*)smem_dyn + 64*260;     // [256][20]
    const int h = blockIdx.x, b = blockIdx.y, z = blockIdx.z;   // z: d-stripe
    const int tid = threadIdx.x;
    const int bh = b*8 + h;

#pragma unroll
    for (int it = 0; it < 16; it++) {
        int i = tid + it * 256;
        int r = i >> 6, c4 = i & 63;
        *(float4*)&spx[r*260 + c4*4] = *(const float4*)&g_px[(size_t)(bh*64 + r)*256 + c4*4];
    }
#pragma unroll
    for (int it = 0; it < 4; it++) {
        int i = tid + it * 256;                 // 1024 float4 tasks
        int r = i >> 2, cq = i & 3;
        *(float4*)&sw[r*20 + cq*4] = *(const float4*)&Wfx[(size_t)r*512 + h*64 + z*16 + cq*4];
    }
    __syncthreads();

    const int g    = tid >> 2;
    const int dsub = (tid & 3) * 4;
    const float nv = g_nrm[bh*64 + g];
    float a4[4];
#pragma unroll
    for (int j = 0; j < 4; j++) a4[j] = nv * bfx[h*64 + z*16 + dsub + j];

    for (int c = 0; c < 256; c++) {
        float av = spx[g*260 + c];
        float4 w = *(float4*)&sw[c*20 + dsub];
        a4[0] += av * w.x;
        a4[1] += av * w.y;
        a4[2] += av * w.z;
        a4[3] += av * w.w;
    }
    *(float4*)&g_st[(size_t)(bh*64 + g)*64 + z*16 + dsub] =
        make_float4(a4[0], a4[1], a4[2], a4[3]);
}

// ---------------- K_C1: tiny attention over slice tokens (256 thr) ----------------
#define SMEM_ATTN (5*64*65*4)
__global__ void __launch_bounds__(256) k_attn(
    const float* __restrict__ Wq, const float* __restrict__ Wk,
    const float* __restrict__ Wv)
{
    float* sm = (float*)smem_dyn;
    float* S  = sm;
    float* Qs = sm + 64*65;
    float* Ks = sm + 2*64*65;
    float* Vs = sm + 3*64*65;
    float* Ps = sm + 4*64*65;

    const int h = blockIdx.x, b = blockIdx.y;
    const int tid = threadIdx.x;
    const int base = (b*8 + h) * 64;
    const int g  = tid >> 2;
    const int qd = (tid & 3) * 16;

    {
        float invn = 1.0f / (g_nrm[base + g] + 1e-5f);
#pragma unroll
        for (int j = 0; j < 16; j += 4) {
            float4 v = *(const float4*)&g_st[(base + g)*64 + qd + j];
            S[g*65 + qd + j]   = v.x * invn;
            S[g*65 + qd + j+1] = v.y * invn;
            S[g*65 + qd + j+2] = v.z * invn;
            S[g*65 + qd + j+3] = v.w * invn;
        }
    }
    __syncthreads();

    {
        float aq[16], ak[16], av[16];
#pragma unroll
        for (int j = 0; j < 16; j++) { aq[j] = 0.f; ak[j] = 0.f; av[j] = 0.f; }
        for (int k = 0; k < 64; k++) {
            float sv = S[g*65 + k];
            const float* wq = &Wq[k*64 + qd];
            const float* wk = &Wk[k*64 + qd];
            const float* wv = &Wv[k*64 + qd];
#pragma unroll
            for (int j = 0; j < 16; j++) {
                aq[j] += sv * wq[j];
                ak[j] += sv * wk[j];
                av[j] += sv * wv[j];
            }
        }
#pragma unroll
        for (int j = 0; j < 16; j++) {
            Qs[g*65 + qd + j] = aq[j];
            Ks[g*65 + qd + j] = ak[j];
            Vs[g*65 + qd + j] = av[j];
        }
    }
    __syncthreads();

    {
        float lg[16];
#pragma unroll
        for (int jj = 0; jj < 16; jj++) {
            int j = qd + jj;
            float dot = 0.f;
#pragma unroll
            for (int d = 0; d < 64; d++) dot += Qs[g*65 + d] * Ks[j*65 + d];
            lg[jj] = dot * 0.125f;
        }
        float mx = -1e30f;
#pragma unroll
        for (int jj = 0; jj < 16; jj++) mx = fmaxf(mx, lg[jj]);
        mx = fmaxf(mx, __shfl_xor_sync(0xffffffff, mx, 1));
        mx = fmaxf(mx, __shfl_xor_sync(0xffffffff, mx, 2));
        float s = 0.f;
#pragma unroll
        for (int jj = 0; jj < 16; jj++) { lg[jj] = __expf(lg[jj] - mx); s += lg[jj]; }
        s += __shfl_xor_sync(0xffffffff, s, 1);
        s += __shfl_xor_sync(0xffffffff, s, 2);
        float inv = 1.0f / s;
#pragma unroll
        for (int jj = 0; jj < 16; jj++) Ps[g*65 + qd + jj] = lg[jj] * inv;
    }
    __syncthreads();

    {
        float o[16];
#pragma unroll
        for (int d = 0; d < 16; d++) o[d] = 0.f;
        for (int j = 0; j < 64; j++) {
            float p = Ps[g*65 + j];
#pragma unroll
            for (int d = 0; d < 16; d++) o[d] += p * Vs[j*65 + qd + d];
        }
#pragma unroll
        for (int d = 0; d < 16; d++)
            g_os[(base + g)*64 + qd + d] = o[d];
    }
}

// ---------------- K_C2: P_t[b][c][h*64+g] split bf16 ----------------
#define SMEM_P ((64*68 + 64*256) * (int)sizeof(float))
__global__ void __launch_bounds__(256) k_P(const float* __restrict__ Wout)
{
    float* sm = (float*)smem_dyn;
    float* Os  = sm;
    float* Wsm = sm + 64*68;

    const int h = blockIdx.x, b = blockIdx.y;
    const int tid = threadIdx.x;
    const int base = (b*8 + h) * 64;

    for (int i = tid; i < 64*16; i += 256) {
        int r = i >> 4, c = i & 15;
        *(float4*)&Os[r*68 + c*4] = *(const float4*)&g_os[(size_t)(base + r)*64 + c*4];
    }
    for (int i = tid; i < 64*64; i += 256) {
        int r = i >> 6, c = i & 63;
        *(float4*)&Wsm[r*256 + c*4] = *(const float4*)&Wout[(size_t)(h*64 + r)*256 + c*4];
    }
    __syncthreads();

    const int gq = tid >> 3;
    const int cq = tid & 7;
    const int g0 = gq * 2;
    const int c0 = cq * 32;

    float acc[2][32];
#pragma unroll
    for (int i = 0; i < 2; i++)
#pragma unroll
        for (int j = 0; j < 32; j++) acc[i][j] = 0.f;

    for (int k = 0; k < 64; k++) {
        float a0 = Os[(g0+0)*68 + k];
        float a1 = Os[(g0+1)*68 + k];
#pragma unroll
        for (int c4 = 0; c4 < 8; c4++) {
            float4 w = *(float4*)&Wsm[k*256 + c0 + c4*4];
            acc[0][c4*4+0] += a0*w.x; acc[0][c4*4+1] += a0*w.y;
            acc[0][c4*4+2] += a0*w.z; acc[0][c4*4+3] += a0*w.w;
            acc[1][c4*4+0] += a1*w.x; acc[1][c4*4+1] += a1*w.y;
            acc[1][c4*4+2] += a1*w.z; acc[1][c4*4+3] += a1*w.w;
        }
    }
    __nv_bfloat16* Ph = &g_Pthi[(size_t)b * C_ * INNER_];
    __nv_bfloat16* Pl = &g_Ptlo[(size_t)b * C_ * INNER_];
#pragma unroll
    for (int i = 0; i < 2; i++)
#pragma unroll
        for (int c4 = 0; c4 < 8; c4++)
#pragma unroll
            for (int e = 0; e < 4; e++) {
                size_t off = (size_t)(c0 + c4*4 + e) * INNER_ + h*64 + g0 + i;
                __nv_bfloat16 hi, lo;
                split_one(acc[i][c4*4+e], hi, lo);
                Ph[off] = hi;
                Pl[off] = lo;
            }
}

// ---------------- launch ----------------
extern "C" void kernel_launch(void* const* d_in, const int* in_sizes, int n_in,
                              void* d_out, int out_size)
{
    const float* x    = (const float*)d_in[0];
    const float* Wfx  = (const float*)d_in[1];
    const float* bfx  = (const float*)d_in[2];
    const float* Wx   = (const float*)d_in[3];
    const float* bx   = (const float*)d_in[4];
    const float* Wsl  = (const float*)d_in[5];
    const float* bsl  = (const float*)d_in[6];
    const float* temp = (const float*)d_in[7];
    const float* Wq   = (const float*)d_in[8];
    const float* Wk   = (const float*)d_in[9];
    const float* Wv   = (const float*)d_in[10];
    const float* Wout = (const float*)d_in[11];
    const float* bout = (const float*)d_in[12];
    float* out = (float*)d_out;

    static bool init = false;
    static __nv_bfloat16 *g_whi_p, *g_wlo_p, *g_Pthi_p, *g_Ptlo_p;
    if (!init) {
        cudaGetSymbolAddress((void**)&g_whi_p,   g_whi);
        cudaGetSymbolAddress((void**)&g_wlo_p,   g_wlo);
        cudaGetSymbolAddress((void**)&g_Pthi_p,  g_Pthi);
        cudaGetSymbolAddress((void**)&g_Ptlo_p,  g_Ptlo);
        cudaFuncSetAttribute(k_gemm_ts, cudaFuncAttributeMaxDynamicSharedMemorySize, GK_SMEM);
        cudaFuncSetAttribute(k_pool, cudaFuncAttributeMaxDynamicSharedMemorySize, SMEM_POOL);
        cudaFuncSetAttribute(k_st,   cudaFuncAttributeMaxDynamicSharedMemorySize, SMEM_ST);
        cudaFuncSetAttribute(k_attn, cudaFuncAttributeMaxDynamicSharedMemorySize, SMEM_ATTN);
        cudaFuncSetAttribute(k_P,    cudaFuncAttributeMaxDynamicSharedMemorySize, SMEM_P);
        init = true;
    }

    // 0) x split + prep (zero px/nrm + W_comb)
    k_split_x<<<(BNTOK * 256 / 4) / 256, 256>>>(x);
    k_prep<<<641, 256>>>(Wx, Wsl, bx, bsl);

    // 1) fused logits/softmax/pool-x (tensor cores)
    k_pool<<<dim3(H_, N_/TOK, B_), 256, SMEM_POOL>>>(temp);

    // 2) st = px @ W_fx + nrm*b_fx (d-split x4)
    k_st<<<dim3(H_, B_, 4), 256, SMEM_ST>>>(Wfx, bfx);

    // 3) tiny attention over slice tokens
    k_attn<<<dim3(H_, B_), 256, SMEM_ATTN>>>(Wq, Wk, Wv);

    // 4) P precompute (transposed + split)
    k_P<<<dim3(H_, B_), 256, SMEM_P>>>(Wout);

    // 5) output GEMM (tensor cores, 3-pass)
    k_gemm_ts<<<dim3(2, BNTOK/128), 256, GK_SMEM>>>(
        g_whi_p, g_wlo_p, g_Pthi_p, g_Ptlo_p, 512, bout, out, 256);
}

// round 14
// speedup vs baseline: 1.3279x; 1.0977x over previous
#include <cuda_runtime.h>
#include <cuda_bf16.h>
#include <cstdint>
#include <math.h>

#define B_      4
#define N_      32768
#define C_      256
#define H_      8
#define D_      64
#define G_      64
#define INNER_  512
#define BNTOK   (B_*N_)          // 131072

// single dynamic smem symbol shared by all kernels
extern __shared__ char smem_dyn[];

// ---------------- scratch (device globals; allocation-free) ----------------
__device__ __nv_bfloat16 g_xhi[(size_t)BNTOK * 256];
__device__ __nv_bfloat16 g_xlo[(size_t)BNTOK * 256];
__device__ __nv_bfloat16 g_Wc[H_ * 64 * 256];        // combined W_x@Ws, [h][g][c]
__device__ float g_bcomb[H_ * 64];
__device__ __nv_bfloat16 g_whi[(size_t)BNTOK * 512]; // slice weights hi
__device__ __nv_bfloat16 g_wlo[(size_t)BNTOK * 512];
__device__ __nv_bfloat16 g_Pthi[B_ * C_ * INNER_];
__device__ __nv_bfloat16 g_Ptlo[B_ * C_ * INNER_];
__device__ float g_px [B_*H_*G_*C_];                 // pooled x: [bh][g][c], 2MB
__device__ float g_st [B_*H_*G_*D_];
__device__ float g_nrm[B_*H_*G_];
__device__ float g_os [B_*H_*G_*D_];

// ---------------- helpers ----------------
__device__ __forceinline__ uint32_t smem_to_u32(const void* p) {
    uint32_t a;
    asm("{ .reg .u64 t; cvta.to.shared.u64 t, %1; cvt.u32.u64 %0, t; }" : "=r"(a) : "l"(p));
    return a;
}
__device__ __forceinline__ void ldsm4(uint32_t &r0, uint32_t &r1, uint32_t &r2, uint32_t &r3,
                                      uint32_t addr) {
    asm volatile("ldmatrix.sync.aligned.m8n8.x4.shared.b16 {%0,%1,%2,%3}, [%4];"
        : "=r"(r0), "=r"(r1), "=r"(r2), "=r"(r3) : "r"(addr));
}
__device__ __forceinline__ void ldsm4t(uint32_t &r0, uint32_t &r1, uint32_t &r2, uint32_t &r3,
                                       uint32_t addr) {
    asm volatile("ldmatrix.sync.aligned.m8n8.x4.trans.shared.b16 {%0,%1,%2,%3}, [%4];"
        : "=r"(r0), "=r"(r1), "=r"(r2), "=r"(r3) : "r"(addr));
}
__device__ __forceinline__ void mma16816(float* c,
                                         uint32_t a0, uint32_t a1, uint32_t a2, uint32_t a3,
                                         uint32_t b0, uint32_t b1) {
    asm volatile(
        "mma.sync.aligned.m16n8k16.row.col.f32.bf16.bf16.f32 "
        "{%0,%1,%2,%3}, {%4,%5,%6,%7}, {%8,%9}, {%0,%1,%2,%3};"
        : "+f"(c[0]), "+f"(c[1]), "+f"(c[2]), "+f"(c[3])
        : "r"(a0), "r"(a1), "r"(a2), "r"(a3), "r"(b0), "r"(b1));
}
__device__ __forceinline__ void split_one(float a, __nv_bfloat16 &hi, __nv_bfloat16 &lo) {
    hi = __float2bfloat16(a);
    lo = __float2bfloat16(a - __bfloat162float(hi));
}
__device__ __forceinline__ void split_pair(float a, float b, unsigned &hi, unsigned &lo) {
    __nv_bfloat16 ah, al, bh, bl;
    split_one(a, ah, al);
    split_one(b, bh, bl);
    hi = ((unsigned)__bfloat16_as_ushort(bh) << 16) | (unsigned)__bfloat16_as_ushort(ah);
    lo = ((unsigned)__bfloat16_as_ushort(bl) << 16) | (unsigned)__bfloat16_as_ushort(al);
}
#define CP_ASYNC16(dst, src) \
    asm volatile("cp.async.cg.shared.global [%0], [%1], 16;" :: "r"(dst), "l"(src))
#define CP_COMMIT()  asm volatile("cp.async.commit_group;")
#define CP_WAIT0()   asm volatile("cp.async.wait_group 0;")
#define RED_ADD_V2(ptr, v0, v1) \
    asm volatile("red.global.add.v2.f32 [%0], {%1,%2};" \
        :: "l"(ptr), "f"(v0), "f"(v1) : "memory")

// ---------------- K_sx: split x into bf16 hi/lo ----------------
__global__ void __launch_bounds__(256) k_split_x(const float* __restrict__ x) {
    size_t i = (size_t)blockIdx.x * 256 + threadIdx.x;
    float4 v = *(const float4*)(x + i * 4);
    unsigned h0, l0, h1, l1;
    split_pair(v.x, v.y, h0, l0);
    split_pair(v.z, v.w, h1, l1);
    *(uint2*)&g_xhi[i * 4] = make_uint2(h0, h1);
    *(uint2*)&g_xlo[i * 4] = make_uint2(l0, l1);
}

// ---------------- K_prep: fused zero(px, nrm) + comb ----------------
__global__ void __launch_bounds__(256) k_prep(
    const float* __restrict__ Wx, const float* __restrict__ Wsl,
    const float* __restrict__ bx, const float* __restrict__ bsl)
{
    __shared__ float sws[64*64];
    const int bid = blockIdx.x;
    const int tid = threadIdx.x;

    if (bid < 512) {
        ((float4*)g_px)[bid * 256 + tid] = make_float4(0.f, 0.f, 0.f, 0.f);
        return;
    }
    if (bid == 512) {
        ((float4*)g_nrm)[tid]       = make_float4(0.f, 0.f, 0.f, 0.f);
        ((float4*)g_nrm)[tid + 256] = make_float4(0.f, 0.f, 0.f, 0.f);
        return;
    }
    const int r  = bid - 513;
    const int h  = r & 7;
    const int cb = r >> 3;
    for (int i = tid; i < 4096; i += 256) sws[i] = Wsl[i];
    __syncthreads();
    const int g = tid & 63, cq = tid >> 6;
#pragma unroll
    for (int cc = 0; cc < 4; cc++) {
        int c = cb * 16 + cq * 4 + cc;
        float s = 0.f;
        const float* wxr = &Wx[(size_t)c * 512 + h * 64];
#pragma unroll 16
        for (int d = 0; d < 64; d++) s += wxr[d] * sws[d*64 + g];
        g_Wc[(h*64 + g)*256 + c] = __float2bfloat16(s);
    }
    if (cb == 0 && tid < 64) {
        float s = bsl[tid];
        for (int d = 0; d < 64; d++) s += bx[h*64 + d] * sws[d*64 + tid];
        g_bcomb[h*64 + tid] = s;
    }
}

// ================= split-bf16 tensor-core GEMM (output GEMM only) =================
#define GK_ROWB 80
#define GK_ARR  (128 * GK_ROWB)
#define GK_STG  (4 * GK_ARR)
#define GK_SMEM (2 * GK_STG)

__global__ void __launch_bounds__(256, 2) k_gemm_ts(
    const __nv_bfloat16* __restrict__ Ahi, const __nv_bfloat16* __restrict__ Alo,
    const __nv_bfloat16* __restrict__ Bhi, const __nv_bfloat16* __restrict__ Blo,
    int K,
    const float* __restrict__ bias,
    float* __restrict__ OutF, int ldc)
{
    char* sm = smem_dyn;
    const uint32_t sbase = smem_to_u32(sm);

    const int tid  = threadIdx.x;
    const int wid  = tid >> 5;
    const int lane = tid & 31;
    const int wm   = wid >> 2;
    const int wn   = wid & 3;
    const int m0   = blockIdx.y * 128;
    const int n0   = blockIdx.x * 128;

    const __nv_bfloat16* srcs[4];
    srcs[0] = Ahi + (size_t)m0 * K;
    srcs[1] = Alo + (size_t)m0 * K;
    size_t boff = (size_t)(m0 >> 15) * 256 * INNER_ + (size_t)n0 * K;
    srcs[2] = Bhi + boff;
    srcs[3] = Blo + boff;

    const int srow0 = tid >> 2,         sq0 = tid & 3;
    const int srow1 = (tid + 256) >> 2, sq1 = (tid + 256) & 3;

    float acc[4][4][4];
#pragma unroll
    for (int i = 0; i < 4; i++)
#pragma unroll
        for (int j = 0; j < 4; j++)
#pragma unroll
            for (int e = 0; e < 4; e++) acc[i][j][e] = 0.f;

    const int lrow = lane & 15;
    const int lkq  = (lane >> 4) << 3;
    const int nch  = K >> 5;

#pragma unroll
    for (int arr = 0; arr < 4; arr++) {
        const __nv_bfloat16* s = srcs[arr];
        uint32_t d = sbase + arr * GK_ARR;
        CP_ASYNC16(d + srow0 * GK_ROWB + sq0 * 16, s + (size_t)srow0 * K + sq0 * 8);
        CP_ASYNC16(d + srow1 * GK_ROWB + sq1 * 16, s + (size_t)srow1 * K + sq1 * 8);
    }
    CP_COMMIT();

    for (int ch = 0; ch < nch; ch++) {
        CP_WAIT0();
        __syncthreads();
        if (ch + 1 < nch) {
            const int k1 = (ch + 1) << 5;
            const uint32_t stg = sbase + ((ch + 1) & 1) * GK_STG;
#pragma unroll
            for (int arr = 0; arr < 4; arr++) {
                const __nv_bfloat16* s = srcs[arr] + k1;
                uint32_t d = stg + arr * GK_ARR;
                CP_ASYNC16(d + srow0 * GK_ROWB + sq0 * 16, s + (size_t)srow0 * K + sq0 * 8);
                CP_ASYNC16(d + srow1 * GK_ROWB + sq1 * 16, s + (size_t)srow1 * K + sq1 * 8);
            }
            CP_COMMIT();
        }

        const uint32_t stg  = sbase + (ch & 1) * GK_STG;
        const uint32_t sahi = stg, salo = stg + GK_ARR;
        const uint32_t sbhi = stg + 2 * GK_ARR, sblo = stg + 3 * GK_ARR;

#pragma unroll
        for (int ks = 0; ks < 2; ks++) {
            const int khb = (ks * 16 + lkq) * 2;
            uint32_t a[4][4], bh[8], bl[8];
#pragma unroll
            for (int i = 0; i < 4; i++) {
                int row = wm * 64 + i * 16 + lrow;
                ldsm4(a[i][0], a[i][1], a[i][2], a[i][3], sahi + row * GK_ROWB + khb);
            }
#pragma unroll
            for (int jp = 0; jp < 2; jp++) {
                int row = wn * 32 + jp * 16 + lrow;
                ldsm4(bh[jp*4+0], bh[jp*4+1], bh[jp*4+2], bh[jp*4+3],
                      sbhi + row * GK_ROWB + khb);
            }
#pragma unroll
            for (int i = 0; i < 4; i++) {
                mma16816(acc[i][0], a[i][0], a[i][1], a[i][2], a[i][3], bh[0], bh[2]);
                mma16816(acc[i][1], a[i][0], a[i][1], a[i][2], a[i][3], bh[1], bh[3]);
                mma16816(acc[i][2], a[i][0], a[i][1], a[i][2], a[i][3], bh[4], bh[6]);
                mma16816(acc[i][3], a[i][0], a[i][1], a[i][2], a[i][3], bh[5], bh[7]);
            }
#pragma unroll
            for (int jp = 0; jp < 2; jp++) {
                int row = wn * 32 + jp * 16 + lrow;
                ldsm4(bl[jp*4+0], bl[jp*4+1], bl[jp*4+2], bl[jp*4+3],
                      sblo + row * GK_ROWB + khb);
            }
#pragma unroll
            for (int i = 0; i < 4; i++) {
                mma16816(acc[i][0], a[i][0], a[i][1], a[i][2], a[i][3], bl[0], bl[2]);
                mma16816(acc[i][1], a[i][0], a[i][1], a[i][2], a[i][3], bl[1], bl[3]);
                mma16816(acc[i][2], a[i][0], a[i][1], a[i][2], a[i][3], bl[4], bl[6]);
                mma16816(acc[i][3], a[i][0], a[i][1], a[i][2], a[i][3], bl[5], bl[7]);
            }
#pragma unroll
            for (int i = 0; i < 4; i++) {
                int row = wm * 64 + i * 16 + lrow;
                ldsm4(a[i][0], a[i][1], a[i][2], a[i][3], salo + row * GK_ROWB + khb);
            }
#pragma unroll
            for (int i = 0; i < 4; i++) {
                mma16816(acc[i][0], a[i][0], a[i][1], a[i][2], a[i][3], bh[0], bh[2]);
                mma16816(acc[i][1], a[i][0], a[i][1], a[i][2], a[i][3], bh[1], bh[3]);
                mma16816(acc[i][2], a[i][0], a[i][1], a[i][2], a[i][3], bh[4], bh[6]);
                mma16816(acc[i][3], a[i][0], a[i][1], a[i][2], a[i][3], bh[5], bh[7]);
            }
        }
    }

    const int r0 = lane >> 2;
    const int c0 = (lane & 3) * 2;
#pragma unroll
    for (int j = 0; j < 4; j++) {
        const int col = n0 + wn * 32 + j * 8 + c0;
        const float2 bi = *(const float2*)&bias[col];
#pragma unroll
        for (int i = 0; i < 4; i++) {
            const int row = m0 + wm * 64 + i * 16 + r0;
            float2 o0 = {acc[i][j][0] + bi.x, acc[i][j][1] + bi.y};
            float2 o1 = {acc[i][j][2] + bi.x, acc[i][j][3] + bi.y};
            *(float2*)&OutF[(size_t)row * ldc + col] = o0;
            *(float2*)&OutF[(size_t)(row + 8) * ldc + col] = o1;
        }
    }
}

// ================= K_B: fused logits+softmax+pool-x (2 CTA/SM) =================
// Phase 1 (1-pass): L = x_hi @ Wc_hi^T -> softmax -> w  ([t][g] smem + gmem split)
// Phase 2 (3-pass): px[64g][256c] += w^T @ x as 16 (cq,ts) tiles, red.v2 flush/cq
#define TOK 256
#define PWTH  0          // 256x144 = 36864 : phase1 x buf A / w hi [t][g]
#define PWTL  36864      // 36864          : phase1 x buf B / w lo
#define PWC   73728      // 33792 Wc (phase1 only)
#define XS0H  73728      // 64x144 = 9216 (phase2 x slice buffers, overlay PWC)
#define XS0L  82944
#define XS1H  92160
#define XS1L  101376
#define PBSL  110592
#define PNRM  110848
#define SMEM_POOL 112128

__global__ void __launch_bounds__(256, 2) k_pool(const float* __restrict__ temperature)
{
    char* sm = smem_dyn;
    const uint32_t sbase = smem_to_u32(sm);
    float* bslf = (float*)(sm + PBSL);
    float* nrmp = (float*)(sm + PNRM);

    const int h  = blockIdx.x;
    const int tb = blockIdx.y;
    const int b  = blockIdx.z;
    const int tid = threadIdx.x;
    const int wid = tid >> 5;
    const int lane = tid & 31;
    const int m0  = b * N_ + tb * TOK;
    const int lrow = lane & 15;
    const int lkq  = (lane >> 4) << 3;

    // prologue: Wc -> PWC, x chunk0 -> PWTH region
#pragma unroll
    for (int it = 0; it < 8; it++) {
        int i = tid + it * 256;
        int r = i >> 5, q = i & 31;
        CP_ASYNC16(sbase + PWC + r*528 + q*16, &g_Wc[(size_t)(h*64 + r)*256 + q*8]);
    }
#pragma unroll
    for (int it = 0; it < 8; it++) {
        int i = tid + it * 256;
        int r = i >> 3, q = i & 7;
        CP_ASYNC16(sbase + PWTH + r*144 + q*16, &g_xhi[(size_t)(m0+r)*256 + q*8]);
    }
    CP_COMMIT();
    if (tid < 64) bslf[tid] = g_bcomb[h*64 + tid];

    // ---- phase 1 MMA (1-pass), K=256 in 4 chunks ----
    float acc[2][8][4];
#pragma unroll
    for (int i = 0; i < 2; i++)
#pragma unroll
        for (int j = 0; j < 8; j++)
#pragma unroll
            for (int e = 0; e < 4; e++) acc[i][j][e] = 0.f;

#pragma unroll
    for (int kc = 0; kc < 4; kc++) {
        CP_WAIT0();
        __syncthreads();
        if (kc + 1 < 4) {
            const uint32_t dstb = sbase + (((kc + 1) & 1) ? PWTL : PWTH);
#pragma unroll
            for (int it = 0; it < 8; it++) {
                int i = tid + it * 256;
                int r = i >> 3, q = i & 7;
                CP_ASYNC16(dstb + r*144 + q*16,
                           &g_xhi[(size_t)(m0+r)*256 + (kc+1)*64 + q*8]);
            }
            CP_COMMIT();
        }
        const uint32_t abuf = sbase + ((kc & 1) ? PWTL : PWTH);
#pragma unroll
        for (int ks = 0; ks < 4; ks++) {
            const int khA = (ks * 16 + lkq) * 2;
            const int khB = (kc * 64 + ks * 16 + lkq) * 2;
            uint32_t a[2][4], bh[16];
#pragma unroll
            for (int i = 0; i < 2; i++) {
                int row = wid * 32 + i * 16 + lrow;
                ldsm4(a[i][0], a[i][1], a[i][2], a[i][3], abuf + row*144 + khA);
            }
#pragma unroll
            for (int jp = 0; jp < 4; jp++) {
                int row = jp * 16 + lrow;
                ldsm4(bh[jp*4+0], bh[jp*4+1], bh[jp*4+2], bh[jp*4+3],
                      sbase + PWC + row*528 + khB);
            }
#pragma unroll
            for (int i = 0; i < 2; i++)
#pragma unroll
                for (int jj = 0; jj < 8; jj++) {
                    int jp = jj >> 1, o = jj & 1;
                    mma16816(acc[i][jj], a[i][0], a[i][1], a[i][2], a[i][3],
                             bh[jp*4+o], bh[jp*4+o+2]);   // non-trans pairing
                }
        }
    }
    __syncthreads();   // PWTH/PWTL/PWC regions free now

    // kick (cq=0, ts=0) x slice into XS0 (overlaps softmax + w writes)
#pragma unroll
    for (int it = 0; it < 2; it++) {
        int i = tid + it * 256;          // 512 tasks per type
        int r = i >> 3, q = i & 7;
        CP_ASYNC16(sbase + XS0H + r*144 + q*16, &g_xhi[(size_t)(m0 + r)*256 + q*8]);
        CP_ASYNC16(sbase + XS0L + r*144 + q*16, &g_xlo[(size_t)(m0 + r)*256 + q*8]);
    }
    CP_COMMIT();

    // ---- softmax over g ----
    float tmp = temperature[h];
    tmp = fminf(fmaxf(tmp, 0.1f), 5.0f);
    const float itemp = 1.0f / tmp;

#pragma unroll
    for (int i = 0; i < 2; i++)
#pragma unroll
        for (int j = 0; j < 8; j++) {
            float2 bi = *(float2*)&bslf[j*8 + (lane & 3)*2];
            acc[i][j][0] = (acc[i][j][0] + bi.x) * itemp;
            acc[i][j][1] = (acc[i][j][1] + bi.y) * itemp;
            acc[i][j][2] = (acc[i][j][2] + bi.x) * itemp;
            acc[i][j][3] = (acc[i][j][3] + bi.y) * itemp;
        }
    float inv0[2], inv1[2];
#pragma unroll
    for (int i = 0; i < 2; i++) {
        float m0v = -1e30f, m1v = -1e30f;
#pragma unroll
        for (int j = 0; j < 8; j++) {
            m0v = fmaxf(m0v, fmaxf(acc[i][j][0], acc[i][j][1]));
            m1v = fmaxf(m1v, fmaxf(acc[i][j][2], acc[i][j][3]));
        }
        m0v = fmaxf(m0v, __shfl_xor_sync(0xffffffff, m0v, 1));
        m0v = fmaxf(m0v, __shfl_xor_sync(0xffffffff, m0v, 2));
        m1v = fmaxf(m1v, __shfl_xor_sync(0xffffffff, m1v, 1));
        m1v = fmaxf(m1v, __shfl_xor_sync(0xffffffff, m1v, 2));
        float s0 = 0.f, s1 = 0.f;
#pragma unroll
        for (int j = 0; j < 8; j++) {
            acc[i][j][0] = __expf(acc[i][j][0] - m0v);
            acc[i][j][1] = __expf(acc[i][j][1] - m0v);
            acc[i][j][2] = __expf(acc[i][j][2] - m1v);
            acc[i][j][3] = __expf(acc[i][j][3] - m1v);
            s0 += acc[i][j][0] + acc[i][j][1];
            s1 += acc[i][j][2] + acc[i][j][3];
        }
        s0 += __shfl_xor_sync(0xffffffff, s0, 1);
        s0 += __shfl_xor_sync(0xffffffff, s0, 2);
        s1 += __shfl_xor_sync(0xffffffff, s1, 1);
        s1 += __shfl_xor_sync(0xffffffff, s1, 2);
        inv0[i] = 1.0f / s0;
        inv1[i] = 1.0f / s1;
    }

    // ---- write w: to [t][g] smem (packed 4B) and to g_w gmem (split) ----
    {
        const int r = lane >> 2;
#pragma unroll
        for (int i = 0; i < 2; i++) {
            int t0 = wid * 32 + i * 16 + r;
            int t1 = t0 + 8;
#pragma unroll
            for (int j = 0; j < 8; j++) {
                int c = j * 8 + (lane & 3) * 2;
                float w00 = acc[i][j][0] * inv0[i], w01 = acc[i][j][1] * inv0[i];
                float w10 = acc[i][j][2] * inv1[i], w11 = acc[i][j][3] * inv1[i];
                unsigned h0, l0, h1, l1;
                split_pair(w00, w01, h0, l0);
                split_pair(w10, w11, h1, l1);
                *(unsigned*)&g_whi[(size_t)(m0 + t0)*512 + h*64 + c] = h0;
                *(unsigned*)&g_wlo[(size_t)(m0 + t0)*512 + h*64 + c] = l0;
                *(unsigned*)&g_whi[(size_t)(m0 + t1)*512 + h*64 + c] = h1;
                *(unsigned*)&g_wlo[(size_t)(m0 + t1)*512 + h*64 + c] = l1;
                *(unsigned*)(sm + PWTH + t0*144 + c*2) = h0;
                *(unsigned*)(sm + PWTL + t0*144 + c*2) = l0;
                *(unsigned*)(sm + PWTH + t1*144 + c*2) = h1;
                *(unsigned*)(sm + PWTL + t1*144 + c*2) = l1;
            }
        }
    }
    __syncthreads();

    // ---- norm partial sums ----
    {
        int g = tid & 63, q = tid >> 6;
        float s = 0.f;
#pragma unroll 8
        for (int t = q*64; t < q*64 + 64; t++) {
            s += __bfloat162float(*(__nv_bfloat16*)(sm + PWTH + t*144 + g*2));
            s += __bfloat162float(*(__nv_bfloat16*)(sm + PWTL + t*144 + g*2));
        }
        nrmp[q*64 + g] = s;
    }
    __syncthreads();
    if (tid < 64) {
        float s = nrmp[tid] + nrmp[64+tid] + nrmp[128+tid] + nrmp[192+tid];
        atomicAdd(&g_nrm[(b*8 + h)*64 + tid], s);
    }

    // ---- phase 2: 16 (cq,ts) tiles; warp tile 32g x 16c; flush per cq ----
    const int wm2 = wid >> 2;
    const int wn2 = wid & 3;
    const int trowA = (lane & 7) | ((lane >> 1) & 8);
    const int gselA = (lane & 8) * 2;
    const int base = (b*8 + h) * 64;
    const int rr = lane >> 2;
    const int cc2 = (lane & 3) * 2;

    float ac2[2][2][4];
#pragma unroll
    for (int i = 0; i < 2; i++)
#pragma unroll
        for (int j = 0; j < 2; j++)
#pragma unroll
            for (int e = 0; e < 4; e++) ac2[i][j][e] = 0.f;

    for (int qq = 0; qq < 16; qq++) {
        const int cq = qq >> 2, ts = qq & 3;
        CP_WAIT0();
        __syncthreads();
        if (qq + 1 < 16) {
            const int ncq = (qq + 1) >> 2, nts = (qq + 1) & 3;
            const uint32_t dh = sbase + (((qq + 1) & 1) ? XS1H : XS0H);
            const uint32_t dl = sbase + (((qq + 1) & 1) ? XS1L : XS0L);
#pragma unroll
            for (int it = 0; it < 2; it++) {
                int i = tid + it * 256;
                int r = i >> 3, q = i & 7;
                size_t src = (size_t)(m0 + nts*64 + r)*256 + ncq*64 + q*8;
                CP_ASYNC16(dh + r*144 + q*16, &g_xhi[src]);
                CP_ASYNC16(dl + r*144 + q*16, &g_xlo[src]);
            }
            CP_COMMIT();
        }
        const uint32_t sh = sbase + ((qq & 1) ? XS1H : XS0H);
        const uint32_t sl = sbase + ((qq & 1) ? XS1L : XS0L);
        const int tbs = ts * 64;

#pragma unroll
        for (int ks = 0; ks < 4; ks++) {
            uint32_t a[2][4], bh[4], bl[4];
#pragma unroll
            for (int i = 0; i < 2; i++) {
                uint32_t addr = sbase + PWTH + (tbs + ks*16 + trowA)*144
                              + (wm2*32 + i*16)*2 + gselA;
                ldsm4t(a[i][0], a[i][1], a[i][2], a[i][3], addr);
            }
            {
                uint32_t addr = sh + (ks*16 + lrow)*144 + (wn2*16 + lkq)*2;
                ldsm4t(bh[0], bh[1], bh[2], bh[3], addr);
            }
#pragma unroll
            for (int i = 0; i < 2; i++) {              // hh
                mma16816(ac2[i][0], a[i][0], a[i][1], a[i][2], a[i][3], bh[0], bh[1]);
                mma16816(ac2[i][1], a[i][0], a[i][1], a[i][2], a[i][3], bh[2], bh[3]);
            }
            {
                uint32_t addr = sl + (ks*16 + lrow)*144 + (wn2*16 + lkq)*2;
                ldsm4t(bl[0], bl[1], bl[2], bl[3], addr);
            }
#pragma unroll
            for (int i = 0; i < 2; i++) {              // hl
                mma16816(ac2[i][0], a[i][0], a[i][1], a[i][2], a[i][3], bl[0], bl[1]);
                mma16816(ac2[i][1], a[i][0], a[i][1], a[i][2], a[i][3], bl[2], bl[3]);
            }
#pragma unroll
            for (int i = 0; i < 2; i++) {
                uint32_t addr = sbase + PWTL + (tbs + ks*16 + trowA)*144
                              + (wm2*32 + i*16)*2 + gselA;
                ldsm4t(a[i][0], a[i][1], a[i][2], a[i][3], addr);
            }
#pragma unroll
            for (int i = 0; i < 2; i++) {              // lh
                mma16816(ac2[i][0], a[i][0], a[i][1], a[i][2], a[i][3], bh[0], bh[1]);
                mma16816(ac2[i][1], a[i][0], a[i][1], a[i][2], a[i][3], bh[2], bh[3]);
            }
        }

        if (ts == 3) {   // flush this c-quarter, zero acc
#pragma unroll
            for (int i = 0; i < 2; i++) {
                int g0r = wm2 * 32 + i * 16 + rr;
#pragma unroll
                for (int j = 0; j < 2; j++) {
                    int col = cq * 64 + wn2 * 16 + j * 8 + cc2;
                    RED_ADD_V2(&g_px[(size_t)(base + g0r)*256 + col],
                               ac2[i][j][0], ac2[i][j][1]);
                    RED_ADD_V2(&g_px[(size_t)(base + g0r + 8)*256 + col],
                               ac2[i][j][2], ac2[i][j][3]);
#pragma unroll
                    for (int e = 0; e < 4; e++) ac2[i][j][e] = 0.f;
                }
            }
        }
    }
}

// ---------------- K_st: st = px @ W_fx + nrm * b_fx (d-split x4) ----------------
#define SMEM_ST (64*260*4 + 256*20*4)
__global__ void __launch_bounds__(256) k_st(
    const float* __restrict__ Wfx, const float* __restrict__ bfx)
{
    float* spx = (float*)smem_dyn;              // [64][260]
    float* sw  = (float*)smem_dyn + 64*260;     // [256][20]
    const int h = blockIdx.x, b = blockIdx.y, z = blockIdx.z;
    const int tid = threadIdx.x;
    const int bh = b*8 + h;

#pragma unroll
    for (int it = 0; it < 16; it++) {
        int i = tid + it * 256;
        int r = i >> 6, c4 = i & 63;
        *(float4*)&spx[r*260 + c4*4] = *(const float4*)&g_px[(size_t)(bh*64 + r)*256 + c4*4];
    }
#pragma unroll
    for (int it = 0; it < 4; it++) {
        int i = tid + it * 256;
        int r = i >> 2, cq = i & 3;
        *(float4*)&sw[r*20 + cq*4] = *(const float4*)&Wfx[(size_t)r*512 + h*64 + z*16 + cq*4];
    }
    __syncthreads();

    const int g    = tid >> 2;
    const int dsub = (tid & 3) * 4;
    const float nv = g_nrm[bh*64 + g];
    float a4[4];
#pragma unroll
    for (int j = 0; j < 4; j++) a4[j] = nv * bfx[h*64 + z*16 + dsub + j];

    for (int c = 0; c < 256; c++) {
        float av = spx[g*260 + c];
        float4 w = *(float4*)&sw[c*20 + dsub];
        a4[0] += av * w.x;
        a4[1] += av * w.y;
        a4[2] += av * w.z;
        a4[3] += av * w.w;
    }
    *(float4*)&g_st[(size_t)(bh*64 + g)*64 + z*16 + dsub] =
        make_float4(a4[0], a4[1], a4[2], a4[3]);
}

// ---------------- K_C1: tiny attention over slice tokens (256 thr) ----------------
#define SMEM_ATTN (5*64*65*4)
__global__ void __launch_bounds__(256) k_attn(
    const float* __restrict__ Wq, const float* __restrict__ Wk,
    const float* __restrict__ Wv)
{
    float* sm = (float*)smem_dyn;
    float* S  = sm;
    float* Qs = sm + 64*65;
    float* Ks = sm + 2*64*65;
    float* Vs = sm + 3*64*65;
    float* Ps = sm + 4*64*65;

    const int h = blockIdx.x, b = blockIdx.y;
    const int tid = threadIdx.x;
    const int base = (b*8 + h) * 64;
    const int g  = tid >> 2;
    const int qd = (tid & 3) * 16;

    {
        float invn = 1.0f / (g_nrm[base + g] + 1e-5f);
#pragma unroll
        for (int j = 0; j < 16; j += 4) {
            float4 v = *(const float4*)&g_st[(base + g)*64 + qd + j];
            S[g*65 + qd + j]   = v.x * invn;
            S[g*65 + qd + j+1] = v.y * invn;
            S[g*65 + qd + j+2] = v.z * invn;
            S[g*65 + qd + j+3] = v.w * invn;
        }
    }
    __syncthreads();

    {
        float aq[16], ak[16], av[16];
#pragma unroll
        for (int j = 0; j < 16; j++) { aq[j] = 0.f; ak[j] = 0.f; av[j] = 0.f; }
        for (int k = 0; k < 64; k++) {
            float sv = S[g*65 + k];
            const float* wq = &Wq[k*64 + qd];
            const float* wk = &Wk[k*64 + qd];
            const float* wv = &Wv[k*64 + qd];
#pragma unroll
            for (int j = 0; j < 16; j++) {
                aq[j] += sv * wq[j];
                ak[j] += sv * wk[j];
                av[j] += sv * wv[j];
            }
        }
#pragma unroll
        for (int j = 0; j < 16; j++) {
            Qs[g*65 + qd + j] = aq[j];
            Ks[g*65 + qd + j] = ak[j];
            Vs[g*65 + qd + j] = av[j];
        }
    }
    __syncthreads();

    {
        float lg[16];
#pragma unroll
        for (int jj = 0; jj < 16; jj++) {
            int j = qd + jj;
            float dot = 0.f;
#pragma unroll
            for (int d = 0; d < 64; d++) dot += Qs[g*65 + d] * Ks[j*65 + d];
            lg[jj] = dot * 0.125f;
        }
        float mx = -1e30f;
#pragma unroll
        for (int jj = 0; jj < 16; jj++) mx = fmaxf(mx, lg[jj]);
        mx = fmaxf(mx, __shfl_xor_sync(0xffffffff, mx, 1));
        mx = fmaxf(mx, __shfl_xor_sync(0xffffffff, mx, 2));
        float s = 0.f;
#pragma unroll
        for (int jj = 0; jj < 16; jj++) { lg[jj] = __expf(lg[jj] - mx); s += lg[jj]; }
        s += __shfl_xor_sync(0xffffffff, s, 1);
        s += __shfl_xor_sync(0xffffffff, s, 2);
        float inv = 1.0f / s;
#pragma unroll
        for (int jj = 0; jj < 16; jj++) Ps[g*65 + qd + jj] = lg[jj] * inv;
    }
    __syncthreads();

    {
        float o[16];
#pragma unroll
        for (int d = 0; d < 16; d++) o[d] = 0.f;
        for (int j = 0; j < 64; j++) {
            float p = Ps[g*65 + j];
#pragma unroll
            for (int d = 0; d < 16; d++) o[d] += p * Vs[j*65 + qd + d];
        }
#pragma unroll
        for (int d = 0; d < 16; d++)
            g_os[(base + g)*64 + qd + d] = o[d];
    }
}

// ---------------- K_C2: P_t[b][c][h*64+g] split bf16 ----------------
#define SMEM_P ((64*68 + 64*256) * (int)sizeof(float))
__global__ void __launch_bounds__(256) k_P(const float* __restrict__ Wout)
{
    float* sm = (float*)smem_dyn;
    float* Os  = sm;
    float* Wsm = sm + 64*68;

    const int h = blockIdx.x, b = blockIdx.y;
    const int tid = threadIdx.x;
    const int base = (b*8 + h) * 64;

    for (int i = tid; i < 64*16; i += 256) {
        int r = i >> 4, c = i & 15;
        *(float4*)&Os[r*68 + c*4] = *(const float4*)&g_os[(size_t)(base + r)*64 + c*4];
    }
    for (int i = tid; i < 64*64; i += 256) {
        int r = i >> 6, c = i & 63;
        *(float4*)&Wsm[r*256 + c*4] = *(const float4*)&Wout[(size_t)(h*64 + r)*256 + c*4];
    }
    __syncthreads();

    const int gq = tid >> 3;
    const int cq = tid & 7;
    const int g0 = gq * 2;
    const int c0 = cq * 32;

    float acc[2][32];
#pragma unroll
    for (int i = 0; i < 2; i++)
#pragma unroll
        for (int j = 0; j < 32; j++) acc[i][j] = 0.f;

    for (int k = 0; k < 64; k++) {
        float a0 = Os[(g0+0)*68 + k];
        float a1 = Os[(g0+1)*68 + k];
#pragma unroll
        for (int c4 = 0; c4 < 8; c4++) {
            float4 w = *(float4*)&Wsm[k*256 + c0 + c4*4];
            acc[0][c4*4+0] += a0*w.x; acc[0][c4*4+1] += a0*w.y;
            acc[0][c4*4+2] += a0*w.z; acc[0][c4*4+3] += a0*w.w;
            acc[1][c4*4+0] += a1*w.x; acc[1][c4*4+1] += a1*w.y;
            acc[1][c4*4+2] += a1*w.z; acc[1][c4*4+3] += a1*w.w;
        }
    }
    __nv_bfloat16* Ph = &g_Pthi[(size_t)b * C_ * INNER_];
    __nv_bfloat16* Pl = &g_Ptlo[(size_t)b * C_ * INNER_];
#pragma unroll
    for (int i = 0; i < 2; i++)
#pragma unroll
        for (int c4 = 0; c4 < 8; c4++)
#pragma unroll
            for (int e = 0; e < 4; e++) {
                size_t off = (size_t)(c0 + c4*4 + e) * INNER_ + h*64 + g0 + i;
                __nv_bfloat16 hi, lo;
                split_one(acc[i][c4*4+e], hi, lo);
                Ph[off] = hi;
                Pl[off] = lo;
            }
}

// ---------------- launch ----------------
extern "C" void kernel_launch(void* const* d_in, const int* in_sizes, int n_in,
                              void* d_out, int out_size)
{
    const float* x    = (const float*)d_in[0];
    const float* Wfx  = (const float*)d_in[1];
    const float* bfx  = (const float*)d_in[2];
    const float* Wx   = (const float*)d_in[3];
    const float* bx   = (const float*)d_in[4];
    const float* Wsl  = (const float*)d_in[5];
    const float* bsl  = (const float*)d_in[6];
    const float* temp = (const float*)d_in[7];
    const float* Wq   = (const float*)d_in[8];
    const float* Wk   = (const float*)d_in[9];
    const float* Wv   = (const float*)d_in[10];
    const float* Wout = (const float*)d_in[11];
    const float* bout = (const float*)d_in[12];
    float* out = (float*)d_out;

    static bool init = false;
    static __nv_bfloat16 *g_whi_p, *g_wlo_p, *g_Pthi_p, *g_Ptlo_p;
    if (!init) {
        cudaGetSymbolAddress((void**)&g_whi_p,   g_whi);
        cudaGetSymbolAddress((void**)&g_wlo_p,   g_wlo);
        cudaGetSymbolAddress((void**)&g_Pthi_p,  g_Pthi);
        cudaGetSymbolAddress((void**)&g_Ptlo_p,  g_Ptlo);
        cudaFuncSetAttribute(k_gemm_ts, cudaFuncAttributeMaxDynamicSharedMemorySize, GK_SMEM);
        cudaFuncSetAttribute(k_pool, cudaFuncAttributeMaxDynamicSharedMemorySize, SMEM_POOL);
        cudaFuncSetAttribute(k_st,   cudaFuncAttributeMaxDynamicSharedMemorySize, SMEM_ST);
        cudaFuncSetAttribute(k_attn, cudaFuncAttributeMaxDynamicSharedMemorySize, SMEM_ATTN);
        cudaFuncSetAttribute(k_P,    cudaFuncAttributeMaxDynamicSharedMemorySize, SMEM_P);
        init = true;
    }

    // 0) x split + prep (zero px/nrm + W_comb)
    k_split_x<<<(BNTOK * 256 / 4) / 256, 256>>>(x);
    k_prep<<<641, 256>>>(Wx, Wsl, bx, bsl);

    // 1) fused logits/softmax/pool-x (tensor cores, 2 CTA/SM)
    k_pool<<<dim3(H_, N_/TOK, B_), 256, SMEM_POOL>>>(temp);

    // 2) st = px @ W_fx + nrm*b_fx (d-split x4)
    k_st<<<dim3(H_, B_, 4), 256, SMEM_ST>>>(Wfx, bfx);

    // 3) tiny attention over slice tokens
    k_attn<<<dim3(H_, B_), 256, SMEM_ATTN>>>(Wq, Wk, Wv);

    // 4) P precompute (transposed + split)
    k_P<<<dim3(H_, B_), 256, SMEM_P>>>(Wout);

    // 5) output GEMM (tensor cores, 3-pass)
    k_gemm_ts<<<dim3(2, BNTOK/128), 256, GK_SMEM>>>(
        g_whi_p, g_wlo_p, g_Pthi_p, g_Ptlo_p, 512, bout, out, 256);
}

// round 15
// speedup vs baseline: 1.3805x; 1.0396x over previous
#include <cuda_runtime.h>
#include <cuda_bf16.h>
#include <cstdint>
#include <math.h>

#define B_      4
#define N_      32768
#define C_      256
#define H_      8
#define D_      64
#define G_      64
#define INNER_  512
#define BNTOK   (B_*N_)          // 131072

// single dynamic smem symbol shared by all kernels
extern __shared__ char smem_dyn[];

// ---------------- scratch (device globals; allocation-free) ----------------
__device__ __nv_bfloat16 g_xhi[(size_t)BNTOK * 256];
__device__ __nv_bfloat16 g_xlo[(size_t)BNTOK * 256];
__device__ __nv_bfloat16 g_Wc[H_ * 64 * 256];        // combined W_x@Ws, [h][g][c]
__device__ float g_bcomb[H_ * 64];
__device__ __nv_bfloat16 g_whi[(size_t)BNTOK * 512]; // slice weights hi
__device__ __nv_bfloat16 g_wlo[(size_t)BNTOK * 512];
__device__ __nv_bfloat16 g_Pthi[B_ * C_ * INNER_];
__device__ __nv_bfloat16 g_Ptlo[B_ * C_ * INNER_];
__device__ float g_px [B_*H_*G_*C_];                 // pooled x: [bh][g][c], 2MB
__device__ float g_st [B_*H_*G_*D_];
__device__ float g_nrm[B_*H_*G_];

// ---------------- helpers ----------------
__device__ __forceinline__ uint32_t smem_to_u32(const void* p) {
    uint32_t a;
    asm("{ .reg .u64 t; cvta.to.shared.u64 t, %1; cvt.u32.u64 %0, t; }" : "=r"(a) : "l"(p));
    return a;
}
__device__ __forceinline__ void ldsm4(uint32_t &r0, uint32_t &r1, uint32_t &r2, uint32_t &r3,
                                      uint32_t addr) {
    asm volatile("ldmatrix.sync.aligned.m8n8.x4.shared.b16 {%0,%1,%2,%3}, [%4];"
        : "=r"(r0), "=r"(r1), "=r"(r2), "=r"(r3) : "r"(addr));
}
__device__ __forceinline__ void ldsm4t(uint32_t &r0, uint32_t &r1, uint32_t &r2, uint32_t &r3,
                                       uint32_t addr) {
    asm volatile("ldmatrix.sync.aligned.m8n8.x4.trans.shared.b16 {%0,%1,%2,%3}, [%4];"
        : "=r"(r0), "=r"(r1), "=r"(r2), "=r"(r3) : "r"(addr));
}
__device__ __forceinline__ void mma16816(float* c,
                                         uint32_t a0, uint32_t a1, uint32_t a2, uint32_t a3,
                                         uint32_t b0, uint32_t b1) {
    asm volatile(
        "mma.sync.aligned.m16n8k16.row.col.f32.bf16.bf16.f32 "
        "{%0,%1,%2,%3}, {%4,%5,%6,%7}, {%8,%9}, {%0,%1,%2,%3};"
        : "+f"(c[0]), "+f"(c[1]), "+f"(c[2]), "+f"(c[3])
        : "r"(a0), "r"(a1), "r"(a2), "r"(a3), "r"(b0), "r"(b1));
}
__device__ __forceinline__ void split_one(float a, __nv_bfloat16 &hi, __nv_bfloat16 &lo) {
    hi = __float2bfloat16(a);
    lo = __float2bfloat16(a - __bfloat162float(hi));
}
__device__ __forceinline__ void split_pair(float a, float b, unsigned &hi, unsigned &lo) {
    __nv_bfloat16 ah, al, bh, bl;
    split_one(a, ah, al);
    split_one(b, bh, bl);
    hi = ((unsigned)__bfloat16_as_ushort(bh) << 16) | (unsigned)__bfloat16_as_ushort(ah);
    lo = ((unsigned)__bfloat16_as_ushort(bl) << 16) | (unsigned)__bfloat16_as_ushort(al);
}
#define CP_ASYNC16(dst, src) \
    asm volatile("cp.async.cg.shared.global [%0], [%1], 16;" :: "r"(dst), "l"(src))
#define CP_COMMIT()  asm volatile("cp.async.commit_group;")
#define CP_WAIT0()   asm volatile("cp.async.wait_group 0;")
#define RED_ADD_V2(ptr, v0, v1) \
    asm volatile("red.global.add.v2.f32 [%0], {%1,%2};" \
        :: "l"(ptr), "f"(v0), "f"(v1) : "memory")

// ---------------- K_sx: split x into bf16 hi/lo ----------------
__global__ void __launch_bounds__(256) k_split_x(const float* __restrict__ x) {
    size_t i = (size_t)blockIdx.x * 256 + threadIdx.x;
    float4 v = *(const float4*)(x + i * 4);
    unsigned h0, l0, h1, l1;
    split_pair(v.x, v.y, h0, l0);
    split_pair(v.z, v.w, h1, l1);
    *(uint2*)&g_xhi[i * 4] = make_uint2(h0, h1);
    *(uint2*)&g_xlo[i * 4] = make_uint2(l0, l1);
}

// ---------------- K_prep: fused zero(px, nrm) + comb ----------------
__global__ void __launch_bounds__(256) k_prep(
    const float* __restrict__ Wx, const float* __restrict__ Wsl,
    const float* __restrict__ bx, const float* __restrict__ bsl)
{
    __shared__ float sws[64*64];
    const int bid = blockIdx.x;
    const int tid = threadIdx.x;

    if (bid < 512) {
        ((float4*)g_px)[bid * 256 + tid] = make_float4(0.f, 0.f, 0.f, 0.f);
        return;
    }
    if (bid == 512) {
        ((float4*)g_nrm)[tid]       = make_float4(0.f, 0.f, 0.f, 0.f);
        ((float4*)g_nrm)[tid + 256] = make_float4(0.f, 0.f, 0.f, 0.f);
        return;
    }
    const int r  = bid - 513;
    const int h  = r & 7;
    const int cb = r >> 3;
    for (int i = tid; i < 4096; i += 256) sws[i] = Wsl[i];
    __syncthreads();
    const int g = tid & 63, cq = tid >> 6;
#pragma unroll
    for (int cc = 0; cc < 4; cc++) {
        int c = cb * 16 + cq * 4 + cc;
        float s = 0.f;
        const float* wxr = &Wx[(size_t)c * 512 + h * 64];
#pragma unroll 16
        for (int d = 0; d < 64; d++) s += wxr[d] * sws[d*64 + g];
        g_Wc[(h*64 + g)*256 + c] = __float2bfloat16(s);
    }
    if (cb == 0 && tid < 64) {
        float s = bsl[tid];
        for (int d = 0; d < 64; d++) s += bx[h*64 + d] * sws[d*64 + tid];
        g_bcomb[h*64 + tid] = s;
    }
}

// ================= split-bf16 tensor-core GEMM (output GEMM only) =================
#define GK_ROWB 80
#define GK_ARR  (128 * GK_ROWB)
#define GK_STG  (4 * GK_ARR)
#define GK_SMEM (2 * GK_STG)

__global__ void __launch_bounds__(256, 2) k_gemm_ts(
    const __nv_bfloat16* __restrict__ Ahi, const __nv_bfloat16* __restrict__ Alo,
    const __nv_bfloat16* __restrict__ Bhi, const __nv_bfloat16* __restrict__ Blo,
    int K,
    const float* __restrict__ bias,
    float* __restrict__ OutF, int ldc)
{
    char* sm = smem_dyn;
    const uint32_t sbase = smem_to_u32(sm);

    const int tid  = threadIdx.x;
    const int wid  = tid >> 5;
    const int lane = tid & 31;
    const int wm   = wid >> 2;
    const int wn   = wid & 3;
    const int m0   = blockIdx.y * 128;
    const int n0   = blockIdx.x * 128;

    const __nv_bfloat16* srcs[4];
    srcs[0] = Ahi + (size_t)m0 * K;
    srcs[1] = Alo + (size_t)m0 * K;
    size_t boff = (size_t)(m0 >> 15) * 256 * INNER_ + (size_t)n0 * K;
    srcs[2] = Bhi + boff;
    srcs[3] = Blo + boff;

    const int srow0 = tid >> 2,         sq0 = tid & 3;
    const int srow1 = (tid + 256) >> 2, sq1 = (tid + 256) & 3;

    float acc[4][4][4];
#pragma unroll
    for (int i = 0; i < 4; i++)
#pragma unroll
        for (int j = 0; j < 4; j++)
#pragma unroll
            for (int e = 0; e < 4; e++) acc[i][j][e] = 0.f;

    const int lrow = lane & 15;
    const int lkq  = (lane >> 4) << 3;
    const int nch  = K >> 5;

#pragma unroll
    for (int arr = 0; arr < 4; arr++) {
        const __nv_bfloat16* s = srcs[arr];
        uint32_t d = sbase + arr * GK_ARR;
        CP_ASYNC16(d + srow0 * GK_ROWB + sq0 * 16, s + (size_t)srow0 * K + sq0 * 8);
        CP_ASYNC16(d + srow1 * GK_ROWB + sq1 * 16, s + (size_t)srow1 * K + sq1 * 8);
    }
    CP_COMMIT();

    for (int ch = 0; ch < nch; ch++) {
        CP_WAIT0();
        __syncthreads();
        if (ch + 1 < nch) {
            const int k1 = (ch + 1) << 5;
            const uint32_t stg = sbase + ((ch + 1) & 1) * GK_STG;
#pragma unroll
            for (int arr = 0; arr < 4; arr++) {
                const __nv_bfloat16* s = srcs[arr] + k1;
                uint32_t d = stg + arr * GK_ARR;
                CP_ASYNC16(d + srow0 * GK_ROWB + sq0 * 16, s + (size_t)srow0 * K + sq0 * 8);
                CP_ASYNC16(d + srow1 * GK_ROWB + sq1 * 16, s + (size_t)srow1 * K + sq1 * 8);
            }
            CP_COMMIT();
        }

        const uint32_t stg  = sbase + (ch & 1) * GK_STG;
        const uint32_t sahi = stg, salo = stg + GK_ARR;
        const uint32_t sbhi = stg + 2 * GK_ARR, sblo = stg + 3 * GK_ARR;

#pragma unroll
        for (int ks = 0; ks < 2; ks++) {
            const int khb = (ks * 16 + lkq) * 2;
            uint32_t a[4][4], bh[8], bl[8];
#pragma unroll
            for (int i = 0; i < 4; i++) {
                int row = wm * 64 + i * 16 + lrow;
                ldsm4(a[i][0], a[i][1], a[i][2], a[i][3], sahi + row * GK_ROWB + khb);
            }
#pragma unroll
            for (int jp = 0; jp < 2; jp++) {
                int row = wn * 32 + jp * 16 + lrow;
                ldsm4(bh[jp*4+0], bh[jp*4+1], bh[jp*4+2], bh[jp*4+3],
                      sbhi + row * GK_ROWB + khb);
            }
#pragma unroll
            for (int i = 0; i < 4; i++) {
                mma16816(acc[i][0], a[i][0], a[i][1], a[i][2], a[i][3], bh[0], bh[2]);
                mma16816(acc[i][1], a[i][0], a[i][1], a[i][2], a[i][3], bh[1], bh[3]);
                mma16816(acc[i][2], a[i][0], a[i][1], a[i][2], a[i][3], bh[4], bh[6]);
                mma16816(acc[i][3], a[i][0], a[i][1], a[i][2], a[i][3], bh[5], bh[7]);
            }
#pragma unroll
            for (int jp = 0; jp < 2; jp++) {
                int row = wn * 32 + jp * 16 + lrow;
                ldsm4(bl[jp*4+0], bl[jp*4+1], bl[jp*4+2], bl[jp*4+3],
                      sblo + row * GK_ROWB + khb);
            }
#pragma unroll
            for (int i = 0; i < 4; i++) {
                mma16816(acc[i][0], a[i][0], a[i][1], a[i][2], a[i][3], bl[0], bl[2]);
                mma16816(acc[i][1], a[i][0], a[i][1], a[i][2], a[i][3], bl[1], bl[3]);
                mma16816(acc[i][2], a[i][0], a[i][1], a[i][2], a[i][3], bl[4], bl[6]);
                mma16816(acc[i][3], a[i][0], a[i][1], a[i][2], a[i][3], bl[5], bl[7]);
            }
#pragma unroll
            for (int i = 0; i < 4; i++) {
                int row = wm * 64 + i * 16 + lrow;
                ldsm4(a[i][0], a[i][1], a[i][2], a[i][3], salo + row * GK_ROWB + khb);
            }
#pragma unroll
            for (int i = 0; i < 4; i++) {
                mma16816(acc[i][0], a[i][0], a[i][1], a[i][2], a[i][3], bh[0], bh[2]);
                mma16816(acc[i][1], a[i][0], a[i][1], a[i][2], a[i][3], bh[1], bh[3]);
                mma16816(acc[i][2], a[i][0], a[i][1], a[i][2], a[i][3], bh[4], bh[6]);
                mma16816(acc[i][3], a[i][0], a[i][1], a[i][2], a[i][3], bh[5], bh[7]);
            }
        }
    }

    const int r0 = lane >> 2;
    const int c0 = (lane & 3) * 2;
#pragma unroll
    for (int j = 0; j < 4; j++) {
        const int col = n0 + wn * 32 + j * 8 + c0;
        const float2 bi = *(const float2*)&bias[col];
#pragma unroll
        for (int i = 0; i < 4; i++) {
            const int row = m0 + wm * 64 + i * 16 + r0;
            float2 o0 = {acc[i][j][0] + bi.x, acc[i][j][1] + bi.y};
            float2 o1 = {acc[i][j][2] + bi.x, acc[i][j][3] + bi.y};
            *(float2*)&OutF[(size_t)row * ldc + col] = o0;
            *(float2*)&OutF[(size_t)(row + 8) * ldc + col] = o1;
        }
    }
}

// ================= K_B: fused logits+softmax+pool-x (2 CTA/SM) =================
#define TOK 256
#define PWTH  0          // 256x144 : phase1 x buf A / w hi [t][g]
#define PWTL  36864      //          : phase1 x buf B / w lo
#define PWC   73728      // Wc (phase1 only)
#define XS0H  73728      // phase2 x slice buffers (overlay PWC)
#define XS0L  82944
#define XS1H  92160
#define XS1L  101376
#define PBSL  110592
#define PNRM  110848
#define SMEM_POOL 112128

__global__ void __launch_bounds__(256, 2) k_pool(const float* __restrict__ temperature)
{
    char* sm = smem_dyn;
    const uint32_t sbase = smem_to_u32(sm);
    float* bslf = (float*)(sm + PBSL);
    float* nrmp = (float*)(sm + PNRM);

    const int h  = blockIdx.x;
    const int tb = blockIdx.y;
    const int b  = blockIdx.z;
    const int tid = threadIdx.x;
    const int wid = tid >> 5;
    const int lane = tid & 31;
    const int m0  = b * N_ + tb * TOK;
    const int lrow = lane & 15;
    const int lkq  = (lane >> 4) << 3;

    // prologue: Wc -> PWC, x chunk0 -> PWTH region
#pragma unroll
    for (int it = 0; it < 8; it++) {
        int i = tid + it * 256;
        int r = i >> 5, q = i & 31;
        CP_ASYNC16(sbase + PWC + r*528 + q*16, &g_Wc[(size_t)(h*64 + r)*256 + q*8]);
    }
#pragma unroll
    for (int it = 0; it < 8; it++) {
        int i = tid + it * 256;
        int r = i >> 3, q = i & 7;
        CP_ASYNC16(sbase + PWTH + r*144 + q*16, &g_xhi[(size_t)(m0+r)*256 + q*8]);
    }
    CP_COMMIT();
    if (tid < 64) bslf[tid] = g_bcomb[h*64 + tid];

    // ---- phase 1 MMA (1-pass), K=256 in 4 chunks ----
    float acc[2][8][4];
#pragma unroll
    for (int i = 0; i < 2; i++)
#pragma unroll
        for (int j = 0; j < 8; j++)
#pragma unroll
            for (int e = 0; e < 4; e++) acc[i][j][e] = 0.f;

#pragma unroll
    for (int kc = 0; kc < 4; kc++) {
        CP_WAIT0();
        __syncthreads();
        if (kc + 1 < 4) {
            const uint32_t dstb = sbase + (((kc + 1) & 1) ? PWTL : PWTH);
#pragma unroll
            for (int it = 0; it < 8; it++) {
                int i = tid + it * 256;
                int r = i >> 3, q = i & 7;
                CP_ASYNC16(dstb + r*144 + q*16,
                           &g_xhi[(size_t)(m0+r)*256 + (kc+1)*64 + q*8]);
            }
            CP_COMMIT();
        }
        const uint32_t abuf = sbase + ((kc & 1) ? PWTL : PWTH);
#pragma unroll
        for (int ks = 0; ks < 4; ks++) {
            const int khA = (ks * 16 + lkq) * 2;
            const int khB = (kc * 64 + ks * 16 + lkq) * 2;
            uint32_t a[2][4], bh[16];
#pragma unroll
            for (int i = 0; i < 2; i++) {
                int row = wid * 32 + i * 16 + lrow;
                ldsm4(a[i][0], a[i][1], a[i][2], a[i][3], abuf + row*144 + khA);
            }
#pragma unroll
            for (int jp = 0; jp < 4; jp++) {
                int row = jp * 16 + lrow;
                ldsm4(bh[jp*4+0], bh[jp*4+1], bh[jp*4+2], bh[jp*4+3],
                      sbase + PWC + row*528 + khB);
            }
#pragma unroll
            for (int i = 0; i < 2; i++)
#pragma unroll
                for (int jj = 0; jj < 8; jj++) {
                    int jp = jj >> 1, o = jj & 1;
                    mma16816(acc[i][jj], a[i][0], a[i][1], a[i][2], a[i][3],
                             bh[jp*4+o], bh[jp*4+o+2]);   // non-trans pairing
                }
        }
    }
    __syncthreads();   // PWTH/PWTL/PWC regions free now

    // kick (cq=0, ts=0) x slice into XS0 (overlaps softmax + w writes)
#pragma unroll
    for (int it = 0; it < 2; it++) {
        int i = tid + it * 256;
        int r = i >> 3, q = i & 7;
        CP_ASYNC16(sbase + XS0H + r*144 + q*16, &g_xhi[(size_t)(m0 + r)*256 + q*8]);
        CP_ASYNC16(sbase + XS0L + r*144 + q*16, &g_xlo[(size_t)(m0 + r)*256 + q*8]);
    }
    CP_COMMIT();

    // ---- softmax over g ----
    float tmp = temperature[h];
    tmp = fminf(fmaxf(tmp, 0.1f), 5.0f);
    const float itemp = 1.0f / tmp;

#pragma unroll
    for (int i = 0; i < 2; i++)
#pragma unroll
        for (int j = 0; j < 8; j++) {
            float2 bi = *(float2*)&bslf[j*8 + (lane & 3)*2];
            acc[i][j][0] = (acc[i][j][0] + bi.x) * itemp;
            acc[i][j][1] = (acc[i][j][1] + bi.y) * itemp;
            acc[i][j][2] = (acc[i][j][2] + bi.x) * itemp;
            acc[i][j][3] = (acc[i][j][3] + bi.y) * itemp;
        }
    float inv0[2], inv1[2];
#pragma unroll
    for (int i = 0; i < 2; i++) {
        float m0v = -1e30f, m1v = -1e30f;
#pragma unroll
        for (int j = 0; j < 8; j++) {
            m0v = fmaxf(m0v, fmaxf(acc[i][j][0], acc[i][j][1]));
            m1v = fmaxf(m1v, fmaxf(acc[i][j][2], acc[i][j][3]));
        }
        m0v = fmaxf(m0v, __shfl_xor_sync(0xffffffff, m0v, 1));
        m0v = fmaxf(m0v, __shfl_xor_sync(0xffffffff, m0v, 2));
        m1v = fmaxf(m1v, __shfl_xor_sync(0xffffffff, m1v, 1));
        m1v = fmaxf(m1v, __shfl_xor_sync(0xffffffff, m1v, 2));
        float s0 = 0.f, s1 = 0.f;
#pragma unroll
        for (int j = 0; j < 8; j++) {
            acc[i][j][0] = __expf(acc[i][j][0] - m0v);
            acc[i][j][1] = __expf(acc[i][j][1] - m0v);
            acc[i][j][2] = __expf(acc[i][j][2] - m1v);
            acc[i][j][3] = __expf(acc[i][j][3] - m1v);
            s0 += acc[i][j][0] + acc[i][j][1];
            s1 += acc[i][j][2] + acc[i][j][3];
        }
        s0 += __shfl_xor_sync(0xffffffff, s0, 1);
        s0 += __shfl_xor_sync(0xffffffff, s0, 2);
        s1 += __shfl_xor_sync(0xffffffff, s1, 1);
        s1 += __shfl_xor_sync(0xffffffff, s1, 2);
        inv0[i] = 1.0f / s0;
        inv1[i] = 1.0f / s1;
    }

    // ---- write w fragments to [t][g] smem only (packed 4B) ----
    {
        const int r = lane >> 2;
#pragma unroll
        for (int i = 0; i < 2; i++) {
            int t0 = wid * 32 + i * 16 + r;
            int t1 = t0 + 8;
#pragma unroll
            for (int j = 0; j < 8; j++) {
                int c = j * 8 + (lane & 3) * 2;
                float w00 = acc[i][j][0] * inv0[i], w01 = acc[i][j][1] * inv0[i];
                float w10 = acc[i][j][2] * inv1[i], w11 = acc[i][j][3] * inv1[i];
                unsigned h0, l0, h1, l1;
                split_pair(w00, w01, h0, l0);
                split_pair(w10, w11, h1, l1);
                *(unsigned*)(sm + PWTH + t0*144 + c*2) = h0;
                *(unsigned*)(sm + PWTL + t0*144 + c*2) = l0;
                *(unsigned*)(sm + PWTH + t1*144 + c*2) = h1;
                *(unsigned*)(sm + PWTL + t1*144 + c*2) = l1;
            }
        }
    }
    __syncthreads();

    // ---- coalesced w gmem commit (uint4 from smem, 16B coalesced stores) ----
#pragma unroll
    for (int it = 0; it < 8; it++) {
        int i = tid + it * 256;          // 2048 tasks
        int r = i >> 3, q = i & 7;
        uint4 vh = *(uint4*)(sm + PWTH + r*144 + q*16);
        uint4 vl = *(uint4*)(sm + PWTL + r*144 + q*16);
        *(uint4*)&g_whi[(size_t)(m0 + r)*512 + h*64 + q*8] = vh;
        *(uint4*)&g_wlo[(size_t)(m0 + r)*512 + h*64 + q*8] = vl;
    }

    // ---- norm partial sums ----
    {
        int g = tid & 63, q = tid >> 6;
        float s = 0.f;
#pragma unroll 8
        for (int t = q*64; t < q*64 + 64; t++) {
            s += __bfloat162float(*(__nv_bfloat16*)(sm + PWTH + t*144 + g*2));
            s += __bfloat162float(*(__nv_bfloat16*)(sm + PWTL + t*144 + g*2));
        }
        nrmp[q*64 + g] = s;
    }
    __syncthreads();
    if (tid < 64) {
        float s = nrmp[tid] + nrmp[64+tid] + nrmp[128+tid] + nrmp[192+tid];
        atomicAdd(&g_nrm[(b*8 + h)*64 + tid], s);
    }

    // ---- phase 2: 16 (cq,ts) tiles; warp tile 32g x 16c; flush per cq ----
    const int wm2 = wid >> 2;
    const int wn2 = wid & 3;
    const int trowA = (lane & 7) | ((lane >> 1) & 8);
    const int gselA = (lane & 8) * 2;
    const int base = (b*8 + h) * 64;
    const int rr = lane >> 2;
    const int cc2 = (lane & 3) * 2;

    float ac2[2][2][4];
#pragma unroll
    for (int i = 0; i < 2; i++)
#pragma unroll
        for (int j = 0; j < 2; j++)
#pragma unroll
            for (int e = 0; e < 4; e++) ac2[i][j][e] = 0.f;

    for (int qq = 0; qq < 16; qq++) {
        const int cq = qq >> 2, ts = qq & 3;
        CP_WAIT0();
        __syncthreads();
        if (qq + 1 < 16) {
            const int ncq = (qq + 1) >> 2, nts = (qq + 1) & 3;
            const uint32_t dh = sbase + (((qq + 1) & 1) ? XS1H : XS0H);
            const uint32_t dl = sbase + (((qq + 1) & 1) ? XS1L : XS0L);
#pragma unroll
            for (int it = 0; it < 2; it++) {
                int i = tid + it * 256;
                int r = i >> 3, q = i & 7;
                size_t src = (size_t)(m0 + nts*64 + r)*256 + ncq*64 + q*8;
                CP_ASYNC16(dh + r*144 + q*16, &g_xhi[src]);
                CP_ASYNC16(dl + r*144 + q*16, &g_xlo[src]);
            }
            CP_COMMIT();
        }
        const uint32_t sh = sbase + ((qq & 1) ? XS1H : XS0H);
        const uint32_t sl = sbase + ((qq & 1) ? XS1L : XS0L);
        const int tbs = ts * 64;

#pragma unroll
        for (int ks = 0; ks < 4; ks++) {
            uint32_t a[2][4], bh[4], bl[4];
#pragma unroll
            for (int i = 0; i < 2; i++) {
                uint32_t addr = sbase + PWTH + (tbs + ks*16 + trowA)*144
                              + (wm2*32 + i*16)*2 + gselA;
                ldsm4t(a[i][0], a[i][1], a[i][2], a[i][3], addr);
            }
            {
                uint32_t addr = sh + (ks*16 + lrow)*144 + (wn2*16 + lkq)*2;
                ldsm4t(bh[0], bh[1], bh[2], bh[3], addr);
            }
#pragma unroll
            for (int i = 0; i < 2; i++) {              // hh
                mma16816(ac2[i][0], a[i][0], a[i][1], a[i][2], a[i][3], bh[0], bh[1]);
                mma16816(ac2[i][1], a[i][0], a[i][1], a[i][2], a[i][3], bh[2], bh[3]);
            }
            {
                uint32_t addr = sl + (ks*16 + lrow)*144 + (wn2*16 + lkq)*2;
                ldsm4t(bl[0], bl[1], bl[2], bl[3], addr);
            }
#pragma unroll
            for (int i = 0; i < 2; i++) {              // hl
                mma16816(ac2[i][0], a[i][0], a[i][1], a[i][2], a[i][3], bl[0], bl[1]);
                mma16816(ac2[i][1], a[i][0], a[i][1], a[i][2], a[i][3], bl[2], bl[3]);
            }
#pragma unroll
            for (int i = 0; i < 2; i++) {
                uint32_t addr = sbase + PWTL + (tbs + ks*16 + trowA)*144
                              + (wm2*32 + i*16)*2 + gselA;
                ldsm4t(a[i][0], a[i][1], a[i][2], a[i][3], addr);
            }
#pragma unroll
            for (int i = 0; i < 2; i++) {              // lh
                mma16816(ac2[i][0], a[i][0], a[i][1], a[i][2], a[i][3], bh[0], bh[1]);
                mma16816(ac2[i][1], a[i][0], a[i][1], a[i][2], a[i][3], bh[2], bh[3]);
            }
        }

        if (ts == 3) {   // flush this c-quarter, zero acc
#pragma unroll
            for (int i = 0; i < 2; i++) {
                int g0r = wm2 * 32 + i * 16 + rr;
#pragma unroll
                for (int j = 0; j < 2; j++) {
                    int col = cq * 64 + wn2 * 16 + j * 8 + cc2;
                    RED_ADD_V2(&g_px[(size_t)(base + g0r)*256 + col],
                               ac2[i][j][0], ac2[i][j][1]);
                    RED_ADD_V2(&g_px[(size_t)(base + g0r + 8)*256 + col],
                               ac2[i][j][2], ac2[i][j][3]);
#pragma unroll
                    for (int e = 0; e < 4; e++) ac2[i][j][e] = 0.f;
                }
            }
        }
    }
}

// ---------------- K_st: st = px @ W_fx + nrm * b_fx (d-split x4) ----------------
#define SMEM_ST (64*260*4 + 256*20*4)
__global__ void __launch_bounds__(256) k_st(
    const float* __restrict__ Wfx, const float* __restrict__ bfx)
{
    float* spx = (float*)smem_dyn;              // [64][260]
    float* sw  = (float*)smem_dyn + 64*260;     // [256][20]
    const int h = blockIdx.x, b = blockIdx.y, z = blockIdx.z;
    const int tid = threadIdx.x;
    const int bh = b*8 + h;

#pragma unroll
    for (int it = 0; it < 16; it++) {
        int i = tid + it * 256;
        int r = i >> 6, c4 = i & 63;
        *(float4*)&spx[r*260 + c4*4] = *(const float4*)&g_px[(size_t)(bh*64 + r)*256 + c4*4];
    }
#pragma unroll
    for (int it = 0; it < 4; it++) {
        int i = tid + it * 256;
        int r = i >> 2, cq = i & 3;
        *(float4*)&sw[r*20 + cq*4] = *(const float4*)&Wfx[(size_t)r*512 + h*64 + z*16 + cq*4];
    }
    __syncthreads();

    const int g    = tid >> 2;
    const int dsub = (tid & 3) * 4;
    const float nv = g_nrm[bh*64 + g];
    float a4[4];
#pragma unroll
    for (int j = 0; j < 4; j++) a4[j] = nv * bfx[h*64 + z*16 + dsub + j];

    for (int c = 0; c < 256; c++) {
        float av = spx[g*260 + c];
        float4 w = *(float4*)&sw[c*20 + dsub];
        a4[0] += av * w.x;
        a4[1] += av * w.y;
        a4[2] += av * w.z;
        a4[3] += av * w.w;
    }
    *(float4*)&g_st[(size_t)(bh*64 + g)*64 + z*16 + dsub] =
        make_float4(a4[0], a4[1], a4[2], a4[3]);
}

// ---------------- K_tail: fused attention + P precompute (grid 8x4) ----------------
#define SMEM_TAIL (5*64*65*4)
__global__ void __launch_bounds__(256) k_tail(
    const float* __restrict__ Wq, const float* __restrict__ Wk,
    const float* __restrict__ Wv, const float* __restrict__ Wout)
{
    float* sm = (float*)smem_dyn;
    float* S  = sm;                    // later: Os (attention output)
    float* Qs = sm + 64*65;
    float* Ks = sm + 2*64*65;
    float* Vs = sm + 3*64*65;
    float* Ps = sm + 4*64*65;
    float* Wsm = Qs;                   // P phase: [64][256] over Qs..Ps

    const int h = blockIdx.x, b = blockIdx.y;
    const int tid = threadIdx.x;
    const int base = (b*8 + h) * 64;
    const int g  = tid >> 2;
    const int qd = (tid & 3) * 16;

    {
        float invn = 1.0f / (g_nrm[base + g] + 1e-5f);
#pragma unroll
        for (int j = 0; j < 16; j += 4) {
            float4 v = *(const float4*)&g_st[(base + g)*64 + qd + j];
            S[g*65 + qd + j]   = v.x * invn;
            S[g*65 + qd + j+1] = v.y * invn;
            S[g*65 + qd + j+2] = v.z * invn;
            S[g*65 + qd + j+3] = v.w * invn;
        }
    }
    __syncthreads();

    {
        float aq[16], ak[16], av[16];
#pragma unroll
        for (int j = 0; j < 16; j++) { aq[j] = 0.f; ak[j] = 0.f; av[j] = 0.f; }
        for (int k = 0; k < 64; k++) {
            float sv = S[g*65 + k];
            const float* wq = &Wq[k*64 + qd];
            const float* wk = &Wk[k*64 + qd];
            const float* wv = &Wv[k*64 + qd];
#pragma unroll
            for (int j = 0; j < 16; j++) {
                aq[j] += sv * wq[j];
                ak[j] += sv * wk[j];
                av[j] += sv * wv[j];
            }
        }
#pragma unroll
        for (int j = 0; j < 16; j++) {
            Qs[g*65 + qd + j] = aq[j];
            Ks[g*65 + qd + j] = ak[j];
            Vs[g*65 + qd + j] = av[j];
        }
    }
    __syncthreads();

    {
        float lg[16];
#pragma unroll
        for (int jj = 0; jj < 16; jj++) {
            int j = qd + jj;
            float dot = 0.f;
#pragma unroll
            for (int d = 0; d < 64; d++) dot += Qs[g*65 + d] * Ks[j*65 + d];
            lg[jj] = dot * 0.125f;
        }
        float mx = -1e30f;
#pragma unroll
        for (int jj = 0; jj < 16; jj++) mx = fmaxf(mx, lg[jj]);
        mx = fmaxf(mx, __shfl_xor_sync(0xffffffff, mx, 1));
        mx = fmaxf(mx, __shfl_xor_sync(0xffffffff, mx, 2));
        float s = 0.f;
#pragma unroll
        for (int jj = 0; jj < 16; jj++) { lg[jj] = __expf(lg[jj] - mx); s += lg[jj]; }
        s += __shfl_xor_sync(0xffffffff, s, 1);
        s += __shfl_xor_sync(0xffffffff, s, 2);
        float inv = 1.0f / s;
#pragma unroll
        for (int jj = 0; jj < 16; jj++) Ps[g*65 + qd + jj] = lg[jj] * inv;
    }
    __syncthreads();

    {
        float o[16];
#pragma unroll
        for (int d = 0; d < 16; d++) o[d] = 0.f;
        for (int j = 0; j < 64; j++) {
            float p = Ps[g*65 + j];
#pragma unroll
            for (int d = 0; d < 16; d++) o[d] += p * Vs[j*65 + qd + d];
        }
#pragma unroll
        for (int d = 0; d < 16; d++)
            S[g*65 + qd + d] = o[d];     // os stays in smem (S repurposed)
    }
    __syncthreads();

    // ---- P phase: load W_out, compute P_t (split bf16) ----
    for (int i = tid; i < 64*64; i += 256) {
        int r = i >> 6, c = i & 63;
        *(float4*)&Wsm[r*256 + c*4] = *(const float4*)&Wout[(size_t)(h*64 + r)*256 + c*4];
    }
    __syncthreads();

    const int gq = tid >> 3;
    const int cq = tid & 7;
    const int g0 = gq * 2;
    const int c0 = cq * 32;

    float acc[2][32];
#pragma unroll
    for (int i = 0; i < 2; i++)
#pragma unroll
        for (int j = 0; j < 32; j++) acc[i][j] = 0.f;

    for (int k = 0; k < 64; k++) {
        float a0 = S[(g0+0)*65 + k];
        float a1 = S[(g0+1)*65 + k];
#pragma unroll
        for (int c4 = 0; c4 < 8; c4++) {
            float4 w = *(float4*)&Wsm[k*256 + c0 + c4*4];
            acc[0][c4*4+0] += a0*w.x; acc[0][c4*4+1] += a0*w.y;
            acc[0][c4*4+2] += a0*w.z; acc[0][c4*4+3] += a0*w.w;
            acc[1][c4*4+0] += a1*w.x; acc[1][c4*4+1] += a1*w.y;
            acc[1][c4*4+2] += a1*w.z; acc[1][c4*4+3] += a1*w.w;
        }
    }
    __nv_bfloat16* Ph = &g_Pthi[(size_t)b * C_ * INNER_];
    __nv_bfloat16* Pl = &g_Ptlo[(size_t)b * C_ * INNER_];
#pragma unroll
    for (int i = 0; i < 2; i++)
#pragma unroll
        for (int c4 = 0; c4 < 8; c4++)
#pragma unroll
            for (int e = 0; e < 4; e++) {
                size_t off = (size_t)(c0 + c4*4 + e) * INNER_ + h*64 + g0 + i;
                __nv_bfloat16 hi, lo;
                split_one(acc[i][c4*4+e], hi, lo);
                Ph[off] = hi;
                Pl[off] = lo;
            }
}

// ---------------- launch ----------------
extern "C" void kernel_launch(void* const* d_in, const int* in_sizes, int n_in,
                              void* d_out, int out_size)
{
    const float* x    = (const float*)d_in[0];
    const float* Wfx  = (const float*)d_in[1];
    const float* bfx  = (const float*)d_in[2];
    const float* Wx   = (const float*)d_in[3];
    const float* bx   = (const float*)d_in[4];
    const float* Wsl  = (const float*)d_in[5];
    const float* bsl  = (const float*)d_in[6];
    const float* temp = (const float*)d_in[7];
    const float* Wq   = (const float*)d_in[8];
    const float* Wk   = (const float*)d_in[9];
    const float* Wv   = (const float*)d_in[10];
    const float* Wout = (const float*)d_in[11];
    const float* bout = (const float*)d_in[12];
    float* out = (float*)d_out;

    static bool init = false;
    static __nv_bfloat16 *g_whi_p, *g_wlo_p, *g_Pthi_p, *g_Ptlo_p;
    if (!init) {
        cudaGetSymbolAddress((void**)&g_whi_p,   g_whi);
        cudaGetSymbolAddress((void**)&g_wlo_p,   g_wlo);
        cudaGetSymbolAddress((void**)&g_Pthi_p,  g_Pthi);
        cudaGetSymbolAddress((void**)&g_Ptlo_p,  g_Ptlo);
        cudaFuncSetAttribute(k_gemm_ts, cudaFuncAttributeMaxDynamicSharedMemorySize, GK_SMEM);
        cudaFuncSetAttribute(k_pool, cudaFuncAttributeMaxDynamicSharedMemorySize, SMEM_POOL);
        cudaFuncSetAttribute(k_st,   cudaFuncAttributeMaxDynamicSharedMemorySize, SMEM_ST);
        cudaFuncSetAttribute(k_tail, cudaFuncAttributeMaxDynamicSharedMemorySize, SMEM_TAIL);
        init = true;
    }

    // 0) x split + prep (zero px/nrm + W_comb)
    k_split_x<<<(BNTOK * 256 / 4) / 256, 256>>>(x);
    k_prep<<<641, 256>>>(Wx, Wsl, bx, bsl);

    // 1) fused logits/softmax/pool-x (tensor cores, 2 CTA/SM)
    k_pool<<<dim3(H_, N_/TOK, B_), 256, SMEM_POOL>>>(temp);

    // 2) st = px @ W_fx + nrm*b_fx (d-split x4)
    k_st<<<dim3(H_, B_, 4), 256, SMEM_ST>>>(Wfx, bfx);

    // 3) fused attention + P precompute
    k_tail<<<dim3(H_, B_), 256, SMEM_TAIL>>>(Wq, Wk, Wv, Wout);

    // 4) output GEMM (tensor cores, 3-pass)
    k_gemm_ts<<<dim3(2, BNTOK/128), 256, GK_SMEM>>>(
        g_whi_p, g_wlo_p, g_Pthi_p, g_Ptlo_p, 512, bout, out, 256);
}

// round 16
// speedup vs baseline: 1.3966x; 1.0116x over previous
#include <cuda_runtime.h>
#include <cuda_bf16.h>
#include <cstdint>
#include <math.h>

#define B_      4
#define N_      32768
#define C_      256
#define H_      8
#define D_      64
#define G_      64
#define INNER_  512
#define BNTOK   (B_*N_)          // 131072

// single dynamic smem symbol shared by all kernels
extern __shared__ char smem_dyn[];

// ---------------- scratch (device globals; allocation-free) ----------------
__device__ __nv_bfloat16 g_xhi[(size_t)BNTOK * 256];
__device__ __nv_bfloat16 g_xlo[(size_t)BNTOK * 256];
__device__ __nv_bfloat16 g_Wc[H_ * 64 * 256];        // combined W_x@Ws, [h][g][c]
__device__ float g_bcomb[H_ * 64];
__device__ __nv_bfloat16 g_whi[(size_t)BNTOK * 512]; // slice weights hi
__device__ __nv_bfloat16 g_wlo[(size_t)BNTOK * 512];
__device__ __nv_bfloat16 g_Pthi[B_ * C_ * INNER_];
__device__ __nv_bfloat16 g_Ptlo[B_ * C_ * INNER_];
__device__ float g_px [B_*H_*G_*C_];                 // pooled x: [bh][g][c], 2MB
__device__ float g_st [B_*H_*G_*D_];
__device__ float g_nrm[B_*H_*G_];

// ---------------- helpers ----------------
__device__ __forceinline__ uint32_t smem_to_u32(const void* p) {
    uint32_t a;
    asm("{ .reg .u64 t; cvta.to.shared.u64 t, %1; cvt.u32.u64 %0, t; }" : "=r"(a) : "l"(p));
    return a;
}
__device__ __forceinline__ void ldsm4(uint32_t &r0, uint32_t &r1, uint32_t &r2, uint32_t &r3,
                                      uint32_t addr) {
    asm volatile("ldmatrix.sync.aligned.m8n8.x4.shared.b16 {%0,%1,%2,%3}, [%4];"
        : "=r"(r0), "=r"(r1), "=r"(r2), "=r"(r3) : "r"(addr));
}
__device__ __forceinline__ void ldsm4t(uint32_t &r0, uint32_t &r1, uint32_t &r2, uint32_t &r3,
                                       uint32_t addr) {
    asm volatile("ldmatrix.sync.aligned.m8n8.x4.trans.shared.b16 {%0,%1,%2,%3}, [%4];"
        : "=r"(r0), "=r"(r1), "=r"(r2), "=r"(r3) : "r"(addr));
}
__device__ __forceinline__ void mma16816(float* c,
                                         uint32_t a0, uint32_t a1, uint32_t a2, uint32_t a3,
                                         uint32_t b0, uint32_t b1) {
    asm volatile(
        "mma.sync.aligned.m16n8k16.row.col.f32.bf16.bf16.f32 "
        "{%0,%1,%2,%3}, {%4,%5,%6,%7}, {%8,%9}, {%0,%1,%2,%3};"
        : "+f"(c[0]), "+f"(c[1]), "+f"(c[2]), "+f"(c[3])
        : "r"(a0), "r"(a1), "r"(a2), "r"(a3), "r"(b0), "r"(b1));
}
__device__ __forceinline__ void split_one(float a, __nv_bfloat16 &hi, __nv_bfloat16 &lo) {
    hi = __float2bfloat16(a);
    lo = __float2bfloat16(a - __bfloat162float(hi));
}
__device__ __forceinline__ void split_pair(float a, float b, unsigned &hi, unsigned &lo) {
    __nv_bfloat16 ah, al, bh, bl;
    split_one(a, ah, al);
    split_one(b, bh, bl);
    hi = ((unsigned)__bfloat16_as_ushort(bh) << 16) | (unsigned)__bfloat16_as_ushort(ah);
    lo = ((unsigned)__bfloat16_as_ushort(bl) << 16) | (unsigned)__bfloat16_as_ushort(al);
}
#define CP_ASYNC16(dst, src) \
    asm volatile("cp.async.cg.shared.global [%0], [%1], 16;" :: "r"(dst), "l"(src))
#define CP_COMMIT()  asm volatile("cp.async.commit_group;")
#define CP_WAIT0()   asm volatile("cp.async.wait_group 0;")
#define RED_ADD_V2(ptr, v0, v1) \
    asm volatile("red.global.add.v2.f32 [%0], {%1,%2};" \
        :: "l"(ptr), "f"(v0), "f"(v1) : "memory")

// ---------------- K_prep: fused split_x + zero(px, nrm) + comb ----------------
// blocks [0,512): zero g_px; 512: zero g_nrm; [513,1025): W_comb (1 dot/thread);
// [1025, 1025+32768): split x
#define PREP_SPLIT0 1025
__global__ void __launch_bounds__(256) k_prep(
    const float* __restrict__ x,
    const float* __restrict__ Wx, const float* __restrict__ Wsl,
    const float* __restrict__ bx, const float* __restrict__ bsl)
{
    __shared__ float sws[64*64];
    const int bid = blockIdx.x;
    const int tid = threadIdx.x;

    if (bid >= PREP_SPLIT0) {
        size_t i = (size_t)(bid - PREP_SPLIT0) * 256 + tid;
        float4 v = *(const float4*)(x + i * 4);
        unsigned h0, l0, h1, l1;
        split_pair(v.x, v.y, h0, l0);
        split_pair(v.z, v.w, h1, l1);
        *(uint2*)&g_xhi[i * 4] = make_uint2(h0, h1);
        *(uint2*)&g_xlo[i * 4] = make_uint2(l0, l1);
        return;
    }
    if (bid < 512) {
        ((float4*)g_px)[bid * 256 + tid] = make_float4(0.f, 0.f, 0.f, 0.f);
        return;
    }
    if (bid == 512) {
        ((float4*)g_nrm)[tid]       = make_float4(0.f, 0.f, 0.f, 0.f);
        ((float4*)g_nrm)[tid + 256] = make_float4(0.f, 0.f, 0.f, 0.f);
        return;
    }
    // comb: r in [0,512): h = r&7, cb = r>>3 (0..63); c = cb*4 + (tid>>6)
    const int r  = bid - 513;
    const int h  = r & 7;
    const int cb = r >> 3;
    for (int i = tid; i < 4096; i += 256) sws[i] = Wsl[i];
    __syncthreads();
    const int g = tid & 63, cq = tid >> 6;
    {
        int c = cb * 4 + cq;
        float s = 0.f;
        const float* wxr = &Wx[(size_t)c * 512 + h * 64];
#pragma unroll 16
        for (int d = 0; d < 64; d++) s += wxr[d] * sws[d*64 + g];
        g_Wc[(h*64 + g)*256 + c] = __float2bfloat16(s);
    }
    if (cb == 0 && tid < 64) {
        float s = bsl[tid];
        for (int d = 0; d < 64; d++) s += bx[h*64 + d] * sws[d*64 + tid];
        g_bcomb[h*64 + tid] = s;
    }
}

// ================= split-bf16 tensor-core GEMM (output GEMM only) =================
#define GK_ROWB 80
#define GK_ARR  (128 * GK_ROWB)
#define GK_STG  (4 * GK_ARR)
#define GK_SMEM (2 * GK_STG)

__global__ void __launch_bounds__(256, 2) k_gemm_ts(
    const __nv_bfloat16* __restrict__ Ahi, const __nv_bfloat16* __restrict__ Alo,
    const __nv_bfloat16* __restrict__ Bhi, const __nv_bfloat16* __restrict__ Blo,
    int K,
    const float* __restrict__ bias,
    float* __restrict__ OutF, int ldc)
{
    char* sm = smem_dyn;
    const uint32_t sbase = smem_to_u32(sm);

    const int tid  = threadIdx.x;
    const int wid  = tid >> 5;
    const int lane = tid & 31;
    const int wm   = wid >> 2;
    const int wn   = wid & 3;
    const int m0   = blockIdx.y * 128;
    const int n0   = blockIdx.x * 128;

    const __nv_bfloat16* srcs[4];
    srcs[0] = Ahi + (size_t)m0 * K;
    srcs[1] = Alo + (size_t)m0 * K;
    size_t boff = (size_t)(m0 >> 15) * 256 * INNER_ + (size_t)n0 * K;
    srcs[2] = Bhi + boff;
    srcs[3] = Blo + boff;

    const int srow0 = tid >> 2,         sq0 = tid & 3;
    const int srow1 = (tid + 256) >> 2, sq1 = (tid + 256) & 3;

    float acc[4][4][4];
#pragma unroll
    for (int i = 0; i < 4; i++)
#pragma unroll
        for (int j = 0; j < 4; j++)
#pragma unroll
            for (int e = 0; e < 4; e++) acc[i][j][e] = 0.f;

    const int lrow = lane & 15;
    const int lkq  = (lane >> 4) << 3;
    const int nch  = K >> 5;

#pragma unroll
    for (int arr = 0; arr < 4; arr++) {
        const __nv_bfloat16* s = srcs[arr];
        uint32_t d = sbase + arr * GK_ARR;
        CP_ASYNC16(d + srow0 * GK_ROWB + sq0 * 16, s + (size_t)srow0 * K + sq0 * 8);
        CP_ASYNC16(d + srow1 * GK_ROWB + sq1 * 16, s + (size_t)srow1 * K + sq1 * 8);
    }
    CP_COMMIT();

    for (int ch = 0; ch < nch; ch++) {
        CP_WAIT0();
        __syncthreads();
        if (ch + 1 < nch) {
            const int k1 = (ch + 1) << 5;
            const uint32_t stg = sbase + ((ch + 1) & 1) * GK_STG;
#pragma unroll
            for (int arr = 0; arr < 4; arr++) {
                const __nv_bfloat16* s = srcs[arr] + k1;
                uint32_t d = stg + arr * GK_ARR;
                CP_ASYNC16(d + srow0 * GK_ROWB + sq0 * 16, s + (size_t)srow0 * K + sq0 * 8);
                CP_ASYNC16(d + srow1 * GK_ROWB + sq1 * 16, s + (size_t)srow1 * K + sq1 * 8);
            }
            CP_COMMIT();
        }

        const uint32_t stg  = sbase + (ch & 1) * GK_STG;
        const uint32_t sahi = stg, salo = stg + GK_ARR;
        const uint32_t sbhi = stg + 2 * GK_ARR, sblo = stg + 3 * GK_ARR;

#pragma unroll
        for (int ks = 0; ks < 2; ks++) {
            const int khb = (ks * 16 + lkq) * 2;
            uint32_t a[4][4], bh[8], bl[8];
#pragma unroll
            for (int i = 0; i < 4; i++) {
                int row = wm * 64 + i * 16 + lrow;
                ldsm4(a[i][0], a[i][1], a[i][2], a[i][3], sahi + row * GK_ROWB + khb);
            }
#pragma unroll
            for (int jp = 0; jp < 2; jp++) {
                int row = wn * 32 + jp * 16 + lrow;
                ldsm4(bh[jp*4+0], bh[jp*4+1], bh[jp*4+2], bh[jp*4+3],
                      sbhi + row * GK_ROWB + khb);
            }
#pragma unroll
            for (int i = 0; i < 4; i++) {
                mma16816(acc[i][0], a[i][0], a[i][1], a[i][2], a[i][3], bh[0], bh[2]);
                mma16816(acc[i][1], a[i][0], a[i][1], a[i][2], a[i][3], bh[1], bh[3]);
                mma16816(acc[i][2], a[i][0], a[i][1], a[i][2], a[i][3], bh[4], bh[6]);
                mma16816(acc[i][3], a[i][0], a[i][1], a[i][2], a[i][3], bh[5], bh[7]);
            }
#pragma unroll
            for (int jp = 0; jp < 2; jp++) {
                int row = wn * 32 + jp * 16 + lrow;
                ldsm4(bl[jp*4+0], bl[jp*4+1], bl[jp*4+2], bl[jp*4+3],
                      sblo + row * GK_ROWB + khb);
            }
#pragma unroll
            for (int i = 0; i < 4; i++) {
                mma16816(acc[i][0], a[i][0], a[i][1], a[i][2], a[i][3], bl[0], bl[2]);
                mma16816(acc[i][1], a[i][0], a[i][1], a[i][2], a[i][3], bl[1], bl[3]);
                mma16816(acc[i][2], a[i][0], a[i][1], a[i][2], a[i][3], bl[4], bl[6]);
                mma16816(acc[i][3], a[i][0], a[i][1], a[i][2], a[i][3], bl[5], bl[7]);
            }
#pragma unroll
            for (int i = 0; i < 4; i++) {
                int row = wm * 64 + i * 16 + lrow;
                ldsm4(a[i][0], a[i][1], a[i][2], a[i][3], salo + row * GK_ROWB + khb);
            }
#pragma unroll
            for (int i = 0; i < 4; i++) {
                mma16816(acc[i][0], a[i][0], a[i][1], a[i][2], a[i][3], bh[0], bh[2]);
                mma16816(acc[i][1], a[i][0], a[i][1], a[i][2], a[i][3], bh[1], bh[3]);
                mma16816(acc[i][2], a[i][0], a[i][1], a[i][2], a[i][3], bh[4], bh[6]);
                mma16816(acc[i][3], a[i][0], a[i][1], a[i][2], a[i][3], bh[5], bh[7]);
            }
        }
    }

    const int r0 = lane >> 2;
    const int c0 = (lane & 3) * 2;
#pragma unroll
    for (int j = 0; j < 4; j++) {
        const int col = n0 + wn * 32 + j * 8 + c0;
        const float2 bi = *(const float2*)&bias[col];
#pragma unroll
        for (int i = 0; i < 4; i++) {
            const int row = m0 + wm * 64 + i * 16 + r0;
            float2 o0 = {acc[i][j][0] + bi.x, acc[i][j][1] + bi.y};
            float2 o1 = {acc[i][j][2] + bi.x, acc[i][j][3] + bi.y};
            *(float2*)&OutF[(size_t)row * ldc + col] = o0;
            *(float2*)&OutF[(size_t)(row + 8) * ldc + col] = o1;
        }
    }
}

// ================= K_B: fused logits+softmax+pool-x (2 CTA/SM) =================
#define TOK 256
#define PWTH  0          // 256x144 : phase1 x buf A / w hi [t][g]
#define PWTL  36864      //          : phase1 x buf B / w lo
#define PWC   73728      // Wc (phase1 only)
#define XS0H  73728      // phase2 x slice buffers (overlay PWC)
#define XS0L  82944
#define XS1H  92160
#define XS1L  101376
#define PBSL  110592
#define PNRM  110848
#define SMEM_POOL 112128

__global__ void __launch_bounds__(256, 2) k_pool(const float* __restrict__ temperature)
{
    char* sm = smem_dyn;
    const uint32_t sbase = smem_to_u32(sm);
    float* bslf = (float*)(sm + PBSL);
    float* nrmp = (float*)(sm + PNRM);

    const int h  = blockIdx.x;
    const int tb = blockIdx.y;
    const int b  = blockIdx.z;
    const int tid = threadIdx.x;
    const int wid = tid >> 5;
    const int lane = tid & 31;
    const int m0  = b * N_ + tb * TOK;
    const int lrow = lane & 15;
    const int lkq  = (lane >> 4) << 3;

    // prologue: Wc -> PWC, x chunk0 -> PWTH region
#pragma unroll
    for (int it = 0; it < 8; it++) {
        int i = tid + it * 256;
        int r = i >> 5, q = i & 31;
        CP_ASYNC16(sbase + PWC + r*528 + q*16, &g_Wc[(size_t)(h*64 + r)*256 + q*8]);
    }
#pragma unroll
    for (int it = 0; it < 8; it++) {
        int i = tid + it * 256;
        int r = i >> 3, q = i & 7;
        CP_ASYNC16(sbase + PWTH + r*144 + q*16, &g_xhi[(size_t)(m0+r)*256 + q*8]);
    }
    CP_COMMIT();
    if (tid < 64) bslf[tid] = g_bcomb[h*64 + tid];

    // ---- phase 1 MMA (1-pass), K=256 in 4 chunks ----
    float acc[2][8][4];
#pragma unroll
    for (int i = 0; i < 2; i++)
#pragma unroll
        for (int j = 0; j < 8; j++)
#pragma unroll
            for (int e = 0; e < 4; e++) acc[i][j][e] = 0.f;

#pragma unroll
    for (int kc = 0; kc < 4; kc++) {
        CP_WAIT0();
        __syncthreads();
        if (kc + 1 < 4) {
            const uint32_t dstb = sbase + (((kc + 1) & 1) ? PWTL : PWTH);
#pragma unroll
            for (int it = 0; it < 8; it++) {
                int i = tid + it * 256;
                int r = i >> 3, q = i & 7;
                CP_ASYNC16(dstb + r*144 + q*16,
                           &g_xhi[(size_t)(m0+r)*256 + (kc+1)*64 + q*8]);
            }
            CP_COMMIT();
        }
        const uint32_t abuf = sbase + ((kc & 1) ? PWTL : PWTH);
#pragma unroll
        for (int ks = 0; ks < 4; ks++) {
            const int khA = (ks * 16 + lkq) * 2;
            const int khB = (kc * 64 + ks * 16 + lkq) * 2;
            uint32_t a[2][4], bh[16];
#pragma unroll
            for (int i = 0; i < 2; i++) {
                int row = wid * 32 + i * 16 + lrow;
                ldsm4(a[i][0], a[i][1], a[i][2], a[i][3], abuf + row*144 + khA);
            }
#pragma unroll
            for (int jp = 0; jp < 4; jp++) {
                int row = jp * 16 + lrow;
                ldsm4(bh[jp*4+0], bh[jp*4+1], bh[jp*4+2], bh[jp*4+3],
                      sbase + PWC + row*528 + khB);
            }
#pragma unroll
            for (int i = 0; i < 2; i++)
#pragma unroll
                for (int jj = 0; jj < 8; jj++) {
                    int jp = jj >> 1, o = jj & 1;
                    mma16816(acc[i][jj], a[i][0], a[i][1], a[i][2], a[i][3],
                             bh[jp*4+o], bh[jp*4+o+2]);   // non-trans pairing
                }
        }
    }
    __syncthreads();   // PWTH/PWTL/PWC regions free now

    // kick (cq=0, ts=0) x slice into XS0 (overlaps softmax + w writes)
#pragma unroll
    for (int it = 0; it < 2; it++) {
        int i = tid + it * 256;
        int r = i >> 3, q = i & 7;
        CP_ASYNC16(sbase + XS0H + r*144 + q*16, &g_xhi[(size_t)(m0 + r)*256 + q*8]);
        CP_ASYNC16(sbase + XS0L + r*144 + q*16, &g_xlo[(size_t)(m0 + r)*256 + q*8]);
    }
    CP_COMMIT();

    // ---- softmax over g ----
    float tmp = temperature[h];
    tmp = fminf(fmaxf(tmp, 0.1f), 5.0f);
    const float itemp = 1.0f / tmp;

#pragma unroll
    for (int i = 0; i < 2; i++)
#pragma unroll
        for (int j = 0; j < 8; j++) {
            float2 bi = *(float2*)&bslf[j*8 + (lane & 3)*2];
            acc[i][j][0] = (acc[i][j][0] + bi.x) * itemp;
            acc[i][j][1] = (acc[i][j][1] + bi.y) * itemp;
            acc[i][j][2] = (acc[i][j][2] + bi.x) * itemp;
            acc[i][j][3] = (acc[i][j][3] + bi.y) * itemp;
        }
    float inv0[2], inv1[2];
#pragma unroll
    for (int i = 0; i < 2; i++) {
        float m0v = -1e30f, m1v = -1e30f;
#pragma unroll
        for (int j = 0; j < 8; j++) {
            m0v = fmaxf(m0v, fmaxf(acc[i][j][0], acc[i][j][1]));
            m1v = fmaxf(m1v, fmaxf(acc[i][j][2], acc[i][j][3]));
        }
        m0v = fmaxf(m0v, __shfl_xor_sync(0xffffffff, m0v, 1));
        m0v = fmaxf(m0v, __shfl_xor_sync(0xffffffff, m0v, 2));
        m1v = fmaxf(m1v, __shfl_xor_sync(0xffffffff, m1v, 1));
        m1v = fmaxf(m1v, __shfl_xor_sync(0xffffffff, m1v, 2));
        float s0 = 0.f, s1 = 0.f;
#pragma unroll
        for (int j = 0; j < 8; j++) {
            acc[i][j][0] = __expf(acc[i][j][0] - m0v);
            acc[i][j][1] = __expf(acc[i][j][1] - m0v);
            acc[i][j][2] = __expf(acc[i][j][2] - m1v);
            acc[i][j][3] = __expf(acc[i][j][3] - m1v);
            s0 += acc[i][j][0] + acc[i][j][1];
            s1 += acc[i][j][2] + acc[i][j][3];
        }
        s0 += __shfl_xor_sync(0xffffffff, s0, 1);
        s0 += __shfl_xor_sync(0xffffffff, s0, 2);
        s1 += __shfl_xor_sync(0xffffffff, s1, 1);
        s1 += __shfl_xor_sync(0xffffffff, s1, 2);
        inv0[i] = 1.0f / s0;
        inv1[i] = 1.0f / s1;
    }

    // ---- write w fragments to [t][g] smem only (packed 4B) ----
    {
        const int r = lane >> 2;
#pragma unroll
        for (int i = 0; i < 2; i++) {
            int t0 = wid * 32 + i * 16 + r;
            int t1 = t0 + 8;
#pragma unroll
            for (int j = 0; j < 8; j++) {
                int c = j * 8 + (lane & 3) * 2;
                float w00 = acc[i][j][0] * inv0[i], w01 = acc[i][j][1] * inv0[i];
                float w10 = acc[i][j][2] * inv1[i], w11 = acc[i][j][3] * inv1[i];
                unsigned h0, l0, h1, l1;
                split_pair(w00, w01, h0, l0);
                split_pair(w10, w11, h1, l1);
                *(unsigned*)(sm + PWTH + t0*144 + c*2) = h0;
                *(unsigned*)(sm + PWTL + t0*144 + c*2) = l0;
                *(unsigned*)(sm + PWTH + t1*144 + c*2) = h1;
                *(unsigned*)(sm + PWTL + t1*144 + c*2) = l1;
            }
        }
    }
    __syncthreads();

    // ---- coalesced w gmem commit (uint4 from smem, 16B coalesced stores) ----
#pragma unroll
    for (int it = 0; it < 8; it++) {
        int i = tid + it * 256;
        int r = i >> 3, q = i & 7;
        uint4 vh = *(uint4*)(sm + PWTH + r*144 + q*16);
        uint4 vl = *(uint4*)(sm + PWTL + r*144 + q*16);
        *(uint4*)&g_whi[(size_t)(m0 + r)*512 + h*64 + q*8] = vh;
        *(uint4*)&g_wlo[(size_t)(m0 + r)*512 + h*64 + q*8] = vl;
    }

    // ---- norm partial sums ----
    {
        int g = tid & 63, q = tid >> 6;
        float s = 0.f;
#pragma unroll 8
        for (int t = q*64; t < q*64 + 64; t++) {
            s += __bfloat162float(*(__nv_bfloat16*)(sm + PWTH + t*144 + g*2));
            s += __bfloat162float(*(__nv_bfloat16*)(sm + PWTL + t*144 + g*2));
        }
        nrmp[q*64 + g] = s;
    }
    __syncthreads();
    if (tid < 64) {
        float s = nrmp[tid] + nrmp[64+tid] + nrmp[128+tid] + nrmp[192+tid];
        atomicAdd(&g_nrm[(b*8 + h)*64 + tid], s);
    }

    // ---- phase 2: 16 (cq,ts) tiles; warp tile 32g x 16c; flush per cq ----
    const int wm2 = wid >> 2;
    const int wn2 = wid & 3;
    const int trowA = (lane & 7) | ((lane >> 1) & 8);
    const int gselA = (lane & 8) * 2;
    const int base = (b*8 + h) * 64;
    const int rr = lane >> 2;
    const int cc2 = (lane & 3) * 2;

    float ac2[2][2][4];
#pragma unroll
    for (int i = 0; i < 2; i++)
#pragma unroll
        for (int j = 0; j < 2; j++)
#pragma unroll
            for (int e = 0; e < 4; e++) ac2[i][j][e] = 0.f;

    for (int qq = 0; qq < 16; qq++) {
        const int cq = qq >> 2, ts = qq & 3;
        CP_WAIT0();
        __syncthreads();
        if (qq + 1 < 16) {
            const int ncq = (qq + 1) >> 2, nts = (qq + 1) & 3;
            const uint32_t dh = sbase + (((qq + 1) & 1) ? XS1H : XS0H);
            const uint32_t dl = sbase + (((qq + 1) & 1) ? XS1L : XS0L);
#pragma unroll
            for (int it = 0; it < 2; it++) {
                int i = tid + it * 256;
                int r = i >> 3, q = i & 7;
                size_t src = (size_t)(m0 + nts*64 + r)*256 + ncq*64 + q*8;
                CP_ASYNC16(dh + r*144 + q*16, &g_xhi[src]);
                CP_ASYNC16(dl + r*144 + q*16, &g_xlo[src]);
            }
            CP_COMMIT();
        }
        const uint32_t sh = sbase + ((qq & 1) ? XS1H : XS0H);
        const uint32_t sl = sbase + ((qq & 1) ? XS1L : XS0L);
        const int tbs = ts * 64;

#pragma unroll
        for (int ks = 0; ks < 4; ks++) {
            uint32_t a[2][4], bh[4], bl[4];
#pragma unroll
            for (int i = 0; i < 2; i++) {
                uint32_t addr = sbase + PWTH + (tbs + ks*16 + trowA)*144
                              + (wm2*32 + i*16)*2 + gselA;
                ldsm4t(a[i][0], a[i][1], a[i][2], a[i][3], addr);
            }
            {
                uint32_t addr = sh + (ks*16 + lrow)*144 + (wn2*16 + lkq)*2;
                ldsm4t(bh[0], bh[1], bh[2], bh[3], addr);
            }
#pragma unroll
            for (int i = 0; i < 2; i++) {              // hh
                mma16816(ac2[i][0], a[i][0], a[i][1], a[i][2], a[i][3], bh[0], bh[1]);
                mma16816(ac2[i][1], a[i][0], a[i][1], a[i][2], a[i][3], bh[2], bh[3]);
            }
            {
                uint32_t addr = sl + (ks*16 + lrow)*144 + (wn2*16 + lkq)*2;
                ldsm4t(bl[0], bl[1], bl[2], bl[3], addr);
            }
#pragma unroll
            for (int i = 0; i < 2; i++) {              // hl
                mma16816(ac2[i][0], a[i][0], a[i][1], a[i][2], a[i][3], bl[0], bl[1]);
                mma16816(ac2[i][1], a[i][0], a[i][1], a[i][2], a[i][3], bl[2], bl[3]);
            }
#pragma unroll
            for (int i = 0; i < 2; i++) {
                uint32_t addr = sbase + PWTL + (tbs + ks*16 + trowA)*144
                              + (wm2*32 + i*16)*2 + gselA;
                ldsm4t(a[i][0], a[i][1], a[i][2], a[i][3], addr);
            }
#pragma unroll
            for (int i = 0; i < 2; i++) {              // lh
                mma16816(ac2[i][0], a[i][0], a[i][1], a[i][2], a[i][3], bh[0], bh[1]);
                mma16816(ac2[i][1], a[i][0], a[i][1], a[i][2], a[i][3], bh[2], bh[3]);
            }
        }

        if (ts == 3) {   // flush this c-quarter, zero acc
#pragma unroll
            for (int i = 0; i < 2; i++) {
                int g0r = wm2 * 32 + i * 16 + rr;
#pragma unroll
                for (int j = 0; j < 2; j++) {
                    int col = cq * 64 + wn2 * 16 + j * 8 + cc2;
                    RED_ADD_V2(&g_px[(size_t)(base + g0r)*256 + col],
                               ac2[i][j][0], ac2[i][j][1]);
                    RED_ADD_V2(&g_px[(size_t)(base + g0r + 8)*256 + col],
                               ac2[i][j][2], ac2[i][j][3]);
#pragma unroll
                    for (int e = 0; e < 4; e++) ac2[i][j][e] = 0.f;
                }
            }
        }
    }
}

// ---------------- K_st: st = px @ W_fx + nrm * b_fx (d-split x4) ----------------
#define SMEM_ST (64*260*4 + 256*20*4)
__global__ void __launch_bounds__(256) k_st(
    const float* __restrict__ Wfx, const float* __restrict__ bfx)
{
    float* spx = (float*)smem_dyn;              // [64][260]
    float* sw  = (float*)smem_dyn + 64*260;     // [256][20]
    const int h = blockIdx.x, b = blockIdx.y, z = blockIdx.z;
    const int tid = threadIdx.x;
    const int bh = b*8 + h;

#pragma unroll
    for (int it = 0; it < 16; it++) {
        int i = tid + it * 256;
        int r = i >> 6, c4 = i & 63;
        *(float4*)&spx[r*260 + c4*4] = *(const float4*)&g_px[(size_t)(bh*64 + r)*256 + c4*4];
    }
#pragma unroll
    for (int it = 0; it < 4; it++) {
        int i = tid + it * 256;
        int r = i >> 2, cq = i & 3;
        *(float4*)&sw[r*20 + cq*4] = *(const float4*)&Wfx[(size_t)r*512 + h*64 + z*16 + cq*4];
    }
    __syncthreads();

    const int g    = tid >> 2;
    const int dsub = (tid & 3) * 4;
    const float nv = g_nrm[bh*64 + g];
    float a4[4];
#pragma unroll
    for (int j = 0; j < 4; j++) a4[j] = nv * bfx[h*64 + z*16 + dsub + j];

    for (int c = 0; c < 256; c++) {
        float av = spx[g*260 + c];
        float4 w = *(float4*)&sw[c*20 + dsub];
        a4[0] += av * w.x;
        a4[1] += av * w.y;
        a4[2] += av * w.z;
        a4[3] += av * w.w;
    }
    *(float4*)&g_st[(size_t)(bh*64 + g)*64 + z*16 + dsub] =
        make_float4(a4[0], a4[1], a4[2], a4[3]);
}

// ---------------- K_tail: fused attention + P precompute (grid 8x4) ----------------
#define SMEM_TAIL (5*64*65*4)
__global__ void __launch_bounds__(256) k_tail(
    const float* __restrict__ Wq, const float* __restrict__ Wk,
    const float* __restrict__ Wv, const float* __restrict__ Wout)
{
    float* sm = (float*)smem_dyn;
    float* S  = sm;                    // later: Os (attention output)
    float* Qs = sm + 64*65;
    float* Ks = sm + 2*64*65;
    float* Vs = sm + 3*64*65;
    float* Ps = sm + 4*64*65;
    float* Wsm = Qs;                   // P phase: [64][256] over Qs..Ps

    const int h = blockIdx.x, b = blockIdx.y;
    const int tid = threadIdx.x;
    const int base = (b*8 + h) * 64;
    const int g  = tid >> 2;
    const int qd = (tid & 3) * 16;

    {
        float invn = 1.0f / (g_nrm[base + g] + 1e-5f);
#pragma unroll
        for (int j = 0; j < 16; j += 4) {
            float4 v = *(const float4*)&g_st[(base + g)*64 + qd + j];
            S[g*65 + qd + j]   = v.x * invn;
            S[g*65 + qd + j+1] = v.y * invn;
            S[g*65 + qd + j+2] = v.z * invn;
            S[g*65 + qd + j+3] = v.w * invn;
        }
    }
    __syncthreads();

    {
        float aq[16], ak[16], av[16];
#pragma unroll
        for (int j = 0; j < 16; j++) { aq[j] = 0.f; ak[j] = 0.f; av[j] = 0.f; }
        for (int k = 0; k < 64; k++) {
            float sv = S[g*65 + k];
            const float* wq = &Wq[k*64 + qd];
            const float* wk = &Wk[k*64 + qd];
            const float* wv = &Wv[k*64 + qd];
#pragma unroll
            for (int j = 0; j < 16; j++) {
                aq[j] += sv * wq[j];
                ak[j] += sv * wk[j];
                av[j] += sv * wv[j];
            }
        }
#pragma unroll
        for (int j = 0; j < 16; j++) {
            Qs[g*65 + qd + j] = aq[j];
            Ks[g*65 + qd + j] = ak[j];
            Vs[g*65 + qd + j] = av[j];
        }
    }
    __syncthreads();

    {
        float lg[16];
#pragma unroll
        for (int jj = 0; jj < 16; jj++) {
            int j = qd + jj;
            float dot = 0.f;
#pragma unroll
            for (int d = 0; d < 64; d++) dot += Qs[g*65 + d] * Ks[j*65 + d];
            lg[jj] = dot * 0.125f;
        }
        float mx = -1e30f;
#pragma unroll
        for (int jj = 0; jj < 16; jj++) mx = fmaxf(mx, lg[jj]);
        mx = fmaxf(mx, __shfl_xor_sync(0xffffffff, mx, 1));
        mx = fmaxf(mx, __shfl_xor_sync(0xffffffff, mx, 2));
        float s = 0.f;
#pragma unroll
        for (int jj = 0; jj < 16; jj++) { lg[jj] = __expf(lg[jj] - mx); s += lg[jj]; }
        s += __shfl_xor_sync(0xffffffff, s, 1);
        s += __shfl_xor_sync(0xffffffff, s, 2);
        float inv = 1.0f / s;
#pragma unroll
        for (int jj = 0; jj < 16; jj++) Ps[g*65 + qd + jj] = lg[jj] * inv;
    }
    __syncthreads();

    {
        float o[16];
#pragma unroll
        for (int d = 0; d < 16; d++) o[d] = 0.f;
        for (int j = 0; j < 64; j++) {
            float p = Ps[g*65 + j];
#pragma unroll
            for (int d = 0; d < 16; d++) o[d] += p * Vs[j*65 + qd + d];
        }
#pragma unroll
        for (int d = 0; d < 16; d++)
            S[g*65 + qd + d] = o[d];     // os stays in smem (S repurposed)
    }
    __syncthreads();

    // ---- P phase: load W_out, compute P_t (split bf16) ----
    for (int i = tid; i < 64*64; i += 256) {
        int r = i >> 6, c = i & 63;
        *(float4*)&Wsm[r*256 + c*4] = *(const float4*)&Wout[(size_t)(h*64 + r)*256 + c*4];
    }
    __syncthreads();

    const int gq = tid >> 3;
    const int cq = tid & 7;
    const int g0 = gq * 2;
    const int c0 = cq * 32;

    float acc[2][32];
#pragma unroll
    for (int i = 0; i < 2; i++)
#pragma unroll
        for (int j = 0; j < 32; j++) acc[i][j] = 0.f;

    for (int k = 0; k < 64; k++) {
        float a0 = S[(g0+0)*65 + k];
        float a1 = S[(g0+1)*65 + k];
#pragma unroll
        for (int c4 = 0; c4 < 8; c4++) {
            float4 w = *(float4*)&Wsm[k*256 + c0 + c4*4];
            acc[0][c4*4+0] += a0*w.x; acc[0][c4*4+1] += a0*w.y;
            acc[0][c4*4+2] += a0*w.z; acc[0][c4*4+3] += a0*w.w;
            acc[1][c4*4+0] += a1*w.x; acc[1][c4*4+1] += a1*w.y;
            acc[1][c4*4+2] += a1*w.z; acc[1][c4*4+3] += a1*w.w;
        }
    }
    __nv_bfloat16* Ph = &g_Pthi[(size_t)b * C_ * INNER_];
    __nv_bfloat16* Pl = &g_Ptlo[(size_t)b * C_ * INNER_];
#pragma unroll
    for (int i = 0; i < 2; i++)
#pragma unroll
        for (int c4 = 0; c4 < 8; c4++)
#pragma unroll
            for (int e = 0; e < 4; e++) {
                size_t off = (size_t)(c0 + c4*4 + e) * INNER_ + h*64 + g0 + i;
                __nv_bfloat16 hi, lo;
                split_one(acc[i][c4*4+e], hi, lo);
                Ph[off] = hi;
                Pl[off] = lo;
            }
}

// ---------------- launch ----------------
extern "C" void kernel_launch(void* const* d_in, const int* in_sizes, int n_in,
                              void* d_out, int out_size)
{
    const float* x    = (const float*)d_in[0];
    const float* Wfx  = (const float*)d_in[1];
    const float* bfx  = (const float*)d_in[2];
    const float* Wx   = (const float*)d_in[3];
    const float* bx   = (const float*)d_in[4];
    const float* Wsl  = (const float*)d_in[5];
    const float* bsl  = (const float*)d_in[6];
    const float* temp = (const float*)d_in[7];
    const float* Wq   = (const float*)d_in[8];
    const float* Wk   = (const float*)d_in[9];
    const float* Wv   = (const float*)d_in[10];
    const float* Wout = (const float*)d_in[11];
    const float* bout = (const float*)d_in[12];
    float* out = (float*)d_out;

    static bool init = false;
    static __nv_bfloat16 *g_whi_p, *g_wlo_p, *g_Pthi_p, *g_Ptlo_p;
    if (!init) {
        cudaGetSymbolAddress((void**)&g_whi_p,   g_whi);
        cudaGetSymbolAddress((void**)&g_wlo_p,   g_wlo);
        cudaGetSymbolAddress((void**)&g_Pthi_p,  g_Pthi);
        cudaGetSymbolAddress((void**)&g_Ptlo_p,  g_Ptlo);
        cudaFuncSetAttribute(k_gemm_ts, cudaFuncAttributeMaxDynamicSharedMemorySize, GK_SMEM);
        cudaFuncSetAttribute(k_pool, cudaFuncAttributeMaxDynamicSharedMemorySize, SMEM_POOL);
        cudaFuncSetAttribute(k_st,   cudaFuncAttributeMaxDynamicSharedMemorySize, SMEM_ST);
        cudaFuncSetAttribute(k_tail, cudaFuncAttributeMaxDynamicSharedMemorySize, SMEM_TAIL);
        init = true;
    }

    // 0) fused prep: split x + zero px/nrm + W_comb (one launch, overlapped)
    k_prep<<<PREP_SPLIT0 + (BNTOK * 256 / 4) / 256, 256>>>(x, Wx, Wsl, bx, bsl);

    // 1) fused logits/softmax/pool-x (tensor cores, 2 CTA/SM)
    k_pool<<<dim3(H_, N_/TOK, B_), 256, SMEM_POOL>>>(temp);

    // 2) st = px @ W_fx + nrm*b_fx (d-split x4)
    k_st<<<dim3(H_, B_, 4), 256, SMEM_ST>>>(Wfx, bfx);

    // 3) fused attention + P precompute
    k_tail<<<dim3(H_, B_), 256, SMEM_TAIL>>>(Wq, Wk, Wv, Wout);

    // 4) output GEMM (tensor cores, 3-pass)
    k_gemm_ts<<<dim3(2, BNTOK/128), 256, GK_SMEM>>>(
        g_whi_p, g_wlo_p, g_Pthi_p, g_Ptlo_p, 512, bout, out, 256);
}